// round 1
// baseline (speedup 1.0000x reference)
#include <cuda_runtime.h>
#include <mma.h>
#include <cstdint>
#include <cstddef>

using namespace nvcuda;

// Problem shape (fixed): B=2, S=2048, D=1024, H=16, Dh=64
#define NB 2
#define NS 2048
#define ND 1024
#define NH 16
#define NDH 64
#define TOK (NB*NS)                         // 4096 tokens
#define OUT_ELEMS (4194304)                 // B*S*D
#define SCALE 0.125f
#define LN_EPS 1e-5f

// ---- scratch (no allocation allowed; __device__ globals) ----
__device__ float g_Q[TOK*ND];
__device__ float g_K[TOK*ND];
__device__ float g_V[TOK*ND];
__device__ float g_ctx[TOK*ND];
__device__ float g_fc[TOK*ND];

// ---------------------------------------------------------------------------
// helper: convert a wmma fragment's floats to tf32 in place
// ---------------------------------------------------------------------------
template <typename Frag>
__device__ __forceinline__ void to_tf32(Frag& f) {
#pragma unroll
    for (int i = 0; i < f.num_elements; i++) f.x[i] = wmma::__float_to_tf32(f.x[i]);
}

// ---------------------------------------------------------------------------
// Generic GEMM: C[4096,1024] = A[4096,1024] @ B[1024,1024], all row-major f32,
// tf32 tensor cores. BM=128, BN=128, BK=16. 256 threads = 8 warps (2x4),
// warp tile 64x32 = 4x2 wmma(16x16x8) frags.
// ---------------------------------------------------------------------------
__global__ __launch_bounds__(256) void gemm_tf32(const float* __restrict__ A,
                                                 const float* __restrict__ Bw,
                                                 float* __restrict__ C) {
    __shared__ float sA[128][20];   // [BM][BK+4]
    __shared__ float sB[16][132];   // [BK][BN+4]

    const int tid = threadIdx.x;
    const int w   = tid >> 5;
    const int wm  = w >> 2;          // 0..1
    const int wn  = w & 3;           // 0..3
    const int m0  = blockIdx.y * 128;
    const int n0  = blockIdx.x * 128;

    wmma::fragment<wmma::accumulator, 16, 16, 8, float> acc[4][2];
#pragma unroll
    for (int i = 0; i < 4; i++)
#pragma unroll
        for (int j = 0; j < 2; j++) wmma::fill_fragment(acc[i][j], 0.0f);

    for (int k0 = 0; k0 < ND; k0 += 16) {
        // load A tile 128x16 (512 float4, 2 per thread)
#pragma unroll
        for (int i = 0; i < 2; i++) {
            int idx = tid + i * 256;
            int r = idx >> 2, c = (idx & 3) << 2;
            float4 v = *(const float4*)&A[(size_t)(m0 + r) * ND + k0 + c];
            *(float4*)&sA[r][c] = v;
        }
        // load B tile 16x128 (512 float4, 2 per thread)
#pragma unroll
        for (int i = 0; i < 2; i++) {
            int idx = tid + i * 256;
            int r = idx >> 5, c = (idx & 31) << 2;
            float4 v = *(const float4*)&Bw[(size_t)(k0 + r) * ND + n0 + c];
            *(float4*)&sB[r][c] = v;
        }
        __syncthreads();

#pragma unroll
        for (int ks = 0; ks < 16; ks += 8) {
            wmma::fragment<wmma::matrix_a, 16, 16, 8, wmma::precision::tf32, wmma::row_major> af[4];
            wmma::fragment<wmma::matrix_b, 16, 16, 8, wmma::precision::tf32, wmma::row_major> bf[2];
#pragma unroll
            for (int i = 0; i < 4; i++) {
                wmma::load_matrix_sync(af[i], &sA[wm * 64 + i * 16][ks], 20);
                to_tf32(af[i]);
            }
#pragma unroll
            for (int j = 0; j < 2; j++) {
                wmma::load_matrix_sync(bf[j], &sB[ks][wn * 32 + j * 16], 132);
                to_tf32(bf[j]);
            }
#pragma unroll
            for (int i = 0; i < 4; i++)
#pragma unroll
                for (int j = 0; j < 2; j++)
                    wmma::mma_sync(acc[i][j], af[i], bf[j], acc[i][j]);
        }
        __syncthreads();
    }

#pragma unroll
    for (int i = 0; i < 4; i++)
#pragma unroll
        for (int j = 0; j < 2; j++)
            wmma::store_matrix_sync(&C[(size_t)(m0 + wm * 64 + i * 16) * ND + n0 + wn * 32 + j * 16],
                                    acc[i][j], ND, wmma::mem_row_major);
}

// ---------------------------------------------------------------------------
// Attention scores + softmax, fused. One block = one (b,h) and 16 query rows.
// Scores (16x2048 f32) live in dynamic smem; K is staged through smem in
// 128-column chunks. After the GEMM, softmax (scale, mask, max, exp, norm)
// and a single write of attn to global.
// grid = (S/16=128, B*H=32), 256 threads.
// ---------------------------------------------------------------------------
#define ATTN_SMEM_BYTES ((16*2048 + 16*68 + 128*68 + 16*17 + 32) * 4)

__global__ __launch_bounds__(256) void attn_kernel(const unsigned char* __restrict__ mask,
                                                   float* __restrict__ attnOut) {
    extern __shared__ float sm[];
    float* sS   = sm;                        // 16 x 2048 scores
    float* sQ   = sS + 16 * 2048;            // 16 x 68
    float* sK   = sQ + 16 * 68;              // 128 x 68
    float* red  = sK + 128 * 68;             // 16 x 17 partials
    float* rowv = red + 16 * 17;             // 32: [0..15] rowmax, [16..31] rowsum

    const int tid = threadIdx.x;
    const int w   = tid >> 5;
    const int b   = blockIdx.y >> 4;
    const int h   = blockIdx.y & 15;
    const int q0  = blockIdx.x * 16;

    const float* Qb = g_Q + ((size_t)(b * NS + q0)) * ND + h * NDH;
    const float* Kb = g_K + ((size_t)b * NS) * ND + h * NDH;

    // load Q tile 16x64 (exactly 256 float4)
    {
        int r = tid >> 4, c = (tid & 15) << 2;
        float4 v = *(const float4*)&Qb[(size_t)r * ND + c];
        *(float4*)&sQ[r * 68 + c] = v;
    }
    __syncthreads();

    // ---- scores: S[16 x 2048] = Q(16x64) @ K^T, in 16 chunks of 128 cols ----
    for (int cc = 0; cc < 16; cc++) {
        // stage K chunk: 128 rows x 64 dims (2048 float4, 8 per thread)
#pragma unroll
        for (int i = 0; i < 8; i++) {
            int idx = tid + i * 256;
            int r = idx >> 4, c = (idx & 15) << 2;
            float4 v = *(const float4*)&Kb[(size_t)(cc * 128 + r) * ND + c];
            *(float4*)&sK[r * 68 + c] = v;
        }
        __syncthreads();

        wmma::fragment<wmma::accumulator, 16, 16, 8, float> acc;
        wmma::fill_fragment(acc, 0.0f);
#pragma unroll
        for (int kk = 0; kk < 8; kk++) {
            wmma::fragment<wmma::matrix_a, 16, 16, 8, wmma::precision::tf32, wmma::row_major> af;
            wmma::fragment<wmma::matrix_b, 16, 16, 8, wmma::precision::tf32, wmma::col_major> bf;
            wmma::load_matrix_sync(af, sQ + kk * 8, 68);
            to_tf32(af);
            wmma::load_matrix_sync(bf, sK + (w * 16) * 68 + kk * 8, 68);
            to_tf32(bf);
            wmma::mma_sync(acc, af, bf, acc);
        }
        wmma::store_matrix_sync(sS + cc * 128 + w * 16, acc, 2048, wmma::mem_row_major);
        __syncthreads();
    }

    // ---- softmax over each of 16 rows (2048 cols); 16 threads per row ----
    const int r = tid >> 4;   // row 0..15
    const int l = tid & 15;   // lane-in-row 0..15
    float* srow = sS + r * 2048;
    const unsigned char* mrow = mask + ((size_t)b * NS + q0 + r) * NS;

    // pass 1: scale + mask + max  (interleaved float4s: conflict-free, coalesced)
    float mx = -3.4e38f;
#pragma unroll 4
    for (int i = 0; i < 32; i++) {
        int c = (l + (i << 4)) << 2;
        float4 v = *(float4*)&srow[c];
        uchar4 mk = *(const uchar4*)&mrow[c];
        v.x = mk.x ? -1e9f : v.x * SCALE;
        v.y = mk.y ? -1e9f : v.y * SCALE;
        v.z = mk.z ? -1e9f : v.z * SCALE;
        v.w = mk.w ? -1e9f : v.w * SCALE;
        *(float4*)&srow[c] = v;
        mx = fmaxf(mx, fmaxf(fmaxf(v.x, v.y), fmaxf(v.z, v.w)));
    }
    red[r * 17 + l] = mx;
    __syncthreads();
    if (l == 0) {
        float mm = red[r * 17];
#pragma unroll
        for (int i = 1; i < 16; i++) mm = fmaxf(mm, red[r * 17 + i]);
        rowv[r] = mm;
    }
    __syncthreads();
    const float rm = rowv[r];

    // pass 2: exp + sum
    float s = 0.0f;
#pragma unroll 4
    for (int i = 0; i < 32; i++) {
        int c = (l + (i << 4)) << 2;
        float4 v = *(float4*)&srow[c];
        v.x = __expf(v.x - rm);
        v.y = __expf(v.y - rm);
        v.z = __expf(v.z - rm);
        v.w = __expf(v.w - rm);
        *(float4*)&srow[c] = v;
        s += v.x + v.y + v.z + v.w;
    }
    red[r * 17 + l] = s;
    __syncthreads();
    if (l == 0) {
        float ss = 0.0f;
#pragma unroll
        for (int i = 0; i < 16; i++) ss += red[r * 17 + i];
        rowv[16 + r] = ss;
    }
    __syncthreads();
    const float inv = 1.0f / rowv[16 + r];

    // pass 3: normalize + write attn [B,H,S,S]
    float* gout = attnOut + (((size_t)(b * NH + h) * NS) + q0 + r) * NS;
#pragma unroll 4
    for (int i = 0; i < 32; i++) {
        int c = (l + (i << 4)) << 2;
        float4 v = *(float4*)&srow[c];
        v.x *= inv; v.y *= inv; v.z *= inv; v.w *= inv;
        *(float4*)&gout[c] = v;
    }
}

// ---------------------------------------------------------------------------
// Context: ctx_bh[2048,64] = attn_bh[2048,2048] @ V_bh[2048,64].
// grid = (2048/128=16, B*H=32), 256 threads = 8 warps, warp tile 16x64.
// Output written in [B,S,H*Dh] layout directly (ld = 1024).
// ---------------------------------------------------------------------------
__global__ __launch_bounds__(256) void context_kernel(const float* __restrict__ attn) {
    __shared__ float sP[128][20];   // [BM][BK+4]
    __shared__ float sV[16][68];    // [BK][64+4]

    const int tid = threadIdx.x;
    const int w   = tid >> 5;
    const int b   = blockIdx.y >> 4;
    const int h   = blockIdx.y & 15;
    const int m0  = blockIdx.x * 128;

    const float* Pb = attn + ((size_t)(b * NH + h) * NS + m0) * NS;
    const float* Vb = g_V + ((size_t)b * NS) * ND + h * NDH;

    wmma::fragment<wmma::accumulator, 16, 16, 8, float> acc[4];
#pragma unroll
    for (int j = 0; j < 4; j++) wmma::fill_fragment(acc[j], 0.0f);

    for (int k0 = 0; k0 < NS; k0 += 16) {
        // P tile 128x16 (512 float4, 2 per thread)
#pragma unroll
        for (int i = 0; i < 2; i++) {
            int idx = tid + i * 256;
            int r = idx >> 2, c = (idx & 3) << 2;
            float4 v = *(const float4*)&Pb[(size_t)r * NS + k0 + c];
            *(float4*)&sP[r][c] = v;
        }
        // V tile 16x64 (256 float4, 1 per thread)
        {
            int r = tid >> 4, c = (tid & 15) << 2;
            float4 v = *(const float4*)&Vb[(size_t)(k0 + r) * ND + c];
            *(float4*)&sV[r][c] = v;
        }
        __syncthreads();

#pragma unroll
        for (int ks = 0; ks < 16; ks += 8) {
            wmma::fragment<wmma::matrix_a, 16, 16, 8, wmma::precision::tf32, wmma::row_major> af;
            wmma::load_matrix_sync(af, &sP[w * 16][ks], 20);
            to_tf32(af);
#pragma unroll
            for (int j = 0; j < 4; j++) {
                wmma::fragment<wmma::matrix_b, 16, 16, 8, wmma::precision::tf32, wmma::row_major> bf;
                wmma::load_matrix_sync(bf, &sV[ks][j * 16], 68);
                to_tf32(bf);
                wmma::mma_sync(acc[j], af, bf, acc[j]);
            }
        }
        __syncthreads();
    }

#pragma unroll
    for (int j = 0; j < 4; j++)
        wmma::store_matrix_sync(&g_ctx[(size_t)(b * NS + m0 + w * 16) * ND + h * NDH + j * 16],
                                acc[j], ND, wmma::mem_row_major);
}

// ---------------------------------------------------------------------------
// Residual + LayerNorm: out[row] = LN(g_fc[row] + resid[row]); 1 block per row.
// ---------------------------------------------------------------------------
__global__ __launch_bounds__(256) void ln_kernel(const float* __restrict__ resid,
                                                 float* __restrict__ out) {
    const int row = blockIdx.x;
    const int tid = threadIdx.x;

    float4 f = *(const float4*)&g_fc[(size_t)row * ND + tid * 4];
    float4 rr = *(const float4*)&resid[(size_t)row * ND + tid * 4];
    float4 y;
    y.x = f.x + rr.x; y.y = f.y + rr.y; y.z = f.z + rr.z; y.w = f.w + rr.w;

    float s = y.x + y.y + y.z + y.w;
    float q = y.x * y.x + y.y * y.y + y.z * y.z + y.w * y.w;
#pragma unroll
    for (int off = 16; off > 0; off >>= 1) {
        s += __shfl_down_sync(0xffffffffu, s, off);
        q += __shfl_down_sync(0xffffffffu, q, off);
    }
    __shared__ float ss[8], sq[8];
    __shared__ float mu_s, rs_s;
    if ((tid & 31) == 0) { ss[tid >> 5] = s; sq[tid >> 5] = q; }
    __syncthreads();
    if (tid == 0) {
        float S = 0.0f, Q = 0.0f;
#pragma unroll
        for (int i = 0; i < 8; i++) { S += ss[i]; Q += sq[i]; }
        float mu = S * (1.0f / ND);
        float var = Q * (1.0f / ND) - mu * mu;
        mu_s = mu;
        rs_s = rsqrtf(var + LN_EPS);
    }
    __syncthreads();
    const float mu = mu_s, rs = rs_s;
    float4 o;
    o.x = (y.x - mu) * rs; o.y = (y.y - mu) * rs;
    o.z = (y.z - mu) * rs; o.w = (y.w - mu) * rs;
    *(float4*)&out[(size_t)row * ND + tid * 4] = o;
}

// ---------------------------------------------------------------------------
// Launch
// ---------------------------------------------------------------------------
extern "C" void kernel_launch(void* const* d_in, const int* in_sizes, int n_in,
                              void* d_out, int out_size) {
    const float* inQ = (const float*)d_in[0];
    const float* inK = (const float*)d_in[1];
    const float* inV = (const float*)d_in[2];
    const unsigned char* mask = (const unsigned char*)d_in[3];
    const float* WQ  = (const float*)d_in[4];
    const float* WK  = (const float*)d_in[5];
    const float* WV  = (const float*)d_in[6];
    const float* Wfc = (const float*)d_in[7];

    float* out  = (float*)d_out;
    float* attn = out + OUT_ELEMS;   // tuple (out, attn) concatenated flat

    void *pQ, *pK, *pV, *pCtx;
    cudaGetSymbolAddress(&pQ, g_Q);
    cudaGetSymbolAddress(&pK, g_K);
    cudaGetSymbolAddress(&pV, g_V);
    cudaGetSymbolAddress(&pCtx, g_ctx);
    void* pFc;
    cudaGetSymbolAddress(&pFc, g_fc);

    cudaFuncSetAttribute(attn_kernel, cudaFuncAttributeMaxDynamicSharedMemorySize,
                         ATTN_SMEM_BYTES);

    dim3 gb(8, 32);   // N/128 x M/128
    gemm_tf32<<<gb, 256>>>(inQ, WQ, (float*)pQ);
    gemm_tf32<<<gb, 256>>>(inK, WK, (float*)pK);
    gemm_tf32<<<gb, 256>>>(inV, WV, (float*)pV);

    attn_kernel<<<dim3(128, 32), 256, ATTN_SMEM_BYTES>>>(mask, attn);

    context_kernel<<<dim3(16, 32), 256>>>(attn);

    gemm_tf32<<<gb, 256>>>((const float*)pCtx, Wfc, (float*)pFc);

    ln_kernel<<<TOK, 256>>>(inQ, out);
}

// round 4
// speedup vs baseline: 1.3098x; 1.3098x over previous
#include <cuda_runtime.h>
#include <mma.h>
#include <cstdint>
#include <cstddef>

using namespace nvcuda;

// Problem shape (fixed): B=2, S=2048, D=1024, H=16, Dh=64
#define NB 2
#define NS 2048
#define ND 1024
#define NH 16
#define NDH 64
#define TOK (NB*NS)
#define OUT_ELEMS (4194304)
#define SCALE 0.125f
#define LN_EPS 1e-5f

// ---- scratch (__device__ globals; no allocation allowed) ----
__device__ float g_Q[TOK*ND];
__device__ float g_K[TOK*ND];
__device__ float g_V[TOK*ND];
__device__ float g_ctx[TOK*ND];
__device__ float g_fc[TOK*ND];
__device__ float g_psum[32 * NS * 16];   // partial row sums [bh][row][coltile]

// ---------------------------------------------------------------------------
template <typename Frag>
__device__ __forceinline__ void to_tf32(Frag& f) {
#pragma unroll
    for (int i = 0; i < f.num_elements; i++) f.x[i] = wmma::__float_to_tf32(f.x[i]);
}

__device__ __forceinline__ void cpa16(void* s, const void* g) {
    uint32_t sa = (uint32_t)__cvta_generic_to_shared(s);
    asm volatile("cp.async.ca.shared.global [%0], [%1], 16;" :: "r"(sa), "l"(g));
}
__device__ __forceinline__ void cpa_commit() {
    asm volatile("cp.async.commit_group;" ::: "memory");
}
template <int N>
__device__ __forceinline__ void cpa_wait() {
    asm volatile("cp.async.wait_group %0;" :: "n"(N) : "memory");
}

// ---------------------------------------------------------------------------
// Double-buffered tf32 GEMM: C[4096,1024] = A[4096,1024] @ B[1024,1024].
// BM=128, BN=128, BK=16, 2-stage cp.async pipeline. 256 threads = 8 warps
// (2x4), warp tile 64x32.
// ---------------------------------------------------------------------------
__global__ __launch_bounds__(256) void gemm_db(const float* __restrict__ A,
                                               const float* __restrict__ Bw,
                                               float* __restrict__ C) {
    __shared__ float sA[2][128][20];
    __shared__ float sB[2][16][132];

    const int tid = threadIdx.x;
    const int w   = tid >> 5;
    const int wm  = w >> 2;
    const int wn  = w & 3;
    const int m0  = blockIdx.y * 128;
    const int n0  = blockIdx.x * 128;

    const int ar = tid >> 2, ac = (tid & 3) << 2;
    const int br = tid >> 5, bc = (tid & 31) << 2;

#define LOADT(st, k0)                                                                  \
    {                                                                                  \
        cpa16(&sA[st][ar][ac],      &A[(size_t)(m0 + ar)      * ND + (k0) + ac]);      \
        cpa16(&sA[st][ar + 64][ac], &A[(size_t)(m0 + ar + 64) * ND + (k0) + ac]);      \
        cpa16(&sB[st][br][bc],      &Bw[(size_t)((k0) + br)      * ND + n0 + bc]);     \
        cpa16(&sB[st][br + 8][bc],  &Bw[(size_t)((k0) + br + 8)  * ND + n0 + bc]);     \
        cpa_commit();                                                                  \
    }

    wmma::fragment<wmma::accumulator, 16, 16, 8, float> acc[4][2];
#pragma unroll
    for (int i = 0; i < 4; i++)
#pragma unroll
        for (int j = 0; j < 2; j++) wmma::fill_fragment(acc[i][j], 0.0f);

    LOADT(0, 0);

    for (int kt = 0; kt < 64; kt++) {
        if (kt < 63) {
            LOADT((kt + 1) & 1, (kt + 1) * 16);
            cpa_wait<1>();
        } else {
            cpa_wait<0>();
        }
        __syncthreads();
        const int st = kt & 1;
#pragma unroll
        for (int ks = 0; ks < 16; ks += 8) {
            wmma::fragment<wmma::matrix_a, 16, 16, 8, wmma::precision::tf32, wmma::row_major> af[4];
            wmma::fragment<wmma::matrix_b, 16, 16, 8, wmma::precision::tf32, wmma::row_major> bf[2];
#pragma unroll
            for (int i = 0; i < 4; i++) {
                wmma::load_matrix_sync(af[i], &sA[st][wm * 64 + i * 16][ks], 20);
                to_tf32(af[i]);
            }
#pragma unroll
            for (int j = 0; j < 2; j++) {
                wmma::load_matrix_sync(bf[j], &sB[st][ks][wn * 32 + j * 16], 132);
                to_tf32(bf[j]);
            }
#pragma unroll
            for (int i = 0; i < 4; i++)
#pragma unroll
                for (int j = 0; j < 2; j++)
                    wmma::mma_sync(acc[i][j], af[i], bf[j], acc[i][j]);
        }
        __syncthreads();
    }
#undef LOADT

#pragma unroll
    for (int i = 0; i < 4; i++)
#pragma unroll
        for (int j = 0; j < 2; j++)
            wmma::store_matrix_sync(&C[(size_t)(m0 + wm * 64 + i * 16) * ND + n0 + wn * 32 + j * 16],
                                    acc[i][j], ND, wmma::mem_row_major);
}

// ---------------------------------------------------------------------------
// escore: E[128x128 tile] = exp(scale * Q_bh K_bh^T  (masked)), written
// UNNORMALIZED to the attn output buffer; partial row sums -> g_psum.
// grid = (coltile=16, rowtile=16, bh=32), 256 threads.
// Dynamic smem: Q[128][68] + K[128][68], scores[128][132] aliased on top.
// ---------------------------------------------------------------------------
#define ESCORE_SMEM (2 * 128 * 68 * 4)   // 69632 >= 128*132*4

__global__ __launch_bounds__(256) void escore_kernel(const unsigned char* __restrict__ mask,
                                                     float* __restrict__ attnOut) {
    extern __shared__ float sm[];
    float* sQ = sm;
    float* sK = sm + 128 * 68;
    float* sS = sm;                  // alias: used only after MMA completes

    const int tid = threadIdx.x;
    const int w   = tid >> 5;
    const int l   = tid & 31;
    const int ct  = blockIdx.x;      // key tile
    const int rt  = blockIdx.y;      // query tile
    const int bh  = blockIdx.z;
    const int b   = bh >> 4;
    const int h   = bh & 15;
    const int q0  = rt * 128;
    const int c0  = ct * 128;

    // load Q tile (128x64) and K tile (128x64): 2048 float4 each, 8/thread
    {
        const float* Qb = g_Q + ((size_t)(b * NS + q0)) * ND + h * NDH;
        const float* Kb = g_K + ((size_t)(b * NS + c0)) * ND + h * NDH;
#pragma unroll
        for (int i = 0; i < 8; i++) {
            int idx = tid + i * 256;
            int r = idx >> 4, c = (idx & 15) << 2;
            *(float4*)&sQ[r * 68 + c] = *(const float4*)&Qb[(size_t)r * ND + c];
            *(float4*)&sK[r * 68 + c] = *(const float4*)&Kb[(size_t)r * ND + c];
        }
    }
    __syncthreads();

    // MMA: warp grid 2x4, warp tile 64x32, K=64 (8 steps)
    const int wm = w >> 2, wn = w & 3;
    wmma::fragment<wmma::accumulator, 16, 16, 8, float> acc[4][2];
#pragma unroll
    for (int i = 0; i < 4; i++)
#pragma unroll
        for (int j = 0; j < 2; j++) wmma::fill_fragment(acc[i][j], 0.0f);

#pragma unroll
    for (int kk = 0; kk < 8; kk++) {
        wmma::fragment<wmma::matrix_a, 16, 16, 8, wmma::precision::tf32, wmma::row_major> af[4];
        wmma::fragment<wmma::matrix_b, 16, 16, 8, wmma::precision::tf32, wmma::col_major> bf[2];
#pragma unroll
        for (int i = 0; i < 4; i++) {
            wmma::load_matrix_sync(af[i], &sQ[(wm * 64 + i * 16) * 68 + kk * 8], 68);
            to_tf32(af[i]);
        }
#pragma unroll
        for (int j = 0; j < 2; j++) {
            wmma::load_matrix_sync(bf[j], &sK[(wn * 32 + j * 16) * 68 + kk * 8], 68);
            to_tf32(bf[j]);
        }
#pragma unroll
        for (int i = 0; i < 4; i++)
#pragma unroll
            for (int j = 0; j < 2; j++)
                wmma::mma_sync(acc[i][j], af[i], bf[j], acc[i][j]);
    }
    __syncthreads();   // all MMA reads of sQ/sK done before sS overwrites them

#pragma unroll
    for (int i = 0; i < 4; i++)
#pragma unroll
        for (int j = 0; j < 2; j++)
            wmma::store_matrix_sync(&sS[(wm * 64 + i * 16) * 132 + wn * 32 + j * 16],
                                    acc[i][j], 132, wmma::mem_row_major);
    __syncthreads();

    // epilogue: each warp handles one row per iteration (32 float4 = 128 cols)
    // exp + mask + global write + warp-reduced row sum
    for (int it = 0; it < 16; it++) {
        const int row = it * 8 + w;
        float4 v = *(float4*)&sS[row * 132 + l * 4];
        const unsigned char* mrow = mask + ((size_t)(b * NS + q0 + row)) * NS + c0;
        uchar4 mk = *(const uchar4*)&mrow[l * 4];
        v.x = mk.x ? 0.0f : __expf(v.x * SCALE);
        v.y = mk.y ? 0.0f : __expf(v.y * SCALE);
        v.z = mk.z ? 0.0f : __expf(v.z * SCALE);
        v.w = mk.w ? 0.0f : __expf(v.w * SCALE);
        float* erow = attnOut + ((size_t)(bh * NS + q0 + row)) * NS + c0;
        *(float4*)&erow[l * 4] = v;
        float s = v.x + v.y + v.z + v.w;
#pragma unroll
        for (int off = 16; off > 0; off >>= 1) s += __shfl_xor_sync(0xffffffffu, s, off);
        if (l == 0) g_psum[(((size_t)bh * NS) + q0 + row) * 16 + ct] = s;
    }
}

// ---------------------------------------------------------------------------
// ctxnorm: per (bh, 64-row tile): reduce partial sums -> inv, then stream E:
// normalize in registers, write normalized attn back IN PLACE, and accumulate
// ctx = Enorm @ V_bh into g_ctx ([B,S,H*Dh] layout).
// grid = (mtile=32, bh=32), 256 threads. Dynamic smem.
// ---------------------------------------------------------------------------
#define CTX_SMEM ((64 * 132 + 128 * 68 + 64) * 4)   // 68864

__global__ __launch_bounds__(256) void ctxnorm_kernel(float* __restrict__ attn) {
    extern __shared__ float sm[];
    float* sE   = sm;                       // 64 x 132
    float* sV   = sE + 64 * 132;            // 128 x 68
    float* sInv = sV + 128 * 68;            // 64

    const int tid = threadIdx.x;
    const int w   = tid >> 5;
    const int bh  = blockIdx.y;
    const int b   = bh >> 4;
    const int h   = bh & 15;
    const int m0  = blockIdx.x * 64;

    // reduce 16 partials per row -> 1/rowsum
    if (tid < 64) {
        const float* p = g_psum + (((size_t)bh * NS) + m0 + tid) * 16;
        float s = 0.0f;
#pragma unroll
        for (int j = 0; j < 16; j++) s += p[j];
        sInv[tid] = 1.0f / s;
    }
    __syncthreads();

    const int wmm = w >> 1, wnn = w & 1;   // warp grid 4x2, warp tile 16x32
    wmma::fragment<wmma::accumulator, 16, 16, 8, float> acc[2];
    wmma::fill_fragment(acc[0], 0.0f);
    wmma::fill_fragment(acc[1], 0.0f);

    float* Eb = attn + ((size_t)bh * NS + m0) * NS;
    const float* Vb = g_V + ((size_t)b * NS) * ND + h * NDH;

    for (int kc = 0; kc < 16; kc++) {
        const int k0 = kc * 128;
        // E chunk 64x128: 2048 f4, 8/thread: normalize, write back, stage
#pragma unroll
        for (int i = 0; i < 8; i++) {
            int idx = tid + i * 256;
            int r = idx >> 5, c = (idx & 31) << 2;
            float* gp = Eb + (size_t)r * NS + k0 + c;
            float4 v = *(float4*)gp;
            float iv = sInv[r];
            v.x *= iv; v.y *= iv; v.z *= iv; v.w *= iv;
            *(float4*)gp = v;
            *(float4*)&sE[r * 132 + c] = v;
        }
        // V chunk 128x64: 2048 f4, 8/thread
#pragma unroll
        for (int i = 0; i < 8; i++) {
            int idx = tid + i * 256;
            int r = idx >> 4, c = (idx & 15) << 2;
            *(float4*)&sV[r * 68 + c] = *(const float4*)&Vb[(size_t)(k0 + r) * ND + c];
        }
        __syncthreads();

#pragma unroll
        for (int kk = 0; kk < 16; kk++) {
            wmma::fragment<wmma::matrix_a, 16, 16, 8, wmma::precision::tf32, wmma::row_major> af;
            wmma::load_matrix_sync(af, &sE[(wmm * 16) * 132 + kk * 8], 132);
            to_tf32(af);
#pragma unroll
            for (int j = 0; j < 2; j++) {
                wmma::fragment<wmma::matrix_b, 16, 16, 8, wmma::precision::tf32, wmma::row_major> bf;
                wmma::load_matrix_sync(bf, &sV[(kk * 8) * 68 + wnn * 32 + j * 16], 68);
                to_tf32(bf);
                wmma::mma_sync(acc[j], af, bf, acc[j]);
            }
        }
        __syncthreads();
    }

#pragma unroll
    for (int j = 0; j < 2; j++)
        wmma::store_matrix_sync(&g_ctx[(size_t)(b * NS + m0 + wmm * 16) * ND + h * NDH + wnn * 32 + j * 16],
                                acc[j], ND, wmma::mem_row_major);
}

// ---------------------------------------------------------------------------
// Residual + LayerNorm
// ---------------------------------------------------------------------------
__global__ __launch_bounds__(256) void ln_kernel(const float* __restrict__ resid,
                                                 float* __restrict__ out) {
    const int row = blockIdx.x;
    const int tid = threadIdx.x;

    float4 f  = *(const float4*)&g_fc[(size_t)row * ND + tid * 4];
    float4 rr = *(const float4*)&resid[(size_t)row * ND + tid * 4];
    float4 y;
    y.x = f.x + rr.x; y.y = f.y + rr.y; y.z = f.z + rr.z; y.w = f.w + rr.w;

    float s = y.x + y.y + y.z + y.w;
    float q = y.x * y.x + y.y * y.y + y.z * y.z + y.w * y.w;
#pragma unroll
    for (int off = 16; off > 0; off >>= 1) {
        s += __shfl_down_sync(0xffffffffu, s, off);
        q += __shfl_down_sync(0xffffffffu, q, off);
    }
    __shared__ float ss[8], sq[8];
    __shared__ float mu_s, rs_s;
    if ((tid & 31) == 0) { ss[tid >> 5] = s; sq[tid >> 5] = q; }
    __syncthreads();
    if (tid == 0) {
        float S = 0.0f, Q = 0.0f;
#pragma unroll
        for (int i = 0; i < 8; i++) { S += ss[i]; Q += sq[i]; }
        float mu  = S * (1.0f / ND);
        float var = Q * (1.0f / ND) - mu * mu;
        mu_s = mu;
        rs_s = rsqrtf(var + LN_EPS);
    }
    __syncthreads();
    const float mu = mu_s, rs = rs_s;
    float4 o;
    o.x = (y.x - mu) * rs; o.y = (y.y - mu) * rs;
    o.z = (y.z - mu) * rs; o.w = (y.w - mu) * rs;
    *(float4*)&out[(size_t)row * ND + tid * 4] = o;
}

// ---------------------------------------------------------------------------
extern "C" void kernel_launch(void* const* d_in, const int* in_sizes, int n_in,
                              void* d_out, int out_size) {
    const float* inQ = (const float*)d_in[0];
    const float* inK = (const float*)d_in[1];
    const float* inV = (const float*)d_in[2];
    const unsigned char* mask = (const unsigned char*)d_in[3];
    const float* WQ  = (const float*)d_in[4];
    const float* WK  = (const float*)d_in[5];
    const float* WV  = (const float*)d_in[6];
    const float* Wfc = (const float*)d_in[7];

    float* out  = (float*)d_out;
    float* attn = out + OUT_ELEMS;

    void *pQ, *pK, *pV, *pCtx, *pFc;
    cudaGetSymbolAddress(&pQ, g_Q);
    cudaGetSymbolAddress(&pK, g_K);
    cudaGetSymbolAddress(&pV, g_V);
    cudaGetSymbolAddress(&pCtx, g_ctx);
    cudaGetSymbolAddress(&pFc, g_fc);

    cudaFuncSetAttribute(escore_kernel, cudaFuncAttributeMaxDynamicSharedMemorySize, ESCORE_SMEM);
    cudaFuncSetAttribute(ctxnorm_kernel, cudaFuncAttributeMaxDynamicSharedMemorySize, CTX_SMEM);

    dim3 gb(8, 32);
    gemm_db<<<gb, 256>>>(inQ, WQ, (float*)pQ);
    gemm_db<<<gb, 256>>>(inK, WK, (float*)pK);
    gemm_db<<<gb, 256>>>(inV, WV, (float*)pV);

    escore_kernel<<<dim3(16, 16, 32), 256, ESCORE_SMEM>>>(mask, attn);

    ctxnorm_kernel<<<dim3(32, 32), 256, CTX_SMEM>>>(attn);

    gemm_db<<<gb, 256>>>((const float*)pCtx, Wfc, (float*)pFc);

    ln_kernel<<<TOK, 256>>>(inQ, out);
}

// round 5
// speedup vs baseline: 1.4299x; 1.0917x over previous
#include <cuda_runtime.h>
#include <mma.h>
#include <cstdint>
#include <cstddef>

using namespace nvcuda;

// Problem shape (fixed): B=2, S=2048, D=1024, H=16, Dh=64
#define NB 2
#define NS 2048
#define ND 1024
#define NH 16
#define NDH 64
#define TOK (NB*NS)
#define OUT_ELEMS (4194304)
#define SCALE 0.125f
#define LN_EPS 1e-5f

// ---- scratch (__device__ globals; no allocation allowed) ----
__device__ float g_Q[TOK*ND];
__device__ float g_K[TOK*ND];
__device__ float g_V[TOK*ND];
__device__ float g_ctx[TOK*ND];
__device__ float g_fc[TOK*ND];
__device__ float g_inv[32 * NS];     // 1/rowsum per [bh][row]

// ---------------------------------------------------------------------------
template <typename Frag>
__device__ __forceinline__ void to_tf32(Frag& f) {
#pragma unroll
    for (int i = 0; i < f.num_elements; i++) f.x[i] = wmma::__float_to_tf32(f.x[i]);
}

__device__ __forceinline__ void cpa16(void* s, const void* g) {
    uint32_t sa = (uint32_t)__cvta_generic_to_shared(s);
    asm volatile("cp.async.ca.shared.global [%0], [%1], 16;" :: "r"(sa), "l"(g));
}
__device__ __forceinline__ void cpa_commit() {
    asm volatile("cp.async.commit_group;" ::: "memory");
}
template <int N>
__device__ __forceinline__ void cpa_wait() {
    asm volatile("cp.async.wait_group %0;" :: "n"(N) : "memory");
}

// ---------------------------------------------------------------------------
// Double-buffered tf32 GEMM body: C[.,1024] = A[.,1024] @ B[1024,1024].
// BM=128, BN=128, BK=16, 2-stage cp.async. 256 threads = 8 warps (2x4),
// warp tile 64x32. Shared by projection kernel and fc kernel.
// ---------------------------------------------------------------------------
__device__ __forceinline__ void gemm_body(const float* __restrict__ A,
                                          const float* __restrict__ Bw,
                                          float* __restrict__ C) {
    __shared__ float sA[2][128][20];
    __shared__ float sB[2][16][132];

    const int tid = threadIdx.x;
    const int w   = tid >> 5;
    const int wm  = w >> 2;
    const int wn  = w & 3;
    const int m0  = blockIdx.y * 128;
    const int n0  = blockIdx.x * 128;

    const int ar = tid >> 2, ac = (tid & 3) << 2;
    const int br = tid >> 5, bc = (tid & 31) << 2;

#define LOADT(st, k0)                                                                  \
    {                                                                                  \
        cpa16(&sA[st][ar][ac],      &A[(size_t)(m0 + ar)      * ND + (k0) + ac]);      \
        cpa16(&sA[st][ar + 64][ac], &A[(size_t)(m0 + ar + 64) * ND + (k0) + ac]);      \
        cpa16(&sB[st][br][bc],      &Bw[(size_t)((k0) + br)      * ND + n0 + bc]);     \
        cpa16(&sB[st][br + 8][bc],  &Bw[(size_t)((k0) + br + 8)  * ND + n0 + bc]);     \
        cpa_commit();                                                                  \
    }

    wmma::fragment<wmma::accumulator, 16, 16, 8, float> acc[4][2];
#pragma unroll
    for (int i = 0; i < 4; i++)
#pragma unroll
        for (int j = 0; j < 2; j++) wmma::fill_fragment(acc[i][j], 0.0f);

    LOADT(0, 0);

    for (int kt = 0; kt < 64; kt++) {
        if (kt < 63) {
            LOADT((kt + 1) & 1, (kt + 1) * 16);
            cpa_wait<1>();
        } else {
            cpa_wait<0>();
        }
        __syncthreads();
        const int st = kt & 1;
#pragma unroll
        for (int ks = 0; ks < 16; ks += 8) {
            wmma::fragment<wmma::matrix_a, 16, 16, 8, wmma::precision::tf32, wmma::row_major> af[4];
            wmma::fragment<wmma::matrix_b, 16, 16, 8, wmma::precision::tf32, wmma::row_major> bf[2];
#pragma unroll
            for (int i = 0; i < 4; i++) {
                wmma::load_matrix_sync(af[i], &sA[st][wm * 64 + i * 16][ks], 20);
                to_tf32(af[i]);
            }
#pragma unroll
            for (int j = 0; j < 2; j++) {
                wmma::load_matrix_sync(bf[j], &sB[st][ks][wn * 32 + j * 16], 132);
                to_tf32(bf[j]);
            }
#pragma unroll
            for (int i = 0; i < 4; i++)
#pragma unroll
                for (int j = 0; j < 2; j++)
                    wmma::mma_sync(acc[i][j], af[i], bf[j], acc[i][j]);
        }
        __syncthreads();
    }
#undef LOADT

#pragma unroll
    for (int i = 0; i < 4; i++)
#pragma unroll
        for (int j = 0; j < 2; j++)
            wmma::store_matrix_sync(&C[(size_t)(m0 + wm * 64 + i * 16) * ND + n0 + wn * 32 + j * 16],
                                    acc[i][j], ND, wmma::mem_row_major);
}

// All three projections in one launch: blockIdx.z selects (A, W, C).
__global__ __launch_bounds__(256, 2) void qkv_gemm(const float* __restrict__ iQ, const float* __restrict__ WQ,
                                                   const float* __restrict__ iK, const float* __restrict__ WK,
                                                   const float* __restrict__ iV, const float* __restrict__ WV,
                                                   float* __restrict__ oQ, float* __restrict__ oK,
                                                   float* __restrict__ oV) {
    const int z = blockIdx.z;
    const float* A  = (z == 0) ? iQ : (z == 1) ? iK : iV;
    const float* Bw = (z == 0) ? WQ : (z == 1) ? WK : WV;
    float*       C  = (z == 0) ? oQ : (z == 1) ? oK : oV;
    gemm_body(A, Bw, C);
}

__global__ __launch_bounds__(256, 2) void fc_gemm(const float* __restrict__ A,
                                                  const float* __restrict__ Bw,
                                                  float* __restrict__ C) {
    gemm_body(A, Bw, C);
}

// ---------------------------------------------------------------------------
// escore: one block owns a 128-row q-stripe of one (b,h); K streamed in 16
// double-buffered cp.async tiles. E = exp(scale*QK^T, masked) written
// unnormalized to attn buffer; FULL row sums accumulated in-block -> g_inv.
// grid = (16, 32), 512 threads = 16 warps (4x4), warp tile 32x32.
// ---------------------------------------------------------------------------
#define ESC_SMEM ((128*68 + 2*128*68 + 128*132 + 128) * 4)   // 172544 B

__global__ __launch_bounds__(512) void escore_kernel(const unsigned char* __restrict__ mask,
                                                     float* __restrict__ attnOut) {
    extern __shared__ float sm[];
    float* sQ   = sm;                       // 128 x 68
    float* sK   = sQ + 128 * 68;            // 2 x (128 x 68)
    float* sS   = sK + 2 * 128 * 68;        // 128 x 132
    float* sSum = sS + 128 * 132;           // 128

    const int tid = threadIdx.x;
    const int w   = tid >> 5;
    const int l   = tid & 31;
    const int bh  = blockIdx.y;
    const int b   = bh >> 4;
    const int h   = bh & 15;
    const int q0  = blockIdx.x * 128;

    const float* Qb = g_Q + ((size_t)(b * NS + q0)) * ND + h * NDH;
    const float* Kb = g_K + ((size_t)b * NS) * ND + h * NDH;

    // issue Q stripe + K tile 0 (one cp.async group)
#pragma unroll
    for (int i = 0; i < 4; i++) {
        int idx = tid + i * 512;
        int r = idx >> 4, c = (idx & 15) << 2;
        cpa16(&sQ[r * 68 + c], &Qb[(size_t)r * ND + c]);
        cpa16(&sK[r * 68 + c], &Kb[(size_t)r * ND + c]);
    }
    cpa_commit();
    if (tid < 128) sSum[tid] = 0.0f;

    const int wm = w >> 2, wn = w & 3;   // 4x4 warp grid, 32x32 tiles

    for (int ct = 0; ct < 16; ct++) {
        if (ct < 15) {
            float* dst = sK + ((ct + 1) & 1) * (128 * 68);
            const float* src = Kb + (size_t)(ct + 1) * 128 * ND;
#pragma unroll
            for (int i = 0; i < 4; i++) {
                int idx = tid + i * 512;
                int r = idx >> 4, c = (idx & 15) << 2;
                cpa16(&dst[r * 68 + c], &src[(size_t)r * ND + c]);
            }
            cpa_commit();
            cpa_wait<1>();
        } else {
            cpa_wait<0>();
        }
        __syncthreads();   // K[ct] ready; prior epilogue done (sS free)

        const float* sKt = sK + (ct & 1) * (128 * 68);
        wmma::fragment<wmma::accumulator, 16, 16, 8, float> acc[2][2];
#pragma unroll
        for (int i = 0; i < 2; i++)
#pragma unroll
            for (int j = 0; j < 2; j++) wmma::fill_fragment(acc[i][j], 0.0f);

#pragma unroll
        for (int kk = 0; kk < 8; kk++) {
            wmma::fragment<wmma::matrix_a, 16, 16, 8, wmma::precision::tf32, wmma::row_major> af[2];
            wmma::fragment<wmma::matrix_b, 16, 16, 8, wmma::precision::tf32, wmma::col_major> bf[2];
#pragma unroll
            for (int i = 0; i < 2; i++) {
                wmma::load_matrix_sync(af[i], &sQ[(wm * 32 + i * 16) * 68 + kk * 8], 68);
                to_tf32(af[i]);
            }
#pragma unroll
            for (int j = 0; j < 2; j++) {
                wmma::load_matrix_sync(bf[j], &sKt[(wn * 32 + j * 16) * 68 + kk * 8], 68);
                to_tf32(bf[j]);
            }
#pragma unroll
            for (int i = 0; i < 2; i++)
#pragma unroll
                for (int j = 0; j < 2; j++)
                    wmma::mma_sync(acc[i][j], af[i], bf[j], acc[i][j]);
        }
#pragma unroll
        for (int i = 0; i < 2; i++)
#pragma unroll
            for (int j = 0; j < 2; j++)
                wmma::store_matrix_sync(&sS[(wm * 32 + i * 16) * 132 + wn * 32 + j * 16],
                                        acc[i][j], 132, wmma::mem_row_major);
        __syncthreads();

        // epilogue: warp w handles rows {w, w+16, ..., w+112}, full 128 cols
        const int c0 = ct * 128;
#pragma unroll
        for (int it = 0; it < 8; it++) {
            const int row = it * 16 + w;
            float4 v = *(float4*)&sS[row * 132 + l * 4];
            const unsigned char* mrow = mask + ((size_t)(b * NS + q0 + row)) * NS + c0;
            uchar4 mk = *(const uchar4*)&mrow[l * 4];
            v.x = mk.x ? 0.0f : __expf(v.x * SCALE);
            v.y = mk.y ? 0.0f : __expf(v.y * SCALE);
            v.z = mk.z ? 0.0f : __expf(v.z * SCALE);
            v.w = mk.w ? 0.0f : __expf(v.w * SCALE);
            float* erow = attnOut + ((size_t)(bh * NS + q0 + row)) * NS + c0;
            *(float4*)&erow[l * 4] = v;
            float s = v.x + v.y + v.z + v.w;
#pragma unroll
            for (int off = 16; off > 0; off >>= 1) s += __shfl_xor_sync(0xffffffffu, s, off);
            if (l == 0) sSum[row] += s;   // one warp per row: no race, deterministic
        }
    }

    __syncthreads();
    if (tid < 128) g_inv[(size_t)bh * NS + q0 + tid] = 1.0f / sSum[tid];
}

// ---------------------------------------------------------------------------
// ctxnorm: per (bh, 64-row tile): stream E (normalize in smem, write
// normalized attn back, feed MMA) and V, both double-buffered cp.async.
// ctx = Enorm @ V_bh -> g_ctx ([B,S,H*Dh] layout). grid=(32,32), 256 thr.
// ---------------------------------------------------------------------------
#define CTX_SMEM ((2*64*132 + 2*128*68 + 64) * 4)   // 137472 B

__global__ __launch_bounds__(256) void ctxnorm_kernel(float* __restrict__ attn) {
    extern __shared__ float sm[];
    float* sE   = sm;                       // 2 x (64 x 132)  raw E chunks
    float* sV   = sE + 2 * 64 * 132;        // 2 x (128 x 68)
    float* sInv = sV + 2 * 128 * 68;        // 64

    const int tid = threadIdx.x;
    const int w   = tid >> 5;
    const int bh  = blockIdx.y;
    const int b   = bh >> 4;
    const int h   = bh & 15;
    const int m0  = blockIdx.x * 64;

    float* Eb = attn + ((size_t)bh * NS + m0) * NS;
    const float* Vb = g_V + ((size_t)b * NS) * ND + h * NDH;

    if (tid < 64) sInv[tid] = g_inv[(size_t)bh * NS + m0 + tid];

#define LOADC(st, k0)                                                                   \
    {                                                                                   \
        float* dE = sE + (st) * (64 * 132);                                             \
        float* dV = sV + (st) * (128 * 68);                                             \
        _Pragma("unroll")                                                               \
        for (int i = 0; i < 8; i++) {                                                   \
            int idx = tid + i * 256;                                                    \
            int er = idx >> 5, ec = (idx & 31) << 2;                                    \
            cpa16(&dE[er * 132 + ec], &Eb[(size_t)er * NS + (k0) + ec]);                \
            int vr = idx >> 4, vc = (idx & 15) << 2;                                    \
            cpa16(&dV[vr * 68 + vc], &Vb[(size_t)((k0) + vr) * ND + vc]);               \
        }                                                                               \
        cpa_commit();                                                                   \
    }

    LOADC(0, 0);

    const int wmm = w >> 1, wnn = w & 1;   // 4x2 warp grid, 16x32 tiles
    wmma::fragment<wmma::accumulator, 16, 16, 8, float> acc[2];
    wmma::fill_fragment(acc[0], 0.0f);
    wmma::fill_fragment(acc[1], 0.0f);

    for (int kc = 0; kc < 16; kc++) {
        if (kc < 15) {
            LOADC((kc + 1) & 1, (kc + 1) * 128);
            cpa_wait<1>();
        } else {
            cpa_wait<0>();
        }
        __syncthreads();   // chunk kc ready

        const int st = kc & 1;
        float* cE = sE + st * (64 * 132);
        const float* cV = sV + st * (128 * 68);
        const int k0 = kc * 128;

        // normalize in smem + write normalized attn back to global
#pragma unroll
        for (int i = 0; i < 8; i++) {
            int idx = tid + i * 256;
            int r = idx >> 5, c = (idx & 31) << 2;
            float4 v = *(float4*)&cE[r * 132 + c];
            float iv = sInv[r];
            v.x *= iv; v.y *= iv; v.z *= iv; v.w *= iv;
            *(float4*)&cE[r * 132 + c] = v;
            *(float4*)&Eb[(size_t)r * NS + k0 + c] = v;
        }
        __syncthreads();   // normalized data visible to all warps

#pragma unroll
        for (int kk = 0; kk < 16; kk++) {
            wmma::fragment<wmma::matrix_a, 16, 16, 8, wmma::precision::tf32, wmma::row_major> af;
            wmma::load_matrix_sync(af, &cE[(wmm * 16) * 132 + kk * 8], 132);
            to_tf32(af);
#pragma unroll
            for (int j = 0; j < 2; j++) {
                wmma::fragment<wmma::matrix_b, 16, 16, 8, wmma::precision::tf32, wmma::row_major> bf;
                wmma::load_matrix_sync(bf, &cV[(kk * 8) * 68 + wnn * 32 + j * 16], 68);
                to_tf32(bf);
                wmma::mma_sync(acc[j], af, bf, acc[j]);
            }
        }
        __syncthreads();   // MMA done before next prefetch overwrites this buffer
    }
#undef LOADC

#pragma unroll
    for (int j = 0; j < 2; j++)
        wmma::store_matrix_sync(&g_ctx[(size_t)(b * NS + m0 + wmm * 16) * ND + h * NDH + wnn * 32 + j * 16],
                                acc[j], ND, wmma::mem_row_major);
}

// ---------------------------------------------------------------------------
// Residual + LayerNorm
// ---------------------------------------------------------------------------
__global__ __launch_bounds__(256) void ln_kernel(const float* __restrict__ resid,
                                                 float* __restrict__ out) {
    const int row = blockIdx.x;
    const int tid = threadIdx.x;

    float4 f  = *(const float4*)&g_fc[(size_t)row * ND + tid * 4];
    float4 rr = *(const float4*)&resid[(size_t)row * ND + tid * 4];
    float4 y;
    y.x = f.x + rr.x; y.y = f.y + rr.y; y.z = f.z + rr.z; y.w = f.w + rr.w;

    float s = y.x + y.y + y.z + y.w;
    float q = y.x * y.x + y.y * y.y + y.z * y.z + y.w * y.w;
#pragma unroll
    for (int off = 16; off > 0; off >>= 1) {
        s += __shfl_down_sync(0xffffffffu, s, off);
        q += __shfl_down_sync(0xffffffffu, q, off);
    }
    __shared__ float ss[8], sq[8];
    __shared__ float mu_s, rs_s;
    if ((tid & 31) == 0) { ss[tid >> 5] = s; sq[tid >> 5] = q; }
    __syncthreads();
    if (tid == 0) {
        float S = 0.0f, Q = 0.0f;
#pragma unroll
        for (int i = 0; i < 8; i++) { S += ss[i]; Q += sq[i]; }
        float mu  = S * (1.0f / ND);
        float var = Q * (1.0f / ND) - mu * mu;
        mu_s = mu;
        rs_s = rsqrtf(var + LN_EPS);
    }
    __syncthreads();
    const float mu = mu_s, rs = rs_s;
    float4 o;
    o.x = (y.x - mu) * rs; o.y = (y.y - mu) * rs;
    o.z = (y.z - mu) * rs; o.w = (y.w - mu) * rs;
    *(float4*)&out[(size_t)row * ND + tid * 4] = o;
}

// ---------------------------------------------------------------------------
extern "C" void kernel_launch(void* const* d_in, const int* in_sizes, int n_in,
                              void* d_out, int out_size) {
    const float* inQ = (const float*)d_in[0];
    const float* inK = (const float*)d_in[1];
    const float* inV = (const float*)d_in[2];
    const unsigned char* mask = (const unsigned char*)d_in[3];
    const float* WQ  = (const float*)d_in[4];
    const float* WK  = (const float*)d_in[5];
    const float* WV  = (const float*)d_in[6];
    const float* Wfc = (const float*)d_in[7];

    float* out  = (float*)d_out;
    float* attn = out + OUT_ELEMS;

    void *pQ, *pK, *pV, *pCtx, *pFc;
    cudaGetSymbolAddress(&pQ, g_Q);
    cudaGetSymbolAddress(&pK, g_K);
    cudaGetSymbolAddress(&pV, g_V);
    cudaGetSymbolAddress(&pCtx, g_ctx);
    cudaGetSymbolAddress(&pFc, g_fc);

    cudaFuncSetAttribute(escore_kernel, cudaFuncAttributeMaxDynamicSharedMemorySize, ESC_SMEM);
    cudaFuncSetAttribute(ctxnorm_kernel, cudaFuncAttributeMaxDynamicSharedMemorySize, CTX_SMEM);

    qkv_gemm<<<dim3(8, 32, 3), 256>>>(inQ, WQ, inK, WK, inV, WV,
                                      (float*)pQ, (float*)pK, (float*)pV);

    escore_kernel<<<dim3(16, 32), 512, ESC_SMEM>>>(mask, attn);

    ctxnorm_kernel<<<dim3(32, 32), 256, CTX_SMEM>>>(attn);

    fc_gemm<<<dim3(8, 32), 256>>>((const float*)pCtx, Wfc, (float*)pFc);

    ln_kernel<<<TOK, 256>>>(inQ, out);
}

// round 6
// speedup vs baseline: 1.6535x; 1.1564x over previous
#include <cuda_runtime.h>
#include <cuda_bf16.h>
#include <mma.h>
#include <cstdint>
#include <cstddef>

using namespace nvcuda;

// Problem shape (fixed): B=2, S=2048, D=1024, H=16, Dh=64
#define NB 2
#define NS 2048
#define ND 1024
#define NH 16
#define NDH 64
#define TOK (NB*NS)
#define OUT_ELEMS (4194304)
#define SCALE 0.125f
#define LN_EPS 1e-5f

// ---- scratch (__device__ globals; no allocation allowed) ----
__device__ float g_Q[TOK*ND];
__device__ float g_K[TOK*ND];
__device__ float g_V[TOK*ND];
__device__ float g_fc[TOK*ND];
__device__ float g_inv[32 * NS];               // 1/rowsum per [bh][row]
__device__ __nv_bfloat16 g_Vh[TOK*ND];         // bf16 copy of V
__device__ __nv_bfloat16 g_Wfch[ND*ND];        // bf16 copy of W_fc
__device__ __nv_bfloat16 g_ctxh[TOK*ND];       // bf16 context

// ---------------------------------------------------------------------------
template <typename Frag>
__device__ __forceinline__ void to_tf32(Frag& f) {
#pragma unroll
    for (int i = 0; i < f.num_elements; i++) f.x[i] = wmma::__float_to_tf32(f.x[i]);
}

__device__ __forceinline__ void cpa16(void* s, const void* g) {
    uint32_t sa = (uint32_t)__cvta_generic_to_shared(s);
    asm volatile("cp.async.ca.shared.global [%0], [%1], 16;" :: "r"(sa), "l"(g));
}
__device__ __forceinline__ void cpa_commit() {
    asm volatile("cp.async.commit_group;" ::: "memory");
}
template <int N>
__device__ __forceinline__ void cpa_wait() {
    asm volatile("cp.async.wait_group %0;" :: "n"(N) : "memory");
}

__device__ __forceinline__ uint32_t pack_bf2(float a, float b) {
    __nv_bfloat162 t = __float22bfloat162_rn(make_float2(a, b));
    return *(uint32_t*)&t;
}

// ---------------------------------------------------------------------------
// f32 -> bf16 convert kernel (grid-stride over float4 groups)
// ---------------------------------------------------------------------------
__global__ __launch_bounds__(256) void cvt_kernel(const float* __restrict__ s,
                                                  __nv_bfloat16* __restrict__ d, int n) {
    int i = (blockIdx.x * 256 + threadIdx.x) * 4;
    if (i < n) {
        float4 v = *(const float4*)&s[i];
        uint32_t p0 = pack_bf2(v.x, v.y);
        uint32_t p1 = pack_bf2(v.z, v.w);
        *(uint32_t*)&d[i]     = p0;
        *(uint32_t*)&d[i + 2] = p1;
    }
}

// ---------------------------------------------------------------------------
// tf32 GEMM body, BK=32, 2-stage cp.async. C = A[.,1024] @ B[1024,1024].
// BM=128, BN=128. 256 threads = 8 warps (2x4), warp tile 64x32.
// ---------------------------------------------------------------------------
__device__ __forceinline__ void gemm_body(const float* __restrict__ A,
                                          const float* __restrict__ Bw,
                                          float* __restrict__ C) {
    __shared__ float sA[2][128][36];
    __shared__ float sB[2][32][132];

    const int tid = threadIdx.x;
    const int w   = tid >> 5;
    const int wm  = w >> 2;
    const int wn  = w & 3;
    const int m0  = blockIdx.y * 128;
    const int n0  = blockIdx.x * 128;

#define LOADT(st, k0)                                                                  \
    {                                                                                  \
        _Pragma("unroll")                                                              \
        for (int i = 0; i < 4; i++) {                                                  \
            int idx = tid + i * 256;                                                   \
            int ra = idx >> 3, ca = (idx & 7) << 2;                                    \
            cpa16(&sA[st][ra][ca], &A[(size_t)(m0 + ra) * ND + (k0) + ca]);            \
            int rb = idx >> 5, cb = (idx & 31) << 2;                                   \
            cpa16(&sB[st][rb][cb], &Bw[(size_t)((k0) + rb) * ND + n0 + cb]);           \
        }                                                                              \
        cpa_commit();                                                                  \
    }

    wmma::fragment<wmma::accumulator, 16, 16, 8, float> acc[4][2];
#pragma unroll
    for (int i = 0; i < 4; i++)
#pragma unroll
        for (int j = 0; j < 2; j++) wmma::fill_fragment(acc[i][j], 0.0f);

    LOADT(0, 0);

    for (int kt = 0; kt < 32; kt++) {
        if (kt < 31) {
            LOADT((kt + 1) & 1, (kt + 1) * 32);
            cpa_wait<1>();
        } else {
            cpa_wait<0>();
        }
        __syncthreads();
        const int st = kt & 1;
#pragma unroll
        for (int ks = 0; ks < 32; ks += 8) {
            wmma::fragment<wmma::matrix_a, 16, 16, 8, wmma::precision::tf32, wmma::row_major> af[4];
            wmma::fragment<wmma::matrix_b, 16, 16, 8, wmma::precision::tf32, wmma::row_major> bf[2];
#pragma unroll
            for (int i = 0; i < 4; i++) {
                wmma::load_matrix_sync(af[i], &sA[st][wm * 64 + i * 16][ks], 36);
                to_tf32(af[i]);
            }
#pragma unroll
            for (int j = 0; j < 2; j++) {
                wmma::load_matrix_sync(bf[j], &sB[st][ks][wn * 32 + j * 16], 132);
                to_tf32(bf[j]);
            }
#pragma unroll
            for (int i = 0; i < 4; i++)
#pragma unroll
                for (int j = 0; j < 2; j++)
                    wmma::mma_sync(acc[i][j], af[i], bf[j], acc[i][j]);
        }
        __syncthreads();
    }
#undef LOADT

#pragma unroll
    for (int i = 0; i < 4; i++)
#pragma unroll
        for (int j = 0; j < 2; j++)
            wmma::store_matrix_sync(&C[(size_t)(m0 + wm * 64 + i * 16) * ND + n0 + wn * 32 + j * 16],
                                    acc[i][j], ND, wmma::mem_row_major);
}

__global__ __launch_bounds__(256, 2) void qkv_gemm(const float* __restrict__ iQ, const float* __restrict__ WQ,
                                                   const float* __restrict__ iK, const float* __restrict__ WK,
                                                   const float* __restrict__ iV, const float* __restrict__ WV,
                                                   float* __restrict__ oQ, float* __restrict__ oK,
                                                   float* __restrict__ oV) {
    const int z = blockIdx.z;
    const float* A  = (z == 0) ? iQ : (z == 1) ? iK : iV;
    const float* Bw = (z == 0) ? WQ : (z == 1) ? WK : WV;
    float*       C  = (z == 0) ? oQ : (z == 1) ? oK : oV;
    gemm_body(A, Bw, C);
}

// ---------------------------------------------------------------------------
// bf16 fc GEMM: C[4096,1024] f32 = A[4096,1024] bf16 @ B[1024,1024] bf16.
// BM=128, BN=128, BK=32, 2-stage cp.async. 256 threads, warp tile 64x32.
// ---------------------------------------------------------------------------
__global__ __launch_bounds__(256, 2) void fc_gemm_bf16(const __nv_bfloat16* __restrict__ A,
                                                       const __nv_bfloat16* __restrict__ Bw,
                                                       float* __restrict__ C) {
    __shared__ __nv_bfloat16 sA[2][128][40];
    __shared__ __nv_bfloat16 sB[2][32][136];

    const int tid = threadIdx.x;
    const int w   = tid >> 5;
    const int wm  = w >> 2;
    const int wn  = w & 3;
    const int m0  = blockIdx.y * 128;
    const int n0  = blockIdx.x * 128;

#define LOADH(st, k0)                                                                  \
    {                                                                                  \
        _Pragma("unroll")                                                              \
        for (int i = 0; i < 2; i++) {                                                  \
            int idx = tid + i * 256;                                                   \
            int ra = idx >> 2, ca = (idx & 3) << 3;                                    \
            cpa16(&sA[st][ra][ca], &A[(size_t)(m0 + ra) * ND + (k0) + ca]);            \
            int rb = idx >> 4, cb = (idx & 15) << 3;                                   \
            cpa16(&sB[st][rb][cb], &Bw[(size_t)((k0) + rb) * ND + n0 + cb]);           \
        }                                                                              \
        cpa_commit();                                                                  \
    }

    wmma::fragment<wmma::accumulator, 16, 16, 16, float> acc[4][2];
#pragma unroll
    for (int i = 0; i < 4; i++)
#pragma unroll
        for (int j = 0; j < 2; j++) wmma::fill_fragment(acc[i][j], 0.0f);

    LOADH(0, 0);

    for (int kt = 0; kt < 32; kt++) {
        if (kt < 31) {
            LOADH((kt + 1) & 1, (kt + 1) * 32);
            cpa_wait<1>();
        } else {
            cpa_wait<0>();
        }
        __syncthreads();
        const int st = kt & 1;
#pragma unroll
        for (int ks = 0; ks < 32; ks += 16) {
            wmma::fragment<wmma::matrix_a, 16, 16, 16, __nv_bfloat16, wmma::row_major> af[4];
            wmma::fragment<wmma::matrix_b, 16, 16, 16, __nv_bfloat16, wmma::row_major> bf[2];
#pragma unroll
            for (int i = 0; i < 4; i++)
                wmma::load_matrix_sync(af[i], &sA[st][wm * 64 + i * 16][ks], 40);
#pragma unroll
            for (int j = 0; j < 2; j++)
                wmma::load_matrix_sync(bf[j], &sB[st][ks][wn * 32 + j * 16], 136);
#pragma unroll
            for (int i = 0; i < 4; i++)
#pragma unroll
                for (int j = 0; j < 2; j++)
                    wmma::mma_sync(acc[i][j], af[i], bf[j], acc[i][j]);
        }
        __syncthreads();
    }
#undef LOADH

#pragma unroll
    for (int i = 0; i < 4; i++)
#pragma unroll
        for (int j = 0; j < 2; j++)
            wmma::store_matrix_sync(&C[(size_t)(m0 + wm * 64 + i * 16) * ND + n0 + wn * 32 + j * 16],
                                    acc[i][j], ND, wmma::mem_row_major);
}

// ---------------------------------------------------------------------------
// escore: one block owns a 128-row q-stripe of one (b,h); K streamed in 16
// double-buffered cp.async tiles. E = exp(scale*QK^T, masked) written
// unnormalized to attn buffer; FULL row sums accumulated in-block -> g_inv.
// grid = (16, 32), 512 threads = 16 warps (4x4), warp tile 32x32.
// ---------------------------------------------------------------------------
#define ESC_SMEM ((128*68 + 2*128*68 + 128*132 + 128) * 4)   // 172544 B

__global__ __launch_bounds__(512) void escore_kernel(const unsigned char* __restrict__ mask,
                                                     float* __restrict__ attnOut) {
    extern __shared__ float sm[];
    float* sQ   = sm;                       // 128 x 68
    float* sK   = sQ + 128 * 68;            // 2 x (128 x 68)
    float* sS   = sK + 2 * 128 * 68;        // 128 x 132
    float* sSum = sS + 128 * 132;           // 128

    const int tid = threadIdx.x;
    const int w   = tid >> 5;
    const int l   = tid & 31;
    const int bh  = blockIdx.y;
    const int b   = bh >> 4;
    const int h   = bh & 15;
    const int q0  = blockIdx.x * 128;

    const float* Qb = g_Q + ((size_t)(b * NS + q0)) * ND + h * NDH;
    const float* Kb = g_K + ((size_t)b * NS) * ND + h * NDH;

#pragma unroll
    for (int i = 0; i < 4; i++) {
        int idx = tid + i * 512;
        int r = idx >> 4, c = (idx & 15) << 2;
        cpa16(&sQ[r * 68 + c], &Qb[(size_t)r * ND + c]);
        cpa16(&sK[r * 68 + c], &Kb[(size_t)r * ND + c]);
    }
    cpa_commit();
    if (tid < 128) sSum[tid] = 0.0f;

    const int wm = w >> 2, wn = w & 3;   // 4x4 warp grid, 32x32 tiles

    for (int ct = 0; ct < 16; ct++) {
        if (ct < 15) {
            float* dst = sK + ((ct + 1) & 1) * (128 * 68);
            const float* src = Kb + (size_t)(ct + 1) * 128 * ND;
#pragma unroll
            for (int i = 0; i < 4; i++) {
                int idx = tid + i * 512;
                int r = idx >> 4, c = (idx & 15) << 2;
                cpa16(&dst[r * 68 + c], &src[(size_t)r * ND + c]);
            }
            cpa_commit();
            cpa_wait<1>();
        } else {
            cpa_wait<0>();
        }
        __syncthreads();

        const float* sKt = sK + (ct & 1) * (128 * 68);
        wmma::fragment<wmma::accumulator, 16, 16, 8, float> acc[2][2];
#pragma unroll
        for (int i = 0; i < 2; i++)
#pragma unroll
            for (int j = 0; j < 2; j++) wmma::fill_fragment(acc[i][j], 0.0f);

#pragma unroll
        for (int kk = 0; kk < 8; kk++) {
            wmma::fragment<wmma::matrix_a, 16, 16, 8, wmma::precision::tf32, wmma::row_major> af[2];
            wmma::fragment<wmma::matrix_b, 16, 16, 8, wmma::precision::tf32, wmma::col_major> bf[2];
#pragma unroll
            for (int i = 0; i < 2; i++) {
                wmma::load_matrix_sync(af[i], &sQ[(wm * 32 + i * 16) * 68 + kk * 8], 68);
                to_tf32(af[i]);
            }
#pragma unroll
            for (int j = 0; j < 2; j++) {
                wmma::load_matrix_sync(bf[j], &sKt[(wn * 32 + j * 16) * 68 + kk * 8], 68);
                to_tf32(bf[j]);
            }
#pragma unroll
            for (int i = 0; i < 2; i++)
#pragma unroll
                for (int j = 0; j < 2; j++)
                    wmma::mma_sync(acc[i][j], af[i], bf[j], acc[i][j]);
        }
#pragma unroll
        for (int i = 0; i < 2; i++)
#pragma unroll
            for (int j = 0; j < 2; j++)
                wmma::store_matrix_sync(&sS[(wm * 32 + i * 16) * 132 + wn * 32 + j * 16],
                                        acc[i][j], 132, wmma::mem_row_major);
        __syncthreads();

        const int c0 = ct * 128;
#pragma unroll
        for (int it = 0; it < 8; it++) {
            const int row = it * 16 + w;
            float4 v = *(float4*)&sS[row * 132 + l * 4];
            const unsigned char* mrow = mask + ((size_t)(b * NS + q0 + row)) * NS + c0;
            uchar4 mk = *(const uchar4*)&mrow[l * 4];
            v.x = mk.x ? 0.0f : __expf(v.x * SCALE);
            v.y = mk.y ? 0.0f : __expf(v.y * SCALE);
            v.z = mk.z ? 0.0f : __expf(v.z * SCALE);
            v.w = mk.w ? 0.0f : __expf(v.w * SCALE);
            float* erow = attnOut + ((size_t)(bh * NS + q0 + row)) * NS + c0;
            *(float4*)&erow[l * 4] = v;
            float s = v.x + v.y + v.z + v.w;
#pragma unroll
            for (int off = 16; off > 0; off >>= 1) s += __shfl_xor_sync(0xffffffffu, s, off);
            if (l == 0) sSum[row] += s;
        }
    }

    __syncthreads();
    if (tid < 128) g_inv[(size_t)bh * NS + q0 + tid] = 1.0f / sSum[tid];
}

// ---------------------------------------------------------------------------
// ctxnorm v2: per (bh, 128-row tile): stream E (f32, double-buffered cp.async),
// normalize in registers -> write normalized attn f32 to global AND bf16 copy
// to smem; bf16 MMA with pre-converted bf16 V (double-buffered).
// ctx output written bf16 to g_ctxh. grid=(16,32), 512 threads = 16 warps.
// ---------------------------------------------------------------------------
#define CTXV2_ERAW  (2 * 128 * 132 * 4)                 // 135168
#define CTXV2_VH    (2 * 128 * 72 * 2)                  // 36864
#define CTXV2_PB    (128 * 136 * 2)                     // 34816
#define CTX_SMEM    (CTXV2_ERAW + CTXV2_VH + CTXV2_PB + 512)   // 207360

__global__ __launch_bounds__(512) void ctxnorm_kernel(float* __restrict__ attn) {
    extern __shared__ char smc[];
    float*         sEraw = (float*)smc;                                  // 2 x 128 x 132
    __nv_bfloat16* sVh   = (__nv_bfloat16*)(smc + CTXV2_ERAW);           // 2 x 128 x 72
    __nv_bfloat16* sPb   = (__nv_bfloat16*)(smc + CTXV2_ERAW + CTXV2_VH); // 128 x 136
    float*         sInv  = (float*)(smc + CTXV2_ERAW + CTXV2_VH + CTXV2_PB); // 128

    const int tid = threadIdx.x;
    const int w   = tid >> 5;
    const int bh  = blockIdx.y;
    const int b   = bh >> 4;
    const int h   = bh & 15;
    const int m0  = blockIdx.x * 128;

    float* Eb = attn + ((size_t)bh * NS + m0) * NS;
    const __nv_bfloat16* Vb = g_Vh + ((size_t)b * NS) * ND + h * NDH;

    if (tid < 128) sInv[tid] = g_inv[(size_t)bh * NS + m0 + tid];

#define LOADC(st, k0)                                                                   \
    {                                                                                   \
        float* dE = sEraw + (st) * (128 * 132);                                         \
        __nv_bfloat16* dV = sVh + (st) * (128 * 72);                                    \
        _Pragma("unroll")                                                               \
        for (int i = 0; i < 8; i++) {                                                   \
            int idx = tid + i * 512;                                                    \
            int er = idx >> 5, ec = (idx & 31) << 2;                                    \
            cpa16(&dE[er * 132 + ec], &Eb[(size_t)er * NS + (k0) + ec]);                \
        }                                                                               \
        _Pragma("unroll")                                                               \
        for (int i = 0; i < 2; i++) {                                                   \
            int idx = tid + i * 512;                                                    \
            int vr = idx >> 3, vc = (idx & 7) << 3;                                     \
            cpa16(&dV[vr * 72 + vc], &Vb[(size_t)((k0) + vr) * ND + vc]);               \
        }                                                                               \
        cpa_commit();                                                                   \
    }

    LOADC(0, 0);

    const int wm = w >> 2, wn = w & 3;   // 4x4 warp grid, warp tile 32(m) x 16(n)
    wmma::fragment<wmma::accumulator, 16, 16, 16, float> acc[2];
    wmma::fill_fragment(acc[0], 0.0f);
    wmma::fill_fragment(acc[1], 0.0f);

    for (int kc = 0; kc < 16; kc++) {
        if (kc < 15) {
            LOADC((kc + 1) & 1, (kc + 1) * 128);
            cpa_wait<1>();
        } else {
            cpa_wait<0>();
        }
        __syncthreads();   // chunk kc ready; prior MMA done (buffer reuse safe)

        const int st = kc & 1;
        const float* cE = sEraw + st * (128 * 132);
        const __nv_bfloat16* cV = sVh + st * (128 * 72);
        const int k0 = kc * 128;

        // normalize: f32 -> global (normalized attn) + bf16 -> sPb for MMA
#pragma unroll
        for (int i = 0; i < 8; i++) {
            int idx = tid + i * 512;
            int r = idx >> 5, c = (idx & 31) << 2;
            float4 v = *(const float4*)&cE[r * 132 + c];
            float iv = sInv[r];
            v.x *= iv; v.y *= iv; v.z *= iv; v.w *= iv;
            *(float4*)&Eb[(size_t)r * NS + k0 + c] = v;
            uint32_t p0 = pack_bf2(v.x, v.y);
            uint32_t p1 = pack_bf2(v.z, v.w);
            *(uint32_t*)&sPb[r * 136 + c]     = p0;
            *(uint32_t*)&sPb[r * 136 + c + 2] = p1;
        }
        __syncthreads();   // sPb complete

#pragma unroll
        for (int kk = 0; kk < 8; kk++) {
            wmma::fragment<wmma::matrix_a, 16, 16, 16, __nv_bfloat16, wmma::row_major> af[2];
            wmma::fragment<wmma::matrix_b, 16, 16, 16, __nv_bfloat16, wmma::row_major> bf;
#pragma unroll
            for (int i = 0; i < 2; i++)
                wmma::load_matrix_sync(af[i], &sPb[(wm * 32 + i * 16) * 136 + kk * 16], 136);
            wmma::load_matrix_sync(bf, &cV[(kk * 16) * 72 + wn * 16], 72);
#pragma unroll
            for (int i = 0; i < 2; i++)
                wmma::mma_sync(acc[i], af[i], bf, acc[i]);
        }
        __syncthreads();   // MMA done before sPb rewrite / buffer reuse
    }
#undef LOADC

    // epilogue: stage acc f32 in sEraw (per-warp region), convert to bf16 ctx
    float* stg = sEraw + w * (32 * 20);
    wmma::store_matrix_sync(&stg[0],       acc[0], 20, wmma::mem_row_major);
    wmma::store_matrix_sync(&stg[16 * 20], acc[1], 20, wmma::mem_row_major);
    __syncwarp();
    {
        const int r = tid & 31;
        const float* row = stg + r * 20;
        uint32_t pk[8];
#pragma unroll
        for (int j = 0; j < 8; j++) pk[j] = pack_bf2(row[2 * j], row[2 * j + 1]);
        __nv_bfloat16* gp = g_ctxh + (size_t)(b * NS + m0 + wm * 32 + r) * ND + h * NDH + wn * 16;
        *(uint4*)gp       = make_uint4(pk[0], pk[1], pk[2], pk[3]);
        *(uint4*)(gp + 8) = make_uint4(pk[4], pk[5], pk[6], pk[7]);
    }
}

// ---------------------------------------------------------------------------
// Residual + LayerNorm
// ---------------------------------------------------------------------------
__global__ __launch_bounds__(256) void ln_kernel(const float* __restrict__ resid,
                                                 float* __restrict__ out) {
    const int row = blockIdx.x;
    const int tid = threadIdx.x;

    float4 f  = *(const float4*)&g_fc[(size_t)row * ND + tid * 4];
    float4 rr = *(const float4*)&resid[(size_t)row * ND + tid * 4];
    float4 y;
    y.x = f.x + rr.x; y.y = f.y + rr.y; y.z = f.z + rr.z; y.w = f.w + rr.w;

    float s = y.x + y.y + y.z + y.w;
    float q = y.x * y.x + y.y * y.y + y.z * y.z + y.w * y.w;
#pragma unroll
    for (int off = 16; off > 0; off >>= 1) {
        s += __shfl_down_sync(0xffffffffu, s, off);
        q += __shfl_down_sync(0xffffffffu, q, off);
    }
    __shared__ float ss[8], sq[8];
    __shared__ float mu_s, rs_s;
    if ((tid & 31) == 0) { ss[tid >> 5] = s; sq[tid >> 5] = q; }
    __syncthreads();
    if (tid == 0) {
        float S = 0.0f, Q = 0.0f;
#pragma unroll
        for (int i = 0; i < 8; i++) { S += ss[i]; Q += sq[i]; }
        float mu  = S * (1.0f / ND);
        float var = Q * (1.0f / ND) - mu * mu;
        mu_s = mu;
        rs_s = rsqrtf(var + LN_EPS);
    }
    __syncthreads();
    const float mu = mu_s, rs = rs_s;
    float4 o;
    o.x = (y.x - mu) * rs; o.y = (y.y - mu) * rs;
    o.z = (y.z - mu) * rs; o.w = (y.w - mu) * rs;
    *(float4*)&out[(size_t)row * ND + tid * 4] = o;
}

// ---------------------------------------------------------------------------
extern "C" void kernel_launch(void* const* d_in, const int* in_sizes, int n_in,
                              void* d_out, int out_size) {
    const float* inQ = (const float*)d_in[0];
    const float* inK = (const float*)d_in[1];
    const float* inV = (const float*)d_in[2];
    const unsigned char* mask = (const unsigned char*)d_in[3];
    const float* WQ  = (const float*)d_in[4];
    const float* WK  = (const float*)d_in[5];
    const float* WV  = (const float*)d_in[6];
    const float* Wfc = (const float*)d_in[7];

    float* out  = (float*)d_out;
    float* attn = out + OUT_ELEMS;

    void *pQ, *pK, *pV, *pFc, *pVh, *pWfch, *pCtxh;
    cudaGetSymbolAddress(&pQ, g_Q);
    cudaGetSymbolAddress(&pK, g_K);
    cudaGetSymbolAddress(&pV, g_V);
    cudaGetSymbolAddress(&pFc, g_fc);
    cudaGetSymbolAddress(&pVh, g_Vh);
    cudaGetSymbolAddress(&pWfch, g_Wfch);
    cudaGetSymbolAddress(&pCtxh, g_ctxh);

    cudaFuncSetAttribute(escore_kernel, cudaFuncAttributeMaxDynamicSharedMemorySize, ESC_SMEM);
    cudaFuncSetAttribute(ctxnorm_kernel, cudaFuncAttributeMaxDynamicSharedMemorySize, CTX_SMEM);

    qkv_gemm<<<dim3(8, 32, 3), 256>>>(inQ, WQ, inK, WK, inV, WV,
                                      (float*)pQ, (float*)pK, (float*)pV);

    // bf16 copies for the insensitive (context/fc) path
    cvt_kernel<<<(TOK * ND / 4 + 255) / 256, 256>>>((const float*)pV, (__nv_bfloat16*)pVh, TOK * ND);
    cvt_kernel<<<(ND * ND / 4 + 255) / 256, 256>>>(Wfc, (__nv_bfloat16*)pWfch, ND * ND);

    escore_kernel<<<dim3(16, 32), 512, ESC_SMEM>>>(mask, attn);

    ctxnorm_kernel<<<dim3(16, 32), 512, CTX_SMEM>>>(attn);

    fc_gemm_bf16<<<dim3(8, 32), 256>>>((const __nv_bfloat16*)pCtxh, (const __nv_bfloat16*)pWfch,
                                       (float*)pFc);

    ln_kernel<<<TOK, 256>>>(inQ, out);
}

// round 8
// speedup vs baseline: 1.7449x; 1.0553x over previous
#include <cuda_runtime.h>
#include <cuda_bf16.h>
#include <mma.h>
#include <cstdint>
#include <cstddef>

using namespace nvcuda;

// Problem shape (fixed): B=2, S=2048, D=1024, H=16, Dh=64
#define NB 2
#define NS 2048
#define ND 1024
#define NH 16
#define NDH 64
#define TOK (NB*NS)
#define OUT_ELEMS (4194304)
#define SCALE 0.125f
#define LN_EPS 1e-5f

// ---- scratch (__device__ globals; no allocation allowed) ----
__device__ float g_Q[TOK*ND];
__device__ float g_K[TOK*ND];
__device__ float g_V[TOK*ND];
__device__ float g_fc[TOK*ND];
__device__ float g_inv[32 * NS];               // 1/rowsum per [bh][row]
__device__ __nv_bfloat16 g_Vh[TOK*ND];         // bf16 copy of V
__device__ __nv_bfloat16 g_Wfch[ND*ND];        // bf16 copy of W_fc
__device__ __nv_bfloat16 g_ctxh[TOK*ND];       // bf16 context

// ---------------------------------------------------------------------------
template <typename Frag>
__device__ __forceinline__ void to_tf32(Frag& f) {
#pragma unroll
    for (int i = 0; i < f.num_elements; i++) f.x[i] = wmma::__float_to_tf32(f.x[i]);
}

__device__ __forceinline__ void cpa16(void* s, const void* g) {
    uint32_t sa = (uint32_t)__cvta_generic_to_shared(s);
    asm volatile("cp.async.ca.shared.global [%0], [%1], 16;" :: "r"(sa), "l"(g));
}
__device__ __forceinline__ void cpa_commit() {
    asm volatile("cp.async.commit_group;" ::: "memory");
}
template <int N>
__device__ __forceinline__ void cpa_wait() {
    asm volatile("cp.async.wait_group %0;" :: "n"(N) : "memory");
}

__device__ __forceinline__ uint32_t pack_bf2(float a, float b) {
    __nv_bfloat162 t = __float22bfloat162_rn(make_float2(a, b));
    return *(uint32_t*)&t;
}

// ---------------------------------------------------------------------------
// f32 -> bf16 convert kernel
// ---------------------------------------------------------------------------
__global__ __launch_bounds__(256) void cvt_kernel(const float* __restrict__ s,
                                                  __nv_bfloat16* __restrict__ d, int n) {
    int i = (blockIdx.x * 256 + threadIdx.x) * 4;
    if (i < n) {
        float4 v = *(const float4*)&s[i];
        uint32_t p0 = pack_bf2(v.x, v.y);
        uint32_t p1 = pack_bf2(v.z, v.w);
        *(uint32_t*)&d[i]     = p0;
        *(uint32_t*)&d[i + 2] = p1;
    }
}

// ---------------------------------------------------------------------------
// tf32 GEMM body, BK=32, 2-stage cp.async. C = A[.,1024] @ B[1024,1024].
// ---------------------------------------------------------------------------
__device__ __forceinline__ void gemm_body(const float* __restrict__ A,
                                          const float* __restrict__ Bw,
                                          float* __restrict__ C) {
    __shared__ float sA[2][128][36];
    __shared__ float sB[2][32][132];

    const int tid = threadIdx.x;
    const int w   = tid >> 5;
    const int wm  = w >> 2;
    const int wn  = w & 3;
    const int m0  = blockIdx.y * 128;
    const int n0  = blockIdx.x * 128;

#define LOADT(st, k0)                                                                  \
    {                                                                                  \
        _Pragma("unroll")                                                              \
        for (int i = 0; i < 4; i++) {                                                  \
            int idx = tid + i * 256;                                                   \
            int ra = idx >> 3, ca = (idx & 7) << 2;                                    \
            cpa16(&sA[st][ra][ca], &A[(size_t)(m0 + ra) * ND + (k0) + ca]);            \
            int rb = idx >> 5, cb = (idx & 31) << 2;                                   \
            cpa16(&sB[st][rb][cb], &Bw[(size_t)((k0) + rb) * ND + n0 + cb]);           \
        }                                                                              \
        cpa_commit();                                                                  \
    }

    wmma::fragment<wmma::accumulator, 16, 16, 8, float> acc[4][2];
#pragma unroll
    for (int i = 0; i < 4; i++)
#pragma unroll
        for (int j = 0; j < 2; j++) wmma::fill_fragment(acc[i][j], 0.0f);

    LOADT(0, 0);

    for (int kt = 0; kt < 32; kt++) {
        if (kt < 31) {
            LOADT((kt + 1) & 1, (kt + 1) * 32);
            cpa_wait<1>();
        } else {
            cpa_wait<0>();
        }
        __syncthreads();
        const int st = kt & 1;
#pragma unroll
        for (int ks = 0; ks < 32; ks += 8) {
            wmma::fragment<wmma::matrix_a, 16, 16, 8, wmma::precision::tf32, wmma::row_major> af[4];
            wmma::fragment<wmma::matrix_b, 16, 16, 8, wmma::precision::tf32, wmma::row_major> bf[2];
#pragma unroll
            for (int i = 0; i < 4; i++) {
                wmma::load_matrix_sync(af[i], &sA[st][wm * 64 + i * 16][ks], 36);
                to_tf32(af[i]);
            }
#pragma unroll
            for (int j = 0; j < 2; j++) {
                wmma::load_matrix_sync(bf[j], &sB[st][ks][wn * 32 + j * 16], 132);
                to_tf32(bf[j]);
            }
#pragma unroll
            for (int i = 0; i < 4; i++)
#pragma unroll
                for (int j = 0; j < 2; j++)
                    wmma::mma_sync(acc[i][j], af[i], bf[j], acc[i][j]);
        }
        __syncthreads();
    }
#undef LOADT

#pragma unroll
    for (int i = 0; i < 4; i++)
#pragma unroll
        for (int j = 0; j < 2; j++)
            wmma::store_matrix_sync(&C[(size_t)(m0 + wm * 64 + i * 16) * ND + n0 + wn * 32 + j * 16],
                                    acc[i][j], ND, wmma::mem_row_major);
}

__global__ __launch_bounds__(256, 2) void qkv_gemm(const float* __restrict__ iQ, const float* __restrict__ WQ,
                                                   const float* __restrict__ iK, const float* __restrict__ WK,
                                                   const float* __restrict__ iV, const float* __restrict__ WV,
                                                   float* __restrict__ oQ, float* __restrict__ oK,
                                                   float* __restrict__ oV) {
    const int z = blockIdx.z;
    const float* A  = (z == 0) ? iQ : (z == 1) ? iK : iV;
    const float* Bw = (z == 0) ? WQ : (z == 1) ? WK : WV;
    float*       C  = (z == 0) ? oQ : (z == 1) ? oK : oV;
    gemm_body(A, Bw, C);
}

// ---------------------------------------------------------------------------
// bf16 fc GEMM: C[4096,1024] f32 = A bf16 @ B bf16. BK=32, 2-stage.
// ---------------------------------------------------------------------------
__global__ __launch_bounds__(256, 2) void fc_gemm_bf16(const __nv_bfloat16* __restrict__ A,
                                                       const __nv_bfloat16* __restrict__ Bw,
                                                       float* __restrict__ C) {
    __shared__ __nv_bfloat16 sA[2][128][40];
    __shared__ __nv_bfloat16 sB[2][32][136];

    const int tid = threadIdx.x;
    const int w   = tid >> 5;
    const int wm  = w >> 2;
    const int wn  = w & 3;
    const int m0  = blockIdx.y * 128;
    const int n0  = blockIdx.x * 128;

#define LOADH(st, k0)                                                                  \
    {                                                                                  \
        _Pragma("unroll")                                                              \
        for (int i = 0; i < 2; i++) {                                                  \
            int idx = tid + i * 256;                                                   \
            int ra = idx >> 2, ca = (idx & 3) << 3;                                    \
            cpa16(&sA[st][ra][ca], &A[(size_t)(m0 + ra) * ND + (k0) + ca]);            \
            int rb = idx >> 4, cb = (idx & 15) << 3;                                   \
            cpa16(&sB[st][rb][cb], &Bw[(size_t)((k0) + rb) * ND + n0 + cb]);           \
        }                                                                              \
        cpa_commit();                                                                  \
    }

    wmma::fragment<wmma::accumulator, 16, 16, 16, float> acc[4][2];
#pragma unroll
    for (int i = 0; i < 4; i++)
#pragma unroll
        for (int j = 0; j < 2; j++) wmma::fill_fragment(acc[i][j], 0.0f);

    LOADH(0, 0);

    for (int kt = 0; kt < 32; kt++) {
        if (kt < 31) {
            LOADH((kt + 1) & 1, (kt + 1) * 32);
            cpa_wait<1>();
        } else {
            cpa_wait<0>();
        }
        __syncthreads();
        const int st = kt & 1;
#pragma unroll
        for (int ks = 0; ks < 32; ks += 16) {
            wmma::fragment<wmma::matrix_a, 16, 16, 16, __nv_bfloat16, wmma::row_major> af[4];
            wmma::fragment<wmma::matrix_b, 16, 16, 16, __nv_bfloat16, wmma::row_major> bf[2];
#pragma unroll
            for (int i = 0; i < 4; i++)
                wmma::load_matrix_sync(af[i], &sA[st][wm * 64 + i * 16][ks], 40);
#pragma unroll
            for (int j = 0; j < 2; j++)
                wmma::load_matrix_sync(bf[j], &sB[st][ks][wn * 32 + j * 16], 136);
#pragma unroll
            for (int i = 0; i < 4; i++)
#pragma unroll
                for (int j = 0; j < 2; j++)
                    wmma::mma_sync(acc[i][j], af[i], bf[j], acc[i][j]);
        }
        __syncthreads();
    }
#undef LOADH

#pragma unroll
    for (int i = 0; i < 4; i++)
#pragma unroll
        for (int j = 0; j < 2; j++)
            wmma::store_matrix_sync(&C[(size_t)(m0 + wm * 64 + i * 16) * ND + n0 + wn * 32 + j * 16],
                                    acc[i][j], ND, wmma::mem_row_major);
}

// ---------------------------------------------------------------------------
// escore v3 — WARP SPECIALIZED. One block = 128-row q-stripe of one (b,h).
// K streamed in 32 tiles of 64 keys, double-buffered cp.async.
// Warps 0-7: tf32 MMA of tile ct into sS[ct&1].
// Warps 8-15: epilogue (exp+mask+global store+rowsum) of tile ct-1 from
// sS[(ct-1)&1]. Tensor and exp/store phases overlap in steady state.
// grid = (16, 32), 512 threads.
// ---------------------------------------------------------------------------
#define ESC_SMEM ((128*68 + 2*64*68 + 2*128*68 + 128) * 4)   // 139776 B

__global__ __launch_bounds__(512) void escore_kernel(const unsigned char* __restrict__ mask,
                                                     float* __restrict__ attnOut) {
    extern __shared__ float sm[];
    float* sQ   = sm;                        // 128 x 68
    float* sK   = sQ + 128 * 68;             // 2 x (64 x 68)
    float* sS   = sK + 2 * 64 * 68;          // 2 x (128 x 68)
    float* sSum = sS + 2 * 128 * 68;         // 128

    const int tid = threadIdx.x;
    const int w   = tid >> 5;
    const int l   = tid & 31;
    const int bh  = blockIdx.y;
    const int b   = bh >> 4;
    const int h   = bh & 15;
    const int q0  = blockIdx.x * 128;

    const float* Qb = g_Q + ((size_t)(b * NS + q0)) * ND + h * NDH;
    const float* Kb = g_K + ((size_t)b * NS) * ND + h * NDH;

    // initial group: Q stripe (2048 f4) + K tile 0 (1024 f4)
#pragma unroll
    for (int i = 0; i < 4; i++) {
        int idx = tid + i * 512;
        int r = idx >> 4, c = (idx & 15) << 2;
        cpa16(&sQ[r * 68 + c], &Qb[(size_t)r * ND + c]);
        if (i < 2) cpa16(&sK[r * 68 + c], &Kb[(size_t)r * ND + c]);
    }
    cpa_commit();
    if (tid < 128) sSum[tid] = 0.0f;

    const int wm = w >> 1, wn = w & 1;      // MMA warps: 4(m) x 2(n), 32x32 tiles
    const int band = (w - 8) * 16;          // epi warps: 16-row band

    for (int ct = 0; ct <= 32; ct++) {
        __syncthreads();   // A: prior compute done -> safe to overwrite buffers
        if (ct < 32) {
            if (ct + 1 < 32) {
                float* dst = sK + ((ct + 1) & 1) * (64 * 68);
                const float* src = Kb + (size_t)(ct + 1) * 64 * ND;
#pragma unroll
                for (int i = 0; i < 2; i++) {
                    int idx = tid + i * 512;
                    int r = idx >> 4, c = (idx & 15) << 2;
                    cpa16(&dst[r * 68 + c], &src[(size_t)r * ND + c]);
                }
                cpa_commit();
                cpa_wait<1>();
            } else {
                cpa_wait<0>();
            }
        }
        __syncthreads();   // B: K[ct] + sS[(ct-1)&1] visible to everyone

        if (w < 8) {
            if (ct < 32) {
                const float* sKt = sK + (ct & 1) * (64 * 68);
                float* sSt = sS + (ct & 1) * (128 * 68);
                wmma::fragment<wmma::accumulator, 16, 16, 8, float> acc[2][2];
#pragma unroll
                for (int i = 0; i < 2; i++)
#pragma unroll
                    for (int j = 0; j < 2; j++) wmma::fill_fragment(acc[i][j], 0.0f);
#pragma unroll
                for (int kk = 0; kk < 8; kk++) {
                    wmma::fragment<wmma::matrix_a, 16, 16, 8, wmma::precision::tf32, wmma::row_major> af[2];
                    wmma::fragment<wmma::matrix_b, 16, 16, 8, wmma::precision::tf32, wmma::col_major> bf[2];
#pragma unroll
                    for (int i = 0; i < 2; i++) {
                        wmma::load_matrix_sync(af[i], &sQ[(wm * 32 + i * 16) * 68 + kk * 8], 68);
                        to_tf32(af[i]);
                    }
#pragma unroll
                    for (int j = 0; j < 2; j++) {
                        wmma::load_matrix_sync(bf[j], &sKt[(wn * 32 + j * 16) * 68 + kk * 8], 68);
                        to_tf32(bf[j]);
                    }
#pragma unroll
                    for (int i = 0; i < 2; i++)
#pragma unroll
                        for (int j = 0; j < 2; j++)
                            wmma::mma_sync(acc[i][j], af[i], bf[j], acc[i][j]);
                }
#pragma unroll
                for (int i = 0; i < 2; i++)
#pragma unroll
                    for (int j = 0; j < 2; j++)
                        wmma::store_matrix_sync(&sSt[(wm * 32 + i * 16) * 68 + wn * 32 + j * 16],
                                                acc[i][j], 68, wmma::mem_row_major);
            }
        } else if (ct >= 1) {
            const int tp = ct - 1;
            const float* sSt = sS + (tp & 1) * (128 * 68);
            const int c0 = tp * 64;
#pragma unroll
            for (int i = 0; i < 8; i++) {
                int idx = i * 32 + l;
                int r = band + (idx >> 4);
                int cc = (idx & 15) << 2;
                float4 v = *(const float4*)&sSt[r * 68 + cc];
                const unsigned char* mrow = mask + ((size_t)(b * NS + q0 + r)) * NS + c0;
                uchar4 mk = *(const uchar4*)&mrow[cc];
                v.x = mk.x ? 0.0f : __expf(v.x * SCALE);
                v.y = mk.y ? 0.0f : __expf(v.y * SCALE);
                v.z = mk.z ? 0.0f : __expf(v.z * SCALE);
                v.w = mk.w ? 0.0f : __expf(v.w * SCALE);
                float* erow = attnOut + ((size_t)(bh * NS + q0 + r)) * NS + c0;
                *(float4*)&erow[cc] = v;
                float s = v.x + v.y + v.z + v.w;
#pragma unroll
                for (int off = 8; off > 0; off >>= 1)
                    s += __shfl_xor_sync(0xffffffffu, s, off);
                if ((l & 15) == 0) sSum[r] += s;   // unique (warp,halfwarp) per row
            }
        }
    }

    __syncthreads();
    if (tid < 128) g_inv[(size_t)bh * NS + q0 + tid] = 1.0f / sSum[tid];
}

// ---------------------------------------------------------------------------
// ctxnorm v3.1 — WARP SPECIALIZED, V-prefetch LAGGED to match the MMA's
// one-iteration lag (fixes the round-7 buffer race).
// One block = 128-row m-tile of one (b,h). 32 chunks of 64 keys.
// Iter kc: prefetch group = { E[kc+1] (if exists), V[kc] }.
//   Warps 0-7:  normalize E[kc] (f32 -> global attn; bf16 -> sPb[kc&1]).
//   Warps 8-15: bf16 MMA of chunk kc-1: sPb[(kc-1)&1] x sVh[(kc-1)&1].
// V[j] lives in sVh[j&1]; writer of V[kc] (parity kc) never collides with
// the concurrent reader of V[kc-1] (parity kc-1); V[kc-2]'s slot is reused
// only after barrier A of iter kc, by which time its MMA (iter kc-1) is done.
// grid = (16, 32), 512 threads.
// ---------------------------------------------------------------------------
#define CTX_ER   (2 * 128 * 68 * 4)     // 69632
#define CTX_VH   (2 * 64 * 72 * 2)      // 18432
#define CTX_PB   (2 * 128 * 72 * 2)     // 73728
#define CTX_SMEM (CTX_ER + CTX_VH + CTX_PB + 512)   // 162304

__global__ __launch_bounds__(512) void ctxnorm_kernel(float* __restrict__ attn) {
    extern __shared__ char smc[];
    float*         sEraw = (float*)smc;                               // 2 x 128 x 68
    __nv_bfloat16* sVh   = (__nv_bfloat16*)(smc + CTX_ER);            // 2 x 64 x 72
    __nv_bfloat16* sPb   = (__nv_bfloat16*)(smc + CTX_ER + CTX_VH);   // 2 x 128 x 72
    float*         sInv  = (float*)(smc + CTX_ER + CTX_VH + CTX_PB);  // 128

    const int tid = threadIdx.x;
    const int w   = tid >> 5;
    const int l   = tid & 31;
    const int bh  = blockIdx.y;
    const int b   = bh >> 4;
    const int h   = bh & 15;
    const int m0  = blockIdx.x * 128;

    float* Eb = attn + ((size_t)bh * NS + m0) * NS;
    const __nv_bfloat16* Vb = g_Vh + ((size_t)b * NS) * ND + h * NDH;

    if (tid < 128) sInv[tid] = g_inv[(size_t)bh * NS + m0 + tid];

    // pre-loop group: E chunk 0 only (V[0] comes with iteration 0's group)
#pragma unroll
    for (int i = 0; i < 4; i++) {
        int idx = tid + i * 512;
        int er = idx >> 4, ec = (idx & 15) << 2;
        cpa16(&sEraw[er * 68 + ec], &Eb[(size_t)er * NS + ec]);
    }
    cpa_commit();

    const int wv = w - 8;
    const int wm = wv >> 1, wn = wv & 1;    // MMA warps: 4(m) x 2(n), 32x32
    const int band = w * 16;                // epi warps (w<8): 16-row band

    wmma::fragment<wmma::accumulator, 16, 16, 16, float> acc[2][2];
    if (w >= 8) {
#pragma unroll
        for (int i = 0; i < 2; i++)
#pragma unroll
            for (int j = 0; j < 2; j++) wmma::fill_fragment(acc[i][j], 0.0f);
    }

    for (int kc = 0; kc <= 32; kc++) {
        __syncthreads();   // A: prior compute done -> buffer reuse safe
        if (kc < 32) {
            // group kc: E[kc+1] (if it exists) + V[kc]
            if (kc + 1 < 32) {
                float* dE = sEraw + ((kc + 1) & 1) * (128 * 68);
#pragma unroll
                for (int i = 0; i < 4; i++) {
                    int idx = tid + i * 512;
                    int er = idx >> 4, ec = (idx & 15) << 2;
                    cpa16(&dE[er * 68 + ec],
                          &Eb[(size_t)er * NS + (size_t)(kc + 1) * 64 + ec]);
                }
            }
            {
                __nv_bfloat16* dV = sVh + (kc & 1) * (64 * 72);
                int vr = tid >> 3, vc = (tid & 7) << 3;
                cpa16(&dV[vr * 72 + vc], &Vb[(size_t)(kc * 64 + vr) * ND + vc]);
            }
            cpa_commit();
            cpa_wait<1>();   // group kc-1 (E[kc], V[kc-1]) complete
        } else {
            cpa_wait<0>();   // everything (incl. V[31]) complete
        }
        __syncthreads();   // B: E[kc], V[kc-1], sPb[(kc-1)&1] visible

        if (w < 8) {
            if (kc < 32) {
                const float* cE = sEraw + (kc & 1) * (128 * 68);
                __nv_bfloat16* dP = sPb + (kc & 1) * (128 * 72);
                const size_t gk = (size_t)kc * 64;
#pragma unroll
                for (int i = 0; i < 8; i++) {
                    int idx = i * 32 + l;
                    int r = band + (idx >> 4);
                    int cc = (idx & 15) << 2;
                    float4 v = *(const float4*)&cE[r * 68 + cc];
                    float iv = sInv[r];
                    v.x *= iv; v.y *= iv; v.z *= iv; v.w *= iv;
                    *(float4*)&Eb[(size_t)r * NS + gk + cc] = v;
                    *(uint32_t*)&dP[r * 72 + cc]     = pack_bf2(v.x, v.y);
                    *(uint32_t*)&dP[r * 72 + cc + 2] = pack_bf2(v.z, v.w);
                }
            }
        } else if (kc >= 1) {
            const int kp = kc - 1;
            const __nv_bfloat16* cP = sPb + (kp & 1) * (128 * 72);
            const __nv_bfloat16* cV = sVh + (kp & 1) * (64 * 72);
#pragma unroll
            for (int kk = 0; kk < 4; kk++) {
                wmma::fragment<wmma::matrix_a, 16, 16, 16, __nv_bfloat16, wmma::row_major> af[2];
                wmma::fragment<wmma::matrix_b, 16, 16, 16, __nv_bfloat16, wmma::row_major> bf[2];
#pragma unroll
                for (int i = 0; i < 2; i++)
                    wmma::load_matrix_sync(af[i], &cP[(wm * 32 + i * 16) * 72 + kk * 16], 72);
#pragma unroll
                for (int j = 0; j < 2; j++)
                    wmma::load_matrix_sync(bf[j], &cV[(kk * 16) * 72 + wn * 32 + j * 16], 72);
#pragma unroll
                for (int i = 0; i < 2; i++)
#pragma unroll
                    for (int j = 0; j < 2; j++)
                        wmma::mma_sync(acc[i][j], af[i], bf[j], acc[i][j]);
            }
        }
    }

    __syncthreads();
    // epilogue: MMA warps stage f32 accs in sEraw (per-warp region), emit bf16
    if (w >= 8) {
        float* stg = sEraw + wv * (32 * 36);
#pragma unroll
        for (int i = 0; i < 2; i++)
#pragma unroll
            for (int j = 0; j < 2; j++)
                wmma::store_matrix_sync(&stg[(i * 16) * 36 + j * 16], acc[i][j], 36,
                                        wmma::mem_row_major);
        __syncwarp();
        const float* row = stg + l * 36;
        uint32_t pk[16];
#pragma unroll
        for (int j = 0; j < 16; j++) pk[j] = pack_bf2(row[2 * j], row[2 * j + 1]);
        __nv_bfloat16* gp = g_ctxh + (size_t)(b * NS + m0 + wm * 32 + l) * ND + h * NDH + wn * 32;
#pragma unroll
        for (int j = 0; j < 4; j++)
            *(uint4*)(gp + j * 8) = make_uint4(pk[4 * j], pk[4 * j + 1], pk[4 * j + 2], pk[4 * j + 3]);
    }
}

// ---------------------------------------------------------------------------
// Residual + LayerNorm
// ---------------------------------------------------------------------------
__global__ __launch_bounds__(256) void ln_kernel(const float* __restrict__ resid,
                                                 float* __restrict__ out) {
    const int row = blockIdx.x;
    const int tid = threadIdx.x;

    float4 f  = *(const float4*)&g_fc[(size_t)row * ND + tid * 4];
    float4 rr = *(const float4*)&resid[(size_t)row * ND + tid * 4];
    float4 y;
    y.x = f.x + rr.x; y.y = f.y + rr.y; y.z = f.z + rr.z; y.w = f.w + rr.w;

    float s = y.x + y.y + y.z + y.w;
    float q = y.x * y.x + y.y * y.y + y.z * y.z + y.w * y.w;
#pragma unroll
    for (int off = 16; off > 0; off >>= 1) {
        s += __shfl_down_sync(0xffffffffu, s, off);
        q += __shfl_down_sync(0xffffffffu, q, off);
    }
    __shared__ float ss[8], sq[8];
    __shared__ float mu_s, rs_s;
    if ((tid & 31) == 0) { ss[tid >> 5] = s; sq[tid >> 5] = q; }
    __syncthreads();
    if (tid == 0) {
        float S = 0.0f, Q = 0.0f;
#pragma unroll
        for (int i = 0; i < 8; i++) { S += ss[i]; Q += sq[i]; }
        float mu  = S * (1.0f / ND);
        float var = Q * (1.0f / ND) - mu * mu;
        mu_s = mu;
        rs_s = rsqrtf(var + LN_EPS);
    }
    __syncthreads();
    const float mu = mu_s, rs = rs_s;
    float4 o;
    o.x = (y.x - mu) * rs; o.y = (y.y - mu) * rs;
    o.z = (y.z - mu) * rs; o.w = (y.w - mu) * rs;
    *(float4*)&out[(size_t)row * ND + tid * 4] = o;
}

// ---------------------------------------------------------------------------
extern "C" void kernel_launch(void* const* d_in, const int* in_sizes, int n_in,
                              void* d_out, int out_size) {
    const float* inQ = (const float*)d_in[0];
    const float* inK = (const float*)d_in[1];
    const float* inV = (const float*)d_in[2];
    const unsigned char* mask = (const unsigned char*)d_in[3];
    const float* WQ  = (const float*)d_in[4];
    const float* WK  = (const float*)d_in[5];
    const float* WV  = (const float*)d_in[6];
    const float* Wfc = (const float*)d_in[7];

    float* out  = (float*)d_out;
    float* attn = out + OUT_ELEMS;

    void *pQ, *pK, *pV, *pFc, *pVh, *pWfch, *pCtxh;
    cudaGetSymbolAddress(&pQ, g_Q);
    cudaGetSymbolAddress(&pK, g_K);
    cudaGetSymbolAddress(&pV, g_V);
    cudaGetSymbolAddress(&pFc, g_fc);
    cudaGetSymbolAddress(&pVh, g_Vh);
    cudaGetSymbolAddress(&pWfch, g_Wfch);
    cudaGetSymbolAddress(&pCtxh, g_ctxh);

    cudaFuncSetAttribute(escore_kernel, cudaFuncAttributeMaxDynamicSharedMemorySize, ESC_SMEM);
    cudaFuncSetAttribute(ctxnorm_kernel, cudaFuncAttributeMaxDynamicSharedMemorySize, CTX_SMEM);

    qkv_gemm<<<dim3(8, 32, 3), 256>>>(inQ, WQ, inK, WK, inV, WV,
                                      (float*)pQ, (float*)pK, (float*)pV);

    cvt_kernel<<<(TOK * ND / 4 + 255) / 256, 256>>>((const float*)pV, (__nv_bfloat16*)pVh, TOK * ND);
    cvt_kernel<<<(ND * ND / 4 + 255) / 256, 256>>>(Wfc, (__nv_bfloat16*)pWfch, ND * ND);

    escore_kernel<<<dim3(16, 32), 512, ESC_SMEM>>>(mask, attn);

    ctxnorm_kernel<<<dim3(16, 32), 512, CTX_SMEM>>>(attn);

    fc_gemm_bf16<<<dim3(8, 32), 256>>>((const __nv_bfloat16*)pCtxh, (const __nv_bfloat16*)pWfch,
                                       (float*)pFc);

    ln_kernel<<<TOK, 256>>>(inQ, out);
}

// round 10
// speedup vs baseline: 1.9796x; 1.1345x over previous
#include <cuda_runtime.h>
#include <cuda_bf16.h>
#include <mma.h>
#include <cstdint>
#include <cstddef>

using namespace nvcuda;

// Problem shape (fixed): B=2, S=2048, D=1024, H=16, Dh=64
#define NB 2
#define NS 2048
#define ND 1024
#define NH 16
#define NDH 64
#define TOK (NB*NS)
#define OUT_ELEMS (4194304)
#define SCALE 0.125f
#define LN_EPS 1e-5f

// ---- scratch (__device__ globals; no allocation allowed) ----
__device__ float g_Q[TOK*ND];
__device__ float g_K[TOK*ND];
__device__ float g_V[TOK*ND];
__device__ float g_fc[TOK*ND];
__device__ float g_inv[32 * NS];               // 1/rowsum per [bh][row]
__device__ __nv_bfloat16 g_Vh[TOK*ND];         // bf16 copy of V
__device__ __nv_bfloat16 g_Wfch[ND*ND];        // bf16 copy of W_fc
__device__ __nv_bfloat16 g_ctxh[TOK*ND];       // bf16 context

// ---------------------------------------------------------------------------
template <typename Frag>
__device__ __forceinline__ void to_tf32(Frag& f) {
#pragma unroll
    for (int i = 0; i < f.num_elements; i++) f.x[i] = wmma::__float_to_tf32(f.x[i]);
}

__device__ __forceinline__ void cpa16(void* s, const void* g) {
    uint32_t sa = (uint32_t)__cvta_generic_to_shared(s);
    asm volatile("cp.async.ca.shared.global [%0], [%1], 16;" :: "r"(sa), "l"(g));
}
__device__ __forceinline__ void cpa_commit() {
    asm volatile("cp.async.commit_group;" ::: "memory");
}
template <int N>
__device__ __forceinline__ void cpa_wait() {
    asm volatile("cp.async.wait_group %0;" :: "n"(N) : "memory");
}

__device__ __forceinline__ uint32_t pack_bf2(float a, float b) {
    __nv_bfloat162 t = __float22bfloat162_rn(make_float2(a, b));
    return *(uint32_t*)&t;
}

// ---------------------------------------------------------------------------
// f32 -> bf16 convert kernel
// ---------------------------------------------------------------------------
__global__ __launch_bounds__(256) void cvt_kernel(const float* __restrict__ s,
                                                  __nv_bfloat16* __restrict__ d, int n) {
    int i = (blockIdx.x * 256 + threadIdx.x) * 4;
    if (i < n) {
        float4 v = *(const float4*)&s[i];
        uint32_t p0 = pack_bf2(v.x, v.y);
        uint32_t p1 = pack_bf2(v.z, v.w);
        *(uint32_t*)&d[i]     = p0;
        *(uint32_t*)&d[i + 2] = p1;
    }
}

// ---------------------------------------------------------------------------
// tf32 GEMM body, BK=32, 2-stage cp.async. C = A[.,1024] @ B[1024,1024].
// ---------------------------------------------------------------------------
__device__ __forceinline__ void gemm_body(const float* __restrict__ A,
                                          const float* __restrict__ Bw,
                                          float* __restrict__ C) {
    __shared__ float sA[2][128][36];
    __shared__ float sB[2][32][132];

    const int tid = threadIdx.x;
    const int w   = tid >> 5;
    const int wm  = w >> 2;
    const int wn  = w & 3;
    const int m0  = blockIdx.y * 128;
    const int n0  = blockIdx.x * 128;

#define LOADT(st, k0)                                                                  \
    {                                                                                  \
        _Pragma("unroll")                                                              \
        for (int i = 0; i < 4; i++) {                                                  \
            int idx = tid + i * 256;                                                   \
            int ra = idx >> 3, ca = (idx & 7) << 2;                                    \
            cpa16(&sA[st][ra][ca], &A[(size_t)(m0 + ra) * ND + (k0) + ca]);            \
            int rb = idx >> 5, cb = (idx & 31) << 2;                                   \
            cpa16(&sB[st][rb][cb], &Bw[(size_t)((k0) + rb) * ND + n0 + cb]);           \
        }                                                                              \
        cpa_commit();                                                                  \
    }

    wmma::fragment<wmma::accumulator, 16, 16, 8, float> acc[4][2];
#pragma unroll
    for (int i = 0; i < 4; i++)
#pragma unroll
        for (int j = 0; j < 2; j++) wmma::fill_fragment(acc[i][j], 0.0f);

    LOADT(0, 0);

    for (int kt = 0; kt < 32; kt++) {
        if (kt < 31) {
            LOADT((kt + 1) & 1, (kt + 1) * 32);
            cpa_wait<1>();
        } else {
            cpa_wait<0>();
        }
        __syncthreads();
        const int st = kt & 1;
#pragma unroll
        for (int ks = 0; ks < 32; ks += 8) {
            wmma::fragment<wmma::matrix_a, 16, 16, 8, wmma::precision::tf32, wmma::row_major> af[4];
            wmma::fragment<wmma::matrix_b, 16, 16, 8, wmma::precision::tf32, wmma::row_major> bf[2];
#pragma unroll
            for (int i = 0; i < 4; i++) {
                wmma::load_matrix_sync(af[i], &sA[st][wm * 64 + i * 16][ks], 36);
                to_tf32(af[i]);
            }
#pragma unroll
            for (int j = 0; j < 2; j++) {
                wmma::load_matrix_sync(bf[j], &sB[st][ks][wn * 32 + j * 16], 132);
                to_tf32(bf[j]);
            }
#pragma unroll
            for (int i = 0; i < 4; i++)
#pragma unroll
                for (int j = 0; j < 2; j++)
                    wmma::mma_sync(acc[i][j], af[i], bf[j], acc[i][j]);
        }
        __syncthreads();
    }
#undef LOADT

#pragma unroll
    for (int i = 0; i < 4; i++)
#pragma unroll
        for (int j = 0; j < 2; j++)
            wmma::store_matrix_sync(&C[(size_t)(m0 + wm * 64 + i * 16) * ND + n0 + wn * 32 + j * 16],
                                    acc[i][j], ND, wmma::mem_row_major);
}

__global__ __launch_bounds__(256, 2) void qkv_gemm(const float* __restrict__ iQ, const float* __restrict__ WQ,
                                                   const float* __restrict__ iK, const float* __restrict__ WK,
                                                   const float* __restrict__ iV, const float* __restrict__ WV,
                                                   float* __restrict__ oQ, float* __restrict__ oK,
                                                   float* __restrict__ oV) {
    const int z = blockIdx.z;
    const float* A  = (z == 0) ? iQ : (z == 1) ? iK : iV;
    const float* Bw = (z == 0) ? WQ : (z == 1) ? WK : WV;
    float*       C  = (z == 0) ? oQ : (z == 1) ? oK : oV;
    gemm_body(A, Bw, C);
}

// ---------------------------------------------------------------------------
// bf16 fc GEMM: C[4096,1024] f32 = A bf16 @ B bf16. BK=32, 2-stage.
// ---------------------------------------------------------------------------
__global__ __launch_bounds__(256, 2) void fc_gemm_bf16(const __nv_bfloat16* __restrict__ A,
                                                       const __nv_bfloat16* __restrict__ Bw,
                                                       float* __restrict__ C) {
    __shared__ __nv_bfloat16 sA[2][128][40];
    __shared__ __nv_bfloat16 sB[2][32][136];

    const int tid = threadIdx.x;
    const int w   = tid >> 5;
    const int wm  = w >> 2;
    const int wn  = w & 3;
    const int m0  = blockIdx.y * 128;
    const int n0  = blockIdx.x * 128;

#define LOADH(st, k0)                                                                  \
    {                                                                                  \
        _Pragma("unroll")                                                              \
        for (int i = 0; i < 2; i++) {                                                  \
            int idx = tid + i * 256;                                                   \
            int ra = idx >> 2, ca = (idx & 3) << 3;                                    \
            cpa16(&sA[st][ra][ca], &A[(size_t)(m0 + ra) * ND + (k0) + ca]);            \
            int rb = idx >> 4, cb = (idx & 15) << 3;                                   \
            cpa16(&sB[st][rb][cb], &Bw[(size_t)((k0) + rb) * ND + n0 + cb]);           \
        }                                                                              \
        cpa_commit();                                                                  \
    }

    wmma::fragment<wmma::accumulator, 16, 16, 16, float> acc[4][2];
#pragma unroll
    for (int i = 0; i < 4; i++)
#pragma unroll
        for (int j = 0; j < 2; j++) wmma::fill_fragment(acc[i][j], 0.0f);

    LOADH(0, 0);

    for (int kt = 0; kt < 32; kt++) {
        if (kt < 31) {
            LOADH((kt + 1) & 1, (kt + 1) * 32);
            cpa_wait<1>();
        } else {
            cpa_wait<0>();
        }
        __syncthreads();
        const int st = kt & 1;
#pragma unroll
        for (int ks = 0; ks < 32; ks += 16) {
            wmma::fragment<wmma::matrix_a, 16, 16, 16, __nv_bfloat16, wmma::row_major> af[4];
            wmma::fragment<wmma::matrix_b, 16, 16, 16, __nv_bfloat16, wmma::row_major> bf[2];
#pragma unroll
            for (int i = 0; i < 4; i++)
                wmma::load_matrix_sync(af[i], &sA[st][wm * 64 + i * 16][ks], 40);
#pragma unroll
            for (int j = 0; j < 2; j++)
                wmma::load_matrix_sync(bf[j], &sB[st][ks][wn * 32 + j * 16], 136);
#pragma unroll
            for (int i = 0; i < 4; i++)
#pragma unroll
                for (int j = 0; j < 2; j++)
                    wmma::mma_sync(acc[i][j], af[i], bf[j], acc[i][j]);
        }
        __syncthreads();
    }
#undef LOADH

#pragma unroll
    for (int i = 0; i < 4; i++)
#pragma unroll
        for (int j = 0; j < 2; j++)
            wmma::store_matrix_sync(&C[(size_t)(m0 + wm * 64 + i * 16) * ND + n0 + wn * 32 + j * 16],
                                    acc[i][j], ND, wmma::mem_row_major);
}

// ---------------------------------------------------------------------------
// escore v4.1 — Q-IN-REGISTERS + 2 BLOCKS/SM (prefetch loop-bound FIXED:
// 4x256 cp.async ops now cover all 64 K rows, not 32).
// One block = 64-row q-stripe of one (b,h). K streamed in 32 tiles of 64
// keys, double-buffered cp.async. 256 threads = 8 warps, warp grid 2(m)x4(n),
// warp tile 32x16. Q fragments loaded+converted to tf32 ONCE (16 frags,
// persistent in registers). grid = (32, 32), 256 threads.
// ---------------------------------------------------------------------------
#define ESC_SMEM ((4 * 64 * 68 + 64) * 4)   // 69888 B

__global__ __launch_bounds__(256, 2) void escore_kernel(const unsigned char* __restrict__ mask,
                                                        float* __restrict__ attnOut) {
    extern __shared__ float sm[];
    float* sQ   = sm;                        // 64 x 68
    float* sK   = sQ + 64 * 68;              // 2 x (64 x 68)
    float* sS   = sK + 2 * 64 * 68;          // 64 x 68
    float* sSum = sS + 64 * 68;              // 64

    const int tid = threadIdx.x;
    const int w   = tid >> 5;
    const int l   = tid & 31;
    const int bh  = blockIdx.y;
    const int b   = bh >> 4;
    const int h   = bh & 15;
    const int q0  = blockIdx.x * 64;

    const float* Qb = g_Q + ((size_t)(b * NS + q0)) * ND + h * NDH;
    const float* Kb = g_K + ((size_t)b * NS) * ND + h * NDH;

    // initial group: Q stripe (1024 f4) + K tile 0 (1024 f4)
#pragma unroll
    for (int i = 0; i < 4; i++) {
        int idx = tid + i * 256;
        int r = idx >> 4, c = (idx & 15) << 2;
        cpa16(&sQ[r * 68 + c], &Qb[(size_t)r * ND + c]);
        cpa16(&sK[r * 68 + c], &Kb[(size_t)r * ND + c]);
    }
    cpa_commit();
    if (tid < 64) sSum[tid] = 0.0f;

    const int wm = w >> 2;          // 0..1 : 32-row band
    const int wn = w & 3;           // 0..3 : 16-col band

    // persistent Q fragments: af[i][kk], rows wm*32+i*16, k-slice kk*8
    wmma::fragment<wmma::matrix_a, 16, 16, 8, wmma::precision::tf32, wmma::row_major> af[2][8];

    for (int ct = 0; ct < 32; ct++) {
        if (ct < 31) {
            float* dst = sK + ((ct + 1) & 1) * (64 * 68);
            const float* src = Kb + (size_t)(ct + 1) * 64 * ND;
#pragma unroll
            for (int i = 0; i < 4; i++) {          // FIX: 4 iters (was 2) -> rows 0..63
                int idx = tid + i * 256;
                int r = idx >> 4, c = (idx & 15) << 2;
                cpa16(&dst[r * 68 + c], &src[(size_t)r * ND + c]);
            }
            cpa_commit();
            cpa_wait<1>();
        } else {
            cpa_wait<0>();
        }
        __syncthreads();   // A: K[ct] (and Q at ct=0) visible; prior epilogue done

        if (ct == 0) {
            // one-time Q fragment load + tf32 conversion
#pragma unroll
            for (int i = 0; i < 2; i++)
#pragma unroll
                for (int kk = 0; kk < 8; kk++) {
                    wmma::load_matrix_sync(af[i][kk], &sQ[(wm * 32 + i * 16) * 68 + kk * 8], 68);
                    to_tf32(af[i][kk]);
                }
        }

        const float* sKt = sK + (ct & 1) * (64 * 68);
        wmma::fragment<wmma::accumulator, 16, 16, 8, float> acc[2];
        wmma::fill_fragment(acc[0], 0.0f);
        wmma::fill_fragment(acc[1], 0.0f);

#pragma unroll
        for (int kk = 0; kk < 8; kk++) {
            wmma::fragment<wmma::matrix_b, 16, 16, 8, wmma::precision::tf32, wmma::col_major> bf;
            wmma::load_matrix_sync(bf, &sKt[(wn * 16) * 68 + kk * 8], 68);
            to_tf32(bf);
            wmma::mma_sync(acc[0], af[0][kk], bf, acc[0]);
            wmma::mma_sync(acc[1], af[1][kk], bf, acc[1]);
        }
#pragma unroll
        for (int i = 0; i < 2; i++)
            wmma::store_matrix_sync(&sS[(wm * 32 + i * 16) * 68 + wn * 16], acc[i], 68,
                                    wmma::mem_row_major);
        __syncthreads();   // B: sS complete; also guards K buffer reuse next iter

        // epilogue: warp w owns rows {8w .. 8w+7}; 64 cols each
        const int c0 = ct * 64;
#pragma unroll
        for (int pass = 0; pass < 4; pass++) {
            const int r  = w * 8 + pass * 2 + (l >> 4);
            const int cc = (l & 15) << 2;
            float4 v = *(const float4*)&sS[r * 68 + cc];
            const unsigned char* mrow = mask + ((size_t)(b * NS + q0 + r)) * NS + c0;
            uchar4 mk = *(const uchar4*)&mrow[cc];
            v.x = mk.x ? 0.0f : __expf(v.x * SCALE);
            v.y = mk.y ? 0.0f : __expf(v.y * SCALE);
            v.z = mk.z ? 0.0f : __expf(v.z * SCALE);
            v.w = mk.w ? 0.0f : __expf(v.w * SCALE);
            float* erow = attnOut + ((size_t)(bh * NS + q0 + r)) * NS + c0;
            *(float4*)&erow[cc] = v;
            float s = v.x + v.y + v.z + v.w;
#pragma unroll
            for (int off = 8; off > 0; off >>= 1)
                s += __shfl_xor_sync(0xffffffffu, s, off);
            if ((l & 15) == 0) sSum[r] += s;   // one (warp,half) per row: no race
        }
    }

    __syncthreads();
    if (tid < 64) g_inv[(size_t)bh * NS + q0 + tid] = 1.0f / sSum[tid];
}

// ---------------------------------------------------------------------------
// ctxnorm v3.1 — WARP SPECIALIZED, V-prefetch lagged (race-free; see r8).
// ---------------------------------------------------------------------------
#define CTX_ER   (2 * 128 * 68 * 4)     // 69632
#define CTX_VH   (2 * 64 * 72 * 2)      // 18432
#define CTX_PB   (2 * 128 * 72 * 2)     // 73728
#define CTX_SMEM (CTX_ER + CTX_VH + CTX_PB + 512)   // 162304

__global__ __launch_bounds__(512) void ctxnorm_kernel(float* __restrict__ attn) {
    extern __shared__ char smc[];
    float*         sEraw = (float*)smc;                               // 2 x 128 x 68
    __nv_bfloat16* sVh   = (__nv_bfloat16*)(smc + CTX_ER);            // 2 x 64 x 72
    __nv_bfloat16* sPb   = (__nv_bfloat16*)(smc + CTX_ER + CTX_VH);   // 2 x 128 x 72
    float*         sInv  = (float*)(smc + CTX_ER + CTX_VH + CTX_PB);  // 128

    const int tid = threadIdx.x;
    const int w   = tid >> 5;
    const int l   = tid & 31;
    const int bh  = blockIdx.y;
    const int b   = bh >> 4;
    const int h   = bh & 15;
    const int m0  = blockIdx.x * 128;

    float* Eb = attn + ((size_t)bh * NS + m0) * NS;
    const __nv_bfloat16* Vb = g_Vh + ((size_t)b * NS) * ND + h * NDH;

    if (tid < 128) sInv[tid] = g_inv[(size_t)bh * NS + m0 + tid];

    // pre-loop group: E chunk 0 only (V[0] comes with iteration 0's group)
#pragma unroll
    for (int i = 0; i < 4; i++) {
        int idx = tid + i * 512;
        int er = idx >> 4, ec = (idx & 15) << 2;
        cpa16(&sEraw[er * 68 + ec], &Eb[(size_t)er * NS + ec]);
    }
    cpa_commit();

    const int wv = w - 8;
    const int wm = wv >> 1, wn = wv & 1;    // MMA warps: 4(m) x 2(n), 32x32
    const int band = w * 16;                // epi warps (w<8): 16-row band

    wmma::fragment<wmma::accumulator, 16, 16, 16, float> acc[2][2];
    if (w >= 8) {
#pragma unroll
        for (int i = 0; i < 2; i++)
#pragma unroll
            for (int j = 0; j < 2; j++) wmma::fill_fragment(acc[i][j], 0.0f);
    }

    for (int kc = 0; kc <= 32; kc++) {
        __syncthreads();   // A: prior compute done -> buffer reuse safe
        if (kc < 32) {
            // group kc: E[kc+1] (if it exists) + V[kc]
            if (kc + 1 < 32) {
                float* dE = sEraw + ((kc + 1) & 1) * (128 * 68);
#pragma unroll
                for (int i = 0; i < 4; i++) {
                    int idx = tid + i * 512;
                    int er = idx >> 4, ec = (idx & 15) << 2;
                    cpa16(&dE[er * 68 + ec],
                          &Eb[(size_t)er * NS + (size_t)(kc + 1) * 64 + ec]);
                }
            }
            {
                __nv_bfloat16* dV = sVh + (kc & 1) * (64 * 72);
                int vr = tid >> 3, vc = (tid & 7) << 3;
                cpa16(&dV[vr * 72 + vc], &Vb[(size_t)(kc * 64 + vr) * ND + vc]);
            }
            cpa_commit();
            cpa_wait<1>();   // group kc-1 (E[kc], V[kc-1]) complete
        } else {
            cpa_wait<0>();   // everything (incl. V[31]) complete
        }
        __syncthreads();   // B: E[kc], V[kc-1], sPb[(kc-1)&1] visible

        if (w < 8) {
            if (kc < 32) {
                const float* cE = sEraw + (kc & 1) * (128 * 68);
                __nv_bfloat16* dP = sPb + (kc & 1) * (128 * 72);
                const size_t gk = (size_t)kc * 64;
#pragma unroll
                for (int i = 0; i < 8; i++) {
                    int idx = i * 32 + l;
                    int r = band + (idx >> 4);
                    int cc = (idx & 15) << 2;
                    float4 v = *(const float4*)&cE[r * 68 + cc];
                    float iv = sInv[r];
                    v.x *= iv; v.y *= iv; v.z *= iv; v.w *= iv;
                    *(float4*)&Eb[(size_t)r * NS + gk + cc] = v;
                    *(uint32_t*)&dP[r * 72 + cc]     = pack_bf2(v.x, v.y);
                    *(uint32_t*)&dP[r * 72 + cc + 2] = pack_bf2(v.z, v.w);
                }
            }
        } else if (kc >= 1) {
            const int kp = kc - 1;
            const __nv_bfloat16* cP = sPb + (kp & 1) * (128 * 72);
            const __nv_bfloat16* cV = sVh + (kp & 1) * (64 * 72);
#pragma unroll
            for (int kk = 0; kk < 4; kk++) {
                wmma::fragment<wmma::matrix_a, 16, 16, 16, __nv_bfloat16, wmma::row_major> af[2];
                wmma::fragment<wmma::matrix_b, 16, 16, 16, __nv_bfloat16, wmma::row_major> bf[2];
#pragma unroll
                for (int i = 0; i < 2; i++)
                    wmma::load_matrix_sync(af[i], &cP[(wm * 32 + i * 16) * 72 + kk * 16], 72);
#pragma unroll
                for (int j = 0; j < 2; j++)
                    wmma::load_matrix_sync(bf[j], &cV[(kk * 16) * 72 + wn * 32 + j * 16], 72);
#pragma unroll
                for (int i = 0; i < 2; i++)
#pragma unroll
                    for (int j = 0; j < 2; j++)
                        wmma::mma_sync(acc[i][j], af[i], bf[j], acc[i][j]);
            }
        }
    }

    __syncthreads();
    // epilogue: MMA warps stage f32 accs in sEraw (per-warp region), emit bf16
    if (w >= 8) {
        float* stg = sEraw + wv * (32 * 36);
#pragma unroll
        for (int i = 0; i < 2; i++)
#pragma unroll
            for (int j = 0; j < 2; j++)
                wmma::store_matrix_sync(&stg[(i * 16) * 36 + j * 16], acc[i][j], 36,
                                        wmma::mem_row_major);
        __syncwarp();
        const float* row = stg + l * 36;
        uint32_t pk[16];
#pragma unroll
        for (int j = 0; j < 16; j++) pk[j] = pack_bf2(row[2 * j], row[2 * j + 1]);
        __nv_bfloat16* gp = g_ctxh + (size_t)(b * NS + m0 + wm * 32 + l) * ND + h * NDH + wn * 32;
#pragma unroll
        for (int j = 0; j < 4; j++)
            *(uint4*)(gp + j * 8) = make_uint4(pk[4 * j], pk[4 * j + 1], pk[4 * j + 2], pk[4 * j + 3]);
    }
}

// ---------------------------------------------------------------------------
// Residual + LayerNorm
// ---------------------------------------------------------------------------
__global__ __launch_bounds__(256) void ln_kernel(const float* __restrict__ resid,
                                                 float* __restrict__ out) {
    const int row = blockIdx.x;
    const int tid = threadIdx.x;

    float4 f  = *(const float4*)&g_fc[(size_t)row * ND + tid * 4];
    float4 rr = *(const float4*)&resid[(size_t)row * ND + tid * 4];
    float4 y;
    y.x = f.x + rr.x; y.y = f.y + rr.y; y.z = f.z + rr.z; y.w = f.w + rr.w;

    float s = y.x + y.y + y.z + y.w;
    float q = y.x * y.x + y.y * y.y + y.z * y.z + y.w * y.w;
#pragma unroll
    for (int off = 16; off > 0; off >>= 1) {
        s += __shfl_down_sync(0xffffffffu, s, off);
        q += __shfl_down_sync(0xffffffffu, q, off);
    }
    __shared__ float ss[8], sq[8];
    __shared__ float mu_s, rs_s;
    if ((tid & 31) == 0) { ss[tid >> 5] = s; sq[tid >> 5] = q; }
    __syncthreads();
    if (tid == 0) {
        float S = 0.0f, Q = 0.0f;
#pragma unroll
        for (int i = 0; i < 8; i++) { S += ss[i]; Q += sq[i]; }
        float mu  = S * (1.0f / ND);
        float var = Q * (1.0f / ND) - mu * mu;
        mu_s = mu;
        rs_s = rsqrtf(var + LN_EPS);
    }
    __syncthreads();
    const float mu = mu_s, rs = rs_s;
    float4 o;
    o.x = (y.x - mu) * rs; o.y = (y.y - mu) * rs;
    o.z = (y.z - mu) * rs; o.w = (y.w - mu) * rs;
    *(float4*)&out[(size_t)row * ND + tid * 4] = o;
}

// ---------------------------------------------------------------------------
extern "C" void kernel_launch(void* const* d_in, const int* in_sizes, int n_in,
                              void* d_out, int out_size) {
    const float* inQ = (const float*)d_in[0];
    const float* inK = (const float*)d_in[1];
    const float* inV = (const float*)d_in[2];
    const unsigned char* mask = (const unsigned char*)d_in[3];
    const float* WQ  = (const float*)d_in[4];
    const float* WK  = (const float*)d_in[5];
    const float* WV  = (const float*)d_in[6];
    const float* Wfc = (const float*)d_in[7];

    float* out  = (float*)d_out;
    float* attn = out + OUT_ELEMS;

    void *pQ, *pK, *pV, *pFc, *pVh, *pWfch, *pCtxh;
    cudaGetSymbolAddress(&pQ, g_Q);
    cudaGetSymbolAddress(&pK, g_K);
    cudaGetSymbolAddress(&pV, g_V);
    cudaGetSymbolAddress(&pFc, g_fc);
    cudaGetSymbolAddress(&pVh, g_Vh);
    cudaGetSymbolAddress(&pWfch, g_Wfch);
    cudaGetSymbolAddress(&pCtxh, g_ctxh);

    cudaFuncSetAttribute(escore_kernel, cudaFuncAttributeMaxDynamicSharedMemorySize, ESC_SMEM);
    cudaFuncSetAttribute(ctxnorm_kernel, cudaFuncAttributeMaxDynamicSharedMemorySize, CTX_SMEM);

    qkv_gemm<<<dim3(8, 32, 3), 256>>>(inQ, WQ, inK, WK, inV, WV,
                                      (float*)pQ, (float*)pK, (float*)pV);

    cvt_kernel<<<(TOK * ND / 4 + 255) / 256, 256>>>((const float*)pV, (__nv_bfloat16*)pVh, TOK * ND);
    cvt_kernel<<<(ND * ND / 4 + 255) / 256, 256>>>(Wfc, (__nv_bfloat16*)pWfch, ND * ND);

    escore_kernel<<<dim3(32, 32), 256, ESC_SMEM>>>(mask, attn);

    ctxnorm_kernel<<<dim3(16, 32), 512, CTX_SMEM>>>(attn);

    fc_gemm_bf16<<<dim3(8, 32), 256>>>((const __nv_bfloat16*)pCtxh, (const __nv_bfloat16*)pWfch,
                                       (float*)pFc);

    ln_kernel<<<TOK, 256>>>(inQ, out);
}

// round 12
// speedup vs baseline: 2.2457x; 1.1344x over previous
#include <cuda_runtime.h>
#include <cuda_bf16.h>
#include <mma.h>
#include <cstdint>
#include <cstddef>

using namespace nvcuda;

// Problem shape (fixed): B=2, S=2048, D=1024, H=16, Dh=64
#define NB 2
#define NS 2048
#define ND 1024
#define NH 16
#define NDH 64
#define TOK (NB*NS)
#define OUT_ELEMS (4194304)
#define SCALE 0.125f
#define LN_EPS 1e-5f

// ---- scratch (__device__ globals; no allocation allowed) ----
__device__ float g_Q[TOK*ND];
__device__ float g_K[TOK*ND];
__device__ float g_V[TOK*ND];
__device__ float g_fc[TOK*ND];
__device__ float g_inv[32 * NS];               // 1/rowsum per [bh][row]
__device__ __nv_bfloat16 g_Vh[TOK*ND];         // bf16 copy of V
__device__ __nv_bfloat16 g_Wfch[ND*ND];        // bf16 copy of W_fc
__device__ __nv_bfloat16 g_ctxh[TOK*ND];       // bf16 context
__device__ __nv_bfloat16 g_inVh[TOK*ND];       // bf16 copy of input_V
__device__ __nv_bfloat16 g_WVh[ND*ND];         // bf16 copy of W_V

// ---------------------------------------------------------------------------
template <typename Frag>
__device__ __forceinline__ void to_tf32(Frag& f) {
#pragma unroll
    for (int i = 0; i < f.num_elements; i++) f.x[i] = wmma::__float_to_tf32(f.x[i]);
}

__device__ __forceinline__ void cpa16(void* s, const void* g) {
    uint32_t sa = (uint32_t)__cvta_generic_to_shared(s);
    asm volatile("cp.async.ca.shared.global [%0], [%1], 16;" :: "r"(sa), "l"(g));
}
__device__ __forceinline__ void cpa_commit() {
    asm volatile("cp.async.commit_group;" ::: "memory");
}
template <int N>
__device__ __forceinline__ void cpa_wait() {
    asm volatile("cp.async.wait_group %0;" :: "n"(N) : "memory");
}

__device__ __forceinline__ uint32_t pack_bf2(float a, float b) {
    __nv_bfloat162 t = __float22bfloat162_rn(make_float2(a, b));
    return *(uint32_t*)&t;
}

// ---------------------------------------------------------------------------
// f32 -> bf16 convert kernel
// ---------------------------------------------------------------------------
__global__ __launch_bounds__(256) void cvt_kernel(const float* __restrict__ s,
                                                  __nv_bfloat16* __restrict__ d, int n) {
    int i = (blockIdx.x * 256 + threadIdx.x) * 4;
    if (i < n) {
        float4 v = *(const float4*)&s[i];
        uint32_t p0 = pack_bf2(v.x, v.y);
        uint32_t p1 = pack_bf2(v.z, v.w);
        *(uint32_t*)&d[i]     = p0;
        *(uint32_t*)&d[i + 2] = p1;
    }
}

// ---------------------------------------------------------------------------
// tf32 GEMM body, BK=32, 2-stage cp.async. C = A[.,1024] @ B[1024,1024].
// ---------------------------------------------------------------------------
__device__ __forceinline__ void gemm_body(const float* __restrict__ A,
                                          const float* __restrict__ Bw,
                                          float* __restrict__ C) {
    __shared__ float sA[2][128][36];
    __shared__ float sB[2][32][132];

    const int tid = threadIdx.x;
    const int w   = tid >> 5;
    const int wm  = w >> 2;
    const int wn  = w & 3;
    const int m0  = blockIdx.y * 128;
    const int n0  = blockIdx.x * 128;

#define LOADT(st, k0)                                                                  \
    {                                                                                  \
        _Pragma("unroll")                                                              \
        for (int i = 0; i < 4; i++) {                                                  \
            int idx = tid + i * 256;                                                   \
            int ra = idx >> 3, ca = (idx & 7) << 2;                                    \
            cpa16(&sA[st][ra][ca], &A[(size_t)(m0 + ra) * ND + (k0) + ca]);            \
            int rb = idx >> 5, cb = (idx & 31) << 2;                                   \
            cpa16(&sB[st][rb][cb], &Bw[(size_t)((k0) + rb) * ND + n0 + cb]);           \
        }                                                                              \
        cpa_commit();                                                                  \
    }

    wmma::fragment<wmma::accumulator, 16, 16, 8, float> acc[4][2];
#pragma unroll
    for (int i = 0; i < 4; i++)
#pragma unroll
        for (int j = 0; j < 2; j++) wmma::fill_fragment(acc[i][j], 0.0f);

    LOADT(0, 0);

    for (int kt = 0; kt < 32; kt++) {
        if (kt < 31) {
            LOADT((kt + 1) & 1, (kt + 1) * 32);
            cpa_wait<1>();
        } else {
            cpa_wait<0>();
        }
        __syncthreads();
        const int st = kt & 1;
#pragma unroll
        for (int ks = 0; ks < 32; ks += 8) {
            wmma::fragment<wmma::matrix_a, 16, 16, 8, wmma::precision::tf32, wmma::row_major> af[4];
            wmma::fragment<wmma::matrix_b, 16, 16, 8, wmma::precision::tf32, wmma::row_major> bf[2];
#pragma unroll
            for (int i = 0; i < 4; i++) {
                wmma::load_matrix_sync(af[i], &sA[st][wm * 64 + i * 16][ks], 36);
                to_tf32(af[i]);
            }
#pragma unroll
            for (int j = 0; j < 2; j++) {
                wmma::load_matrix_sync(bf[j], &sB[st][ks][wn * 32 + j * 16], 132);
                to_tf32(bf[j]);
            }
#pragma unroll
            for (int i = 0; i < 4; i++)
#pragma unroll
                for (int j = 0; j < 2; j++)
                    wmma::mma_sync(acc[i][j], af[i], bf[j], acc[i][j]);
        }
        __syncthreads();
    }
#undef LOADT

#pragma unroll
    for (int i = 0; i < 4; i++)
#pragma unroll
        for (int j = 0; j < 2; j++)
            wmma::store_matrix_sync(&C[(size_t)(m0 + wm * 64 + i * 16) * ND + n0 + wn * 32 + j * 16],
                                    acc[i][j], ND, wmma::mem_row_major);
}

// Q and K projections only (z selects); V goes through the bf16 path.
__global__ __launch_bounds__(256, 2) void qk_gemm(const float* __restrict__ iQ, const float* __restrict__ WQ,
                                                  const float* __restrict__ iK, const float* __restrict__ WK,
                                                  float* __restrict__ oQ, float* __restrict__ oK) {
    const int z = blockIdx.z;
    gemm_body(z == 0 ? iQ : iK, z == 0 ? WQ : WK, z == 0 ? oQ : oK);
}

// ---------------------------------------------------------------------------
// bf16 GEMM: C[4096,1024] f32 = A bf16 @ B bf16. BK=32, 2-stage.
// Used for the V projection and the fc projection (both error-insensitive).
// ---------------------------------------------------------------------------
__global__ __launch_bounds__(256, 2) void gemm_bf16(const __nv_bfloat16* __restrict__ A,
                                                    const __nv_bfloat16* __restrict__ Bw,
                                                    float* __restrict__ C) {
    __shared__ __nv_bfloat16 sA[2][128][40];
    __shared__ __nv_bfloat16 sB[2][32][136];

    const int tid = threadIdx.x;
    const int w   = tid >> 5;
    const int wm  = w >> 2;
    const int wn  = w & 3;
    const int m0  = blockIdx.y * 128;
    const int n0  = blockIdx.x * 128;

#define LOADH(st, k0)                                                                  \
    {                                                                                  \
        _Pragma("unroll")                                                              \
        for (int i = 0; i < 2; i++) {                                                  \
            int idx = tid + i * 256;                                                   \
            int ra = idx >> 2, ca = (idx & 3) << 3;                                    \
            cpa16(&sA[st][ra][ca], &A[(size_t)(m0 + ra) * ND + (k0) + ca]);            \
            int rb = idx >> 4, cb = (idx & 15) << 3;                                   \
            cpa16(&sB[st][rb][cb], &Bw[(size_t)((k0) + rb) * ND + n0 + cb]);           \
        }                                                                              \
        cpa_commit();                                                                  \
    }

    wmma::fragment<wmma::accumulator, 16, 16, 16, float> acc[4][2];
#pragma unroll
    for (int i = 0; i < 4; i++)
#pragma unroll
        for (int j = 0; j < 2; j++) wmma::fill_fragment(acc[i][j], 0.0f);

    LOADH(0, 0);

    for (int kt = 0; kt < 32; kt++) {
        if (kt < 31) {
            LOADH((kt + 1) & 1, (kt + 1) * 32);
            cpa_wait<1>();
        } else {
            cpa_wait<0>();
        }
        __syncthreads();
        const int st = kt & 1;
#pragma unroll
        for (int ks = 0; ks < 32; ks += 16) {
            wmma::fragment<wmma::matrix_a, 16, 16, 16, __nv_bfloat16, wmma::row_major> af[4];
            wmma::fragment<wmma::matrix_b, 16, 16, 16, __nv_bfloat16, wmma::row_major> bf[2];
#pragma unroll
            for (int i = 0; i < 4; i++)
                wmma::load_matrix_sync(af[i], &sA[st][wm * 64 + i * 16][ks], 40);
#pragma unroll
            for (int j = 0; j < 2; j++)
                wmma::load_matrix_sync(bf[j], &sB[st][ks][wn * 32 + j * 16], 136);
#pragma unroll
            for (int i = 0; i < 4; i++)
#pragma unroll
                for (int j = 0; j < 2; j++)
                    wmma::mma_sync(acc[i][j], af[i], bf[j], acc[i][j]);
        }
        __syncthreads();
    }
#undef LOADH

#pragma unroll
    for (int i = 0; i < 4; i++)
#pragma unroll
        for (int j = 0; j < 2; j++)
            wmma::store_matrix_sync(&C[(size_t)(m0 + wm * 64 + i * 16) * ND + n0 + wn * 32 + j * 16],
                                    acc[i][j], ND, wmma::mem_row_major);
}

// ---------------------------------------------------------------------------
// escore v5 — v4.1 + MASK PREFETCHED TO SMEM (cp.async, TRIPLE-buffered).
// The mask tile for iteration ct is consumed by the epilogue AFTER sync B,
// while iteration ct+1's prefetch issues with no intervening barrier; with
// 3 buffers the writer at iter t targets buf[(t+1)%3] whose last readers
// (iter t-2... actually t-1's tile lives in buf[(t)%3]) finished at iter
// t-1 and are drained by iter t's two barriers. K stays double-buffered:
// its consumer (MMA) finishes before sync B of the same iteration, so the
// next iteration's write to the opposite-parity buffer is safe.
// grid = (32, 32), 256 threads, 2 blocks/SM.
// ---------------------------------------------------------------------------
#define ESC_FLOATS (4 * 64 * 68 + 64)                    // 17472 floats
#define ESC_SMEM   (ESC_FLOATS * 4 + 3 * 64 * 64)        // 69888 + 12288 = 82176 B

__global__ __launch_bounds__(256, 2) void escore_kernel(const unsigned char* __restrict__ mask,
                                                        float* __restrict__ attnOut) {
    extern __shared__ float sm[];
    float* sQ   = sm;                        // 64 x 68
    float* sK   = sQ + 64 * 68;              // 2 x (64 x 68)
    float* sS   = sK + 2 * 64 * 68;          // 64 x 68
    float* sSum = sS + 64 * 68;              // 64
    unsigned char* sMask = (unsigned char*)(sSum + 64);   // 3 x (64 x 64) bytes

    const int tid = threadIdx.x;
    const int w   = tid >> 5;
    const int l   = tid & 31;
    const int bh  = blockIdx.y;
    const int b   = bh >> 4;
    const int h   = bh & 15;
    const int q0  = blockIdx.x * 64;

    const float* Qb = g_Q + ((size_t)(b * NS + q0)) * ND + h * NDH;
    const float* Kb = g_K + ((size_t)b * NS) * ND + h * NDH;
    const unsigned char* Mb = mask + ((size_t)(b * NS + q0)) * NS;

    const int mrw = tid >> 2;               // mask row this thread copies
    const int mcc = (tid & 3) << 4;         // 16-byte column offset

    // initial group: Q stripe + K tile 0 + mask tile 0
#pragma unroll
    for (int i = 0; i < 4; i++) {
        int idx = tid + i * 256;
        int r = idx >> 4, c = (idx & 15) << 2;
        cpa16(&sQ[r * 68 + c], &Qb[(size_t)r * ND + c]);
        cpa16(&sK[r * 68 + c], &Kb[(size_t)r * ND + c]);
    }
    cpa16(&sMask[mrw * 64 + mcc], &Mb[(size_t)mrw * NS + mcc]);
    cpa_commit();
    if (tid < 64) sSum[tid] = 0.0f;

    const int wm = w >> 2;          // 0..1 : 32-row band
    const int wn = w & 3;           // 0..3 : 16-col band

    // persistent Q fragments
    wmma::fragment<wmma::matrix_a, 16, 16, 8, wmma::precision::tf32, wmma::row_major> af[2][8];

    int mbuf = 0;                   // sMask buffer holding tile ct

    for (int ct = 0; ct < 32; ct++) {
        const int mnext = (mbuf + 1 == 3) ? 0 : mbuf + 1;
        if (ct < 31) {
            float* dst = sK + ((ct + 1) & 1) * (64 * 68);
            const float* src = Kb + (size_t)(ct + 1) * 64 * ND;
#pragma unroll
            for (int i = 0; i < 4; i++) {
                int idx = tid + i * 256;
                int r = idx >> 4, c = (idx & 15) << 2;
                cpa16(&dst[r * 68 + c], &src[(size_t)r * ND + c]);
            }
            cpa16(&sMask[mnext * 4096 + mrw * 64 + mcc],
                  &Mb[(size_t)mrw * NS + (size_t)(ct + 1) * 64 + mcc]);
            cpa_commit();
            cpa_wait<1>();
        } else {
            cpa_wait<0>();
        }
        __syncthreads();   // A: K[ct], M[ct] (and Q at ct=0) visible

        if (ct == 0) {
#pragma unroll
            for (int i = 0; i < 2; i++)
#pragma unroll
                for (int kk = 0; kk < 8; kk++) {
                    wmma::load_matrix_sync(af[i][kk], &sQ[(wm * 32 + i * 16) * 68 + kk * 8], 68);
                    to_tf32(af[i][kk]);
                }
        }

        const float* sKt = sK + (ct & 1) * (64 * 68);
        wmma::fragment<wmma::accumulator, 16, 16, 8, float> acc[2];
        wmma::fill_fragment(acc[0], 0.0f);
        wmma::fill_fragment(acc[1], 0.0f);

#pragma unroll
        for (int kk = 0; kk < 8; kk++) {
            wmma::fragment<wmma::matrix_b, 16, 16, 8, wmma::precision::tf32, wmma::col_major> bf;
            wmma::load_matrix_sync(bf, &sKt[(wn * 16) * 68 + kk * 8], 68);
            to_tf32(bf);
            wmma::mma_sync(acc[0], af[0][kk], bf, acc[0]);
            wmma::mma_sync(acc[1], af[1][kk], bf, acc[1]);
        }
#pragma unroll
        for (int i = 0; i < 2; i++)
            wmma::store_matrix_sync(&sS[(wm * 32 + i * 16) * 68 + wn * 16], acc[i], 68,
                                    wmma::mem_row_major);
        __syncthreads();   // B: sS complete; K buffer reuse guarded

        // epilogue: warp w owns rows {8w .. 8w+7}; mask read from SMEM
        const int c0 = ct * 64;
        const unsigned char* mTile = sMask + mbuf * 4096;
#pragma unroll
        for (int pass = 0; pass < 4; pass++) {
            const int r  = w * 8 + pass * 2 + (l >> 4);
            const int cc = (l & 15) << 2;
            float4 v = *(const float4*)&sS[r * 68 + cc];
            uchar4 mk = *(const uchar4*)&mTile[r * 64 + cc];
            v.x = mk.x ? 0.0f : __expf(v.x * SCALE);
            v.y = mk.y ? 0.0f : __expf(v.y * SCALE);
            v.z = mk.z ? 0.0f : __expf(v.z * SCALE);
            v.w = mk.w ? 0.0f : __expf(v.w * SCALE);
            float* erow = attnOut + ((size_t)(bh * NS + q0 + r)) * NS + c0;
            *(float4*)&erow[cc] = v;
            float s = v.x + v.y + v.z + v.w;
#pragma unroll
            for (int off = 8; off > 0; off >>= 1)
                s += __shfl_xor_sync(0xffffffffu, s, off);
            if ((l & 15) == 0) sSum[r] += s;   // one (warp,half) per row: no race
        }
        mbuf = mnext;
    }

    __syncthreads();
    if (tid < 64) g_inv[(size_t)bh * NS + q0 + tid] = 1.0f / sSum[tid];
}

// ---------------------------------------------------------------------------
// ctxnorm v3.1 — WARP SPECIALIZED, V-prefetch lagged (race-free; see r8).
// ---------------------------------------------------------------------------
#define CTX_ER   (2 * 128 * 68 * 4)     // 69632
#define CTX_VH   (2 * 64 * 72 * 2)      // 18432
#define CTX_PB   (2 * 128 * 72 * 2)     // 73728
#define CTX_SMEM (CTX_ER + CTX_VH + CTX_PB + 512)   // 162304

__global__ __launch_bounds__(512) void ctxnorm_kernel(float* __restrict__ attn) {
    extern __shared__ char smc[];
    float*         sEraw = (float*)smc;                               // 2 x 128 x 68
    __nv_bfloat16* sVh   = (__nv_bfloat16*)(smc + CTX_ER);            // 2 x 64 x 72
    __nv_bfloat16* sPb   = (__nv_bfloat16*)(smc + CTX_ER + CTX_VH);   // 2 x 128 x 72
    float*         sInv  = (float*)(smc + CTX_ER + CTX_VH + CTX_PB);  // 128

    const int tid = threadIdx.x;
    const int w   = tid >> 5;
    const int l   = tid & 31;
    const int bh  = blockIdx.y;
    const int b   = bh >> 4;
    const int h   = bh & 15;
    const int m0  = blockIdx.x * 128;

    float* Eb = attn + ((size_t)bh * NS + m0) * NS;
    const __nv_bfloat16* Vb = g_Vh + ((size_t)b * NS) * ND + h * NDH;

    if (tid < 128) sInv[tid] = g_inv[(size_t)bh * NS + m0 + tid];

    // pre-loop group: E chunk 0 only (V[0] comes with iteration 0's group)
#pragma unroll
    for (int i = 0; i < 4; i++) {
        int idx = tid + i * 512;
        int er = idx >> 4, ec = (idx & 15) << 2;
        cpa16(&sEraw[er * 68 + ec], &Eb[(size_t)er * NS + ec]);
    }
    cpa_commit();

    const int wv = w - 8;
    const int wm = wv >> 1, wn = wv & 1;    // MMA warps: 4(m) x 2(n), 32x32
    const int band = w * 16;                // epi warps (w<8): 16-row band

    wmma::fragment<wmma::accumulator, 16, 16, 16, float> acc[2][2];
    if (w >= 8) {
#pragma unroll
        for (int i = 0; i < 2; i++)
#pragma unroll
            for (int j = 0; j < 2; j++) wmma::fill_fragment(acc[i][j], 0.0f);
    }

    for (int kc = 0; kc <= 32; kc++) {
        __syncthreads();   // A: prior compute done -> buffer reuse safe
        if (kc < 32) {
            // group kc: E[kc+1] (if it exists) + V[kc]
            if (kc + 1 < 32) {
                float* dE = sEraw + ((kc + 1) & 1) * (128 * 68);
#pragma unroll
                for (int i = 0; i < 4; i++) {
                    int idx = tid + i * 512;
                    int er = idx >> 4, ec = (idx & 15) << 2;
                    cpa16(&dE[er * 68 + ec],
                          &Eb[(size_t)er * NS + (size_t)(kc + 1) * 64 + ec]);
                }
            }
            {
                __nv_bfloat16* dV = sVh + (kc & 1) * (64 * 72);
                int vr = tid >> 3, vc = (tid & 7) << 3;
                cpa16(&dV[vr * 72 + vc], &Vb[(size_t)(kc * 64 + vr) * ND + vc]);
            }
            cpa_commit();
            cpa_wait<1>();   // group kc-1 (E[kc], V[kc-1]) complete
        } else {
            cpa_wait<0>();   // everything (incl. V[31]) complete
        }
        __syncthreads();   // B: E[kc], V[kc-1], sPb[(kc-1)&1] visible

        if (w < 8) {
            if (kc < 32) {
                const float* cE = sEraw + (kc & 1) * (128 * 68);
                __nv_bfloat16* dP = sPb + (kc & 1) * (128 * 72);
                const size_t gk = (size_t)kc * 64;
#pragma unroll
                for (int i = 0; i < 8; i++) {
                    int idx = i * 32 + l;
                    int r = band + (idx >> 4);
                    int cc = (idx & 15) << 2;
                    float4 v = *(const float4*)&cE[r * 68 + cc];
                    float iv = sInv[r];
                    v.x *= iv; v.y *= iv; v.z *= iv; v.w *= iv;
                    *(float4*)&Eb[(size_t)r * NS + gk + cc] = v;
                    *(uint32_t*)&dP[r * 72 + cc]     = pack_bf2(v.x, v.y);
                    *(uint32_t*)&dP[r * 72 + cc + 2] = pack_bf2(v.z, v.w);
                }
            }
        } else if (kc >= 1) {
            const int kp = kc - 1;
            const __nv_bfloat16* cP = sPb + (kp & 1) * (128 * 72);
            const __nv_bfloat16* cV = sVh + (kp & 1) * (64 * 72);
#pragma unroll
            for (int kk = 0; kk < 4; kk++) {
                wmma::fragment<wmma::matrix_a, 16, 16, 16, __nv_bfloat16, wmma::row_major> af[2];
                wmma::fragment<wmma::matrix_b, 16, 16, 16, __nv_bfloat16, wmma::row_major> bf[2];
#pragma unroll
                for (int i = 0; i < 2; i++)
                    wmma::load_matrix_sync(af[i], &cP[(wm * 32 + i * 16) * 72 + kk * 16], 72);
#pragma unroll
                for (int j = 0; j < 2; j++)
                    wmma::load_matrix_sync(bf[j], &cV[(kk * 16) * 72 + wn * 32 + j * 16], 72);
#pragma unroll
                for (int i = 0; i < 2; i++)
#pragma unroll
                    for (int j = 0; j < 2; j++)
                        wmma::mma_sync(acc[i][j], af[i], bf[j], acc[i][j]);
            }
        }
    }

    __syncthreads();
    // epilogue: MMA warps stage f32 accs in sEraw (per-warp region), emit bf16
    if (w >= 8) {
        float* stg = sEraw + wv * (32 * 36);
#pragma unroll
        for (int i = 0; i < 2; i++)
#pragma unroll
            for (int j = 0; j < 2; j++)
                wmma::store_matrix_sync(&stg[(i * 16) * 36 + j * 16], acc[i][j], 36,
                                        wmma::mem_row_major);
        __syncwarp();
        const float* row = stg + l * 36;
        uint32_t pk[16];
#pragma unroll
        for (int j = 0; j < 16; j++) pk[j] = pack_bf2(row[2 * j], row[2 * j + 1]);
        __nv_bfloat16* gp = g_ctxh + (size_t)(b * NS + m0 + wm * 32 + l) * ND + h * NDH + wn * 32;
#pragma unroll
        for (int j = 0; j < 4; j++)
            *(uint4*)(gp + j * 8) = make_uint4(pk[4 * j], pk[4 * j + 1], pk[4 * j + 2], pk[4 * j + 3]);
    }
}

// ---------------------------------------------------------------------------
// Residual + LayerNorm
// ---------------------------------------------------------------------------
__global__ __launch_bounds__(256) void ln_kernel(const float* __restrict__ resid,
                                                 float* __restrict__ out) {
    const int row = blockIdx.x;
    const int tid = threadIdx.x;

    float4 f  = *(const float4*)&g_fc[(size_t)row * ND + tid * 4];
    float4 rr = *(const float4*)&resid[(size_t)row * ND + tid * 4];
    float4 y;
    y.x = f.x + rr.x; y.y = f.y + rr.y; y.z = f.z + rr.z; y.w = f.w + rr.w;

    float s = y.x + y.y + y.z + y.w;
    float q = y.x * y.x + y.y * y.y + y.z * y.z + y.w * y.w;
#pragma unroll
    for (int off = 16; off > 0; off >>= 1) {
        s += __shfl_down_sync(0xffffffffu, s, off);
        q += __shfl_down_sync(0xffffffffu, q, off);
    }
    __shared__ float ss[8], sq[8];
    __shared__ float mu_s, rs_s;
    if ((tid & 31) == 0) { ss[tid >> 5] = s; sq[tid >> 5] = q; }
    __syncthreads();
    if (tid == 0) {
        float S = 0.0f, Q = 0.0f;
#pragma unroll
        for (int i = 0; i < 8; i++) { S += ss[i]; Q += sq[i]; }
        float mu  = S * (1.0f / ND);
        float var = Q * (1.0f / ND) - mu * mu;
        mu_s = mu;
        rs_s = rsqrtf(var + LN_EPS);
    }
    __syncthreads();
    const float mu = mu_s, rs = rs_s;
    float4 o;
    o.x = (y.x - mu) * rs; o.y = (y.y - mu) * rs;
    o.z = (y.z - mu) * rs; o.w = (y.w - mu) * rs;
    *(float4*)&out[(size_t)row * ND + tid * 4] = o;
}

// ---------------------------------------------------------------------------
extern "C" void kernel_launch(void* const* d_in, const int* in_sizes, int n_in,
                              void* d_out, int out_size) {
    const float* inQ = (const float*)d_in[0];
    const float* inK = (const float*)d_in[1];
    const float* inV = (const float*)d_in[2];
    const unsigned char* mask = (const unsigned char*)d_in[3];
    const float* WQ  = (const float*)d_in[4];
    const float* WK  = (const float*)d_in[5];
    const float* WV  = (const float*)d_in[6];
    const float* Wfc = (const float*)d_in[7];

    float* out  = (float*)d_out;
    float* attn = out + OUT_ELEMS;

    void *pQ, *pK, *pV, *pFc, *pVh, *pWfch, *pCtxh, *pInVh, *pWVh;
    cudaGetSymbolAddress(&pQ, g_Q);
    cudaGetSymbolAddress(&pK, g_K);
    cudaGetSymbolAddress(&pV, g_V);
    cudaGetSymbolAddress(&pFc, g_fc);
    cudaGetSymbolAddress(&pVh, g_Vh);
    cudaGetSymbolAddress(&pWfch, g_Wfch);
    cudaGetSymbolAddress(&pCtxh, g_ctxh);
    cudaGetSymbolAddress(&pInVh, g_inVh);
    cudaGetSymbolAddress(&pWVh, g_WVh);

    cudaFuncSetAttribute(escore_kernel, cudaFuncAttributeMaxDynamicSharedMemorySize, ESC_SMEM);
    cudaFuncSetAttribute(ctxnorm_kernel, cudaFuncAttributeMaxDynamicSharedMemorySize, CTX_SMEM);

    // bf16 staging for the error-insensitive path (V projection + fc)
    cvt_kernel<<<(TOK * ND / 4 + 255) / 256, 256>>>(inV, (__nv_bfloat16*)pInVh, TOK * ND);
    cvt_kernel<<<(ND * ND / 4 + 255) / 256, 256>>>(WV, (__nv_bfloat16*)pWVh, ND * ND);
    cvt_kernel<<<(ND * ND / 4 + 255) / 256, 256>>>(Wfc, (__nv_bfloat16*)pWfch, ND * ND);

    // Q, K projections in tf32 (attn-precision-critical)
    qk_gemm<<<dim3(8, 32, 2), 256>>>(inQ, WQ, inK, WK, (float*)pQ, (float*)pK);

    // V projection in bf16
    gemm_bf16<<<dim3(8, 32), 256>>>((const __nv_bfloat16*)pInVh, (const __nv_bfloat16*)pWVh,
                                    (float*)pV);
    cvt_kernel<<<(TOK * ND / 4 + 255) / 256, 256>>>((const float*)pV, (__nv_bfloat16*)pVh, TOK * ND);

    escore_kernel<<<dim3(32, 32), 256, ESC_SMEM>>>(mask, attn);

    ctxnorm_kernel<<<dim3(16, 32), 512, CTX_SMEM>>>(attn);

    gemm_bf16<<<dim3(8, 32), 256>>>((const __nv_bfloat16*)pCtxh, (const __nv_bfloat16*)pWfch,
                                    (float*)pFc);

    ln_kernel<<<TOK, 256>>>(inQ, out);
}

// round 13
// speedup vs baseline: 2.2592x; 1.0060x over previous
#include <cuda_runtime.h>
#include <cuda_bf16.h>
#include <mma.h>
#include <cstdint>
#include <cstddef>

using namespace nvcuda;

// Problem shape (fixed): B=2, S=2048, D=1024, H=16, Dh=64
#define NB 2
#define NS 2048
#define ND 1024
#define NH 16
#define NDH 64
#define TOK (NB*NS)
#define OUT_ELEMS (4194304)
#define SCALE 0.125f
#define LN_EPS 1e-5f

// ---- scratch (__device__ globals; no allocation allowed) ----
__device__ float g_Q[TOK*ND];                  // tf32-rounded Q projection
__device__ float g_K[TOK*ND];                  // tf32-rounded K projection
__device__ float g_V[TOK*ND];                  // staging: tf32-rounded inQ
__device__ float g_fc[TOK*ND];                 // staging: tf32-rounded inK; later fc output
__device__ float g_WQr[ND*ND];                 // tf32-rounded W_Q
__device__ float g_WKr[ND*ND];                 // tf32-rounded W_K
__device__ float g_inv[32 * NS];               // 1/rowsum per [bh][row]
__device__ __nv_bfloat16 g_Vh[TOK*ND];         // bf16 V projection (direct output)
__device__ __nv_bfloat16 g_Wfch[ND*ND];        // bf16 copy of W_fc
__device__ __nv_bfloat16 g_ctxh[TOK*ND];       // bf16 context
__device__ __nv_bfloat16 g_inVh[TOK*ND];       // bf16 copy of input_V
__device__ __nv_bfloat16 g_WVh[ND*ND];         // bf16 copy of W_V

// ---------------------------------------------------------------------------
template <typename Frag>
__device__ __forceinline__ void to_tf32(Frag& f) {
#pragma unroll
    for (int i = 0; i < f.num_elements; i++) f.x[i] = wmma::__float_to_tf32(f.x[i]);
}

__device__ __forceinline__ void cpa16(void* s, const void* g) {
    uint32_t sa = (uint32_t)__cvta_generic_to_shared(s);
    asm volatile("cp.async.ca.shared.global [%0], [%1], 16;" :: "r"(sa), "l"(g));
}
__device__ __forceinline__ void cpa_commit() {
    asm volatile("cp.async.commit_group;" ::: "memory");
}
template <int N>
__device__ __forceinline__ void cpa_wait() {
    asm volatile("cp.async.wait_group %0;" :: "n"(N) : "memory");
}

__device__ __forceinline__ uint32_t pack_bf2(float a, float b) {
    __nv_bfloat162 t = __float22bfloat162_rn(make_float2(a, b));
    return *(uint32_t*)&t;
}

// ---------------------------------------------------------------------------
// f32 -> bf16 convert kernel
// ---------------------------------------------------------------------------
__global__ __launch_bounds__(256) void cvt_kernel(const float* __restrict__ s,
                                                  __nv_bfloat16* __restrict__ d, int n) {
    int i = (blockIdx.x * 256 + threadIdx.x) * 4;
    if (i < n) {
        float4 v = *(const float4*)&s[i];
        *(uint32_t*)&d[i]     = pack_bf2(v.x, v.y);
        *(uint32_t*)&d[i + 2] = pack_bf2(v.z, v.w);
    }
}

// f32 -> tf32-rounded f32 (RN), elementwise
__global__ __launch_bounds__(256) void cvt_tf32_kernel(const float* __restrict__ s,
                                                       float* __restrict__ d, int n) {
    int i = (blockIdx.x * 256 + threadIdx.x) * 4;
    if (i < n) {
        float4 v = *(const float4*)&s[i];
        v.x = wmma::__float_to_tf32(v.x);
        v.y = wmma::__float_to_tf32(v.y);
        v.z = wmma::__float_to_tf32(v.z);
        v.w = wmma::__float_to_tf32(v.w);
        *(float4*)&d[i] = v;
    }
}

// ---------------------------------------------------------------------------
// tf32 GEMM, NO in-loop conversions (inputs pre-rounded to tf32).
// Epilogue rounds C to tf32 so consumers need no conversion either.
// BK=32, 2-stage cp.async, BM=BN=128, 8 warps, warp tile 64x32.
// ---------------------------------------------------------------------------
__device__ __forceinline__ void gemm_body_nr(const float* __restrict__ A,
                                             const float* __restrict__ Bw,
                                             float* __restrict__ C) {
    __shared__ float sA[2][128][36];
    __shared__ float sB[2][32][132];

    const int tid = threadIdx.x;
    const int w   = tid >> 5;
    const int wm  = w >> 2;
    const int wn  = w & 3;
    const int m0  = blockIdx.y * 128;
    const int n0  = blockIdx.x * 128;

#define LOADT(st, k0)                                                                  \
    {                                                                                  \
        _Pragma("unroll")                                                              \
        for (int i = 0; i < 4; i++) {                                                  \
            int idx = tid + i * 256;                                                   \
            int ra = idx >> 3, ca = (idx & 7) << 2;                                    \
            cpa16(&sA[st][ra][ca], &A[(size_t)(m0 + ra) * ND + (k0) + ca]);            \
            int rb = idx >> 5, cb = (idx & 31) << 2;                                   \
            cpa16(&sB[st][rb][cb], &Bw[(size_t)((k0) + rb) * ND + n0 + cb]);           \
        }                                                                              \
        cpa_commit();                                                                  \
    }

    wmma::fragment<wmma::accumulator, 16, 16, 8, float> acc[4][2];
#pragma unroll
    for (int i = 0; i < 4; i++)
#pragma unroll
        for (int j = 0; j < 2; j++) wmma::fill_fragment(acc[i][j], 0.0f);

    LOADT(0, 0);

    for (int kt = 0; kt < 32; kt++) {
        if (kt < 31) {
            LOADT((kt + 1) & 1, (kt + 1) * 32);
            cpa_wait<1>();
        } else {
            cpa_wait<0>();
        }
        __syncthreads();
        const int st = kt & 1;
#pragma unroll
        for (int ks = 0; ks < 32; ks += 8) {
            wmma::fragment<wmma::matrix_a, 16, 16, 8, wmma::precision::tf32, wmma::row_major> af[4];
            wmma::fragment<wmma::matrix_b, 16, 16, 8, wmma::precision::tf32, wmma::row_major> bf[2];
#pragma unroll
            for (int i = 0; i < 4; i++)
                wmma::load_matrix_sync(af[i], &sA[st][wm * 64 + i * 16][ks], 36);
#pragma unroll
            for (int j = 0; j < 2; j++)
                wmma::load_matrix_sync(bf[j], &sB[st][ks][wn * 32 + j * 16], 132);
#pragma unroll
            for (int i = 0; i < 4; i++)
#pragma unroll
                for (int j = 0; j < 2; j++)
                    wmma::mma_sync(acc[i][j], af[i], bf[j], acc[i][j]);
        }
        __syncthreads();
    }
#undef LOADT

    // round outputs to tf32 so downstream MMAs need no conversion
#pragma unroll
    for (int i = 0; i < 4; i++)
#pragma unroll
        for (int j = 0; j < 2; j++) {
            to_tf32(acc[i][j]);
            wmma::store_matrix_sync(&C[(size_t)(m0 + wm * 64 + i * 16) * ND + n0 + wn * 32 + j * 16],
                                    acc[i][j], ND, wmma::mem_row_major);
        }
}

// Q and K projections (z selects); inputs pre-rounded to tf32.
__global__ __launch_bounds__(256, 2) void qk_gemm(const float* __restrict__ iQr, const float* __restrict__ WQr,
                                                  const float* __restrict__ iKr, const float* __restrict__ WKr,
                                                  float* __restrict__ oQ, float* __restrict__ oK) {
    const int z = blockIdx.z;
    gemm_body_nr(z == 0 ? iQr : iKr, z == 0 ? WQr : WKr, z == 0 ? oQ : oK);
}

// ---------------------------------------------------------------------------
// bf16 GEMM: C f32 = A bf16 @ B bf16. BK=32, 2-stage. (fc projection)
// ---------------------------------------------------------------------------
__global__ __launch_bounds__(256, 2) void gemm_bf16(const __nv_bfloat16* __restrict__ A,
                                                    const __nv_bfloat16* __restrict__ Bw,
                                                    float* __restrict__ C) {
    __shared__ __nv_bfloat16 sA[2][128][40];
    __shared__ __nv_bfloat16 sB[2][32][136];

    const int tid = threadIdx.x;
    const int w   = tid >> 5;
    const int wm  = w >> 2;
    const int wn  = w & 3;
    const int m0  = blockIdx.y * 128;
    const int n0  = blockIdx.x * 128;

#define LOADH(st, k0)                                                                  \
    {                                                                                  \
        _Pragma("unroll")                                                              \
        for (int i = 0; i < 2; i++) {                                                  \
            int idx = tid + i * 256;                                                   \
            int ra = idx >> 2, ca = (idx & 3) << 3;                                    \
            cpa16(&sA[st][ra][ca], &A[(size_t)(m0 + ra) * ND + (k0) + ca]);            \
            int rb = idx >> 4, cb = (idx & 15) << 3;                                   \
            cpa16(&sB[st][rb][cb], &Bw[(size_t)((k0) + rb) * ND + n0 + cb]);           \
        }                                                                              \
        cpa_commit();                                                                  \
    }

    wmma::fragment<wmma::accumulator, 16, 16, 16, float> acc[4][2];
#pragma unroll
    for (int i = 0; i < 4; i++)
#pragma unroll
        for (int j = 0; j < 2; j++) wmma::fill_fragment(acc[i][j], 0.0f);

    LOADH(0, 0);

    for (int kt = 0; kt < 32; kt++) {
        if (kt < 31) {
            LOADH((kt + 1) & 1, (kt + 1) * 32);
            cpa_wait<1>();
        } else {
            cpa_wait<0>();
        }
        __syncthreads();
        const int st = kt & 1;
#pragma unroll
        for (int ks = 0; ks < 32; ks += 16) {
            wmma::fragment<wmma::matrix_a, 16, 16, 16, __nv_bfloat16, wmma::row_major> af[4];
            wmma::fragment<wmma::matrix_b, 16, 16, 16, __nv_bfloat16, wmma::row_major> bf[2];
#pragma unroll
            for (int i = 0; i < 4; i++)
                wmma::load_matrix_sync(af[i], &sA[st][wm * 64 + i * 16][ks], 40);
#pragma unroll
            for (int j = 0; j < 2; j++)
                wmma::load_matrix_sync(bf[j], &sB[st][ks][wn * 32 + j * 16], 136);
#pragma unroll
            for (int i = 0; i < 4; i++)
#pragma unroll
                for (int j = 0; j < 2; j++)
                    wmma::mma_sync(acc[i][j], af[i], bf[j], acc[i][j]);
        }
        __syncthreads();
    }

#pragma unroll
    for (int i = 0; i < 4; i++)
#pragma unroll
        for (int j = 0; j < 2; j++)
            wmma::store_matrix_sync(&C[(size_t)(m0 + wm * 64 + i * 16) * ND + n0 + wn * 32 + j * 16],
                                    acc[i][j], ND, wmma::mem_row_major);
}

// ---------------------------------------------------------------------------
// bf16 GEMM with DIRECT bf16 output (V projection): C bf16 = A bf16 @ B bf16.
// Epilogue stages f32 accums through reused sA smem, packs to bf16.
// ---------------------------------------------------------------------------
__global__ __launch_bounds__(256, 2) void gemm_bf16_obf(const __nv_bfloat16* __restrict__ A,
                                                        const __nv_bfloat16* __restrict__ Bw,
                                                        __nv_bfloat16* __restrict__ C) {
    __shared__ __nv_bfloat16 sA[2][128][40];   // 20480 B (reused as f32 staging in epilogue)
    __shared__ __nv_bfloat16 sB[2][32][136];

    const int tid = threadIdx.x;
    const int w   = tid >> 5;
    const int l   = tid & 31;
    const int wm  = w >> 2;
    const int wn  = w & 3;
    const int m0  = blockIdx.y * 128;
    const int n0  = blockIdx.x * 128;

    wmma::fragment<wmma::accumulator, 16, 16, 16, float> acc[4][2];
#pragma unroll
    for (int i = 0; i < 4; i++)
#pragma unroll
        for (int j = 0; j < 2; j++) wmma::fill_fragment(acc[i][j], 0.0f);

    LOADH(0, 0);

    for (int kt = 0; kt < 32; kt++) {
        if (kt < 31) {
            LOADH((kt + 1) & 1, (kt + 1) * 32);
            cpa_wait<1>();
        } else {
            cpa_wait<0>();
        }
        __syncthreads();
        const int st = kt & 1;
#pragma unroll
        for (int ks = 0; ks < 32; ks += 16) {
            wmma::fragment<wmma::matrix_a, 16, 16, 16, __nv_bfloat16, wmma::row_major> af[4];
            wmma::fragment<wmma::matrix_b, 16, 16, 16, __nv_bfloat16, wmma::row_major> bf[2];
#pragma unroll
            for (int i = 0; i < 4; i++)
                wmma::load_matrix_sync(af[i], &sA[st][wm * 64 + i * 16][ks], 40);
#pragma unroll
            for (int j = 0; j < 2; j++)
                wmma::load_matrix_sync(bf[j], &sB[st][ks][wn * 32 + j * 16], 136);
#pragma unroll
            for (int i = 0; i < 4; i++)
#pragma unroll
                for (int j = 0; j < 2; j++)
                    wmma::mma_sync(acc[i][j], af[i], bf[j], acc[i][j]);
        }
        __syncthreads();   // final iter: all sA/sB reads done -> safe to reuse sA
    }
#undef LOADH

    // epilogue: per-warp 16x36 f32 staging inside sA (8 * 2304B = 18432 <= 20480)
    float* stg = (float*)sA + (size_t)w * (16 * 36);
#pragma unroll
    for (int i = 0; i < 4; i++) {
        wmma::store_matrix_sync(&stg[0],  acc[i][0], 36, wmma::mem_row_major);
        wmma::store_matrix_sync(&stg[16], acc[i][1], 36, wmma::mem_row_major);
        __syncwarp();
        const int r  = l & 15;          // row within 16
        const int hf = l >> 4;          // 0/1: which 16-col half
        const float* row = stg + r * 36 + hf * 16;
        uint32_t pk[8];
#pragma unroll
        for (int q = 0; q < 8; q++) pk[q] = pack_bf2(row[2 * q], row[2 * q + 1]);
        __nv_bfloat16* gp = C + (size_t)(m0 + wm * 64 + i * 16 + r) * ND + n0 + wn * 32 + hf * 16;
        *(uint4*)gp       = make_uint4(pk[0], pk[1], pk[2], pk[3]);
        *(uint4*)(gp + 8) = make_uint4(pk[4], pk[5], pk[6], pk[7]);
        __syncwarp();
    }
}

// ---------------------------------------------------------------------------
// escore v6 — v5 minus ALL tf32 conversions (Q/K pre-rounded by qk_gemm).
// grid = (32, 32), 256 threads, 2 blocks/SM. Mask triple-buffered in smem.
// ---------------------------------------------------------------------------
#define ESC_FLOATS (4 * 64 * 68 + 64)                    // 17472 floats
#define ESC_SMEM   (ESC_FLOATS * 4 + 3 * 64 * 64)        // 82176 B

__global__ __launch_bounds__(256, 2) void escore_kernel(const unsigned char* __restrict__ mask,
                                                        float* __restrict__ attnOut) {
    extern __shared__ float sm[];
    float* sQ   = sm;                        // 64 x 68
    float* sK   = sQ + 64 * 68;              // 2 x (64 x 68)
    float* sS   = sK + 2 * 64 * 68;          // 64 x 68
    float* sSum = sS + 64 * 68;              // 64
    unsigned char* sMask = (unsigned char*)(sSum + 64);   // 3 x (64 x 64) bytes

    const int tid = threadIdx.x;
    const int w   = tid >> 5;
    const int l   = tid & 31;
    const int bh  = blockIdx.y;
    const int b   = bh >> 4;
    const int h   = bh & 15;
    const int q0  = blockIdx.x * 64;

    const float* Qb = g_Q + ((size_t)(b * NS + q0)) * ND + h * NDH;
    const float* Kb = g_K + ((size_t)b * NS) * ND + h * NDH;
    const unsigned char* Mb = mask + ((size_t)(b * NS + q0)) * NS;

    const int mrw = tid >> 2;
    const int mcc = (tid & 3) << 4;

#pragma unroll
    for (int i = 0; i < 4; i++) {
        int idx = tid + i * 256;
        int r = idx >> 4, c = (idx & 15) << 2;
        cpa16(&sQ[r * 68 + c], &Qb[(size_t)r * ND + c]);
        cpa16(&sK[r * 68 + c], &Kb[(size_t)r * ND + c]);
    }
    cpa16(&sMask[mrw * 64 + mcc], &Mb[(size_t)mrw * NS + mcc]);
    cpa_commit();
    if (tid < 64) sSum[tid] = 0.0f;

    const int wm = w >> 2;
    const int wn = w & 3;

    wmma::fragment<wmma::matrix_a, 16, 16, 8, wmma::precision::tf32, wmma::row_major> af[2][8];

    int mbuf = 0;

    for (int ct = 0; ct < 32; ct++) {
        const int mnext = (mbuf + 1 == 3) ? 0 : mbuf + 1;
        if (ct < 31) {
            float* dst = sK + ((ct + 1) & 1) * (64 * 68);
            const float* src = Kb + (size_t)(ct + 1) * 64 * ND;
#pragma unroll
            for (int i = 0; i < 4; i++) {
                int idx = tid + i * 256;
                int r = idx >> 4, c = (idx & 15) << 2;
                cpa16(&dst[r * 68 + c], &src[(size_t)r * ND + c]);
            }
            cpa16(&sMask[mnext * 4096 + mrw * 64 + mcc],
                  &Mb[(size_t)mrw * NS + (size_t)(ct + 1) * 64 + mcc]);
            cpa_commit();
            cpa_wait<1>();
        } else {
            cpa_wait<0>();
        }
        __syncthreads();   // A: K[ct], M[ct] (and Q at ct=0) visible

        if (ct == 0) {
#pragma unroll
            for (int i = 0; i < 2; i++)
#pragma unroll
                for (int kk = 0; kk < 8; kk++)
                    wmma::load_matrix_sync(af[i][kk], &sQ[(wm * 32 + i * 16) * 68 + kk * 8], 68);
        }

        const float* sKt = sK + (ct & 1) * (64 * 68);
        wmma::fragment<wmma::accumulator, 16, 16, 8, float> acc[2];
        wmma::fill_fragment(acc[0], 0.0f);
        wmma::fill_fragment(acc[1], 0.0f);

#pragma unroll
        for (int kk = 0; kk < 8; kk++) {
            wmma::fragment<wmma::matrix_b, 16, 16, 8, wmma::precision::tf32, wmma::col_major> bf;
            wmma::load_matrix_sync(bf, &sKt[(wn * 16) * 68 + kk * 8], 68);
            wmma::mma_sync(acc[0], af[0][kk], bf, acc[0]);
            wmma::mma_sync(acc[1], af[1][kk], bf, acc[1]);
        }
#pragma unroll
        for (int i = 0; i < 2; i++)
            wmma::store_matrix_sync(&sS[(wm * 32 + i * 16) * 68 + wn * 16], acc[i], 68,
                                    wmma::mem_row_major);
        __syncthreads();   // B: sS complete; K buffer reuse guarded

        const int c0 = ct * 64;
        const unsigned char* mTile = sMask + mbuf * 4096;
#pragma unroll
        for (int pass = 0; pass < 4; pass++) {
            const int r  = w * 8 + pass * 2 + (l >> 4);
            const int cc = (l & 15) << 2;
            float4 v = *(const float4*)&sS[r * 68 + cc];
            uchar4 mk = *(const uchar4*)&mTile[r * 64 + cc];
            v.x = mk.x ? 0.0f : __expf(v.x * SCALE);
            v.y = mk.y ? 0.0f : __expf(v.y * SCALE);
            v.z = mk.z ? 0.0f : __expf(v.z * SCALE);
            v.w = mk.w ? 0.0f : __expf(v.w * SCALE);
            float* erow = attnOut + ((size_t)(bh * NS + q0 + r)) * NS + c0;
            *(float4*)&erow[cc] = v;
            float s = v.x + v.y + v.z + v.w;
#pragma unroll
            for (int off = 8; off > 0; off >>= 1)
                s += __shfl_xor_sync(0xffffffffu, s, off);
            if ((l & 15) == 0) sSum[r] += s;
        }
        mbuf = mnext;
    }

    __syncthreads();
    if (tid < 64) g_inv[(size_t)bh * NS + q0 + tid] = 1.0f / sSum[tid];
}

// ---------------------------------------------------------------------------
// ctxnorm v3.1 — WARP SPECIALIZED, V-prefetch lagged (race-free).
// ---------------------------------------------------------------------------
#define CTX_ER   (2 * 128 * 68 * 4)     // 69632
#define CTX_VH   (2 * 64 * 72 * 2)      // 18432
#define CTX_PB   (2 * 128 * 72 * 2)     // 73728
#define CTX_SMEM (CTX_ER + CTX_VH + CTX_PB + 512)   // 162304

__global__ __launch_bounds__(512) void ctxnorm_kernel(float* __restrict__ attn) {
    extern __shared__ char smc[];
    float*         sEraw = (float*)smc;
    __nv_bfloat16* sVh   = (__nv_bfloat16*)(smc + CTX_ER);
    __nv_bfloat16* sPb   = (__nv_bfloat16*)(smc + CTX_ER + CTX_VH);
    float*         sInv  = (float*)(smc + CTX_ER + CTX_VH + CTX_PB);

    const int tid = threadIdx.x;
    const int w   = tid >> 5;
    const int l   = tid & 31;
    const int bh  = blockIdx.y;
    const int b   = bh >> 4;
    const int h   = bh & 15;
    const int m0  = blockIdx.x * 128;

    float* Eb = attn + ((size_t)bh * NS + m0) * NS;
    const __nv_bfloat16* Vb = g_Vh + ((size_t)b * NS) * ND + h * NDH;

    if (tid < 128) sInv[tid] = g_inv[(size_t)bh * NS + m0 + tid];

#pragma unroll
    for (int i = 0; i < 4; i++) {
        int idx = tid + i * 512;
        int er = idx >> 4, ec = (idx & 15) << 2;
        cpa16(&sEraw[er * 68 + ec], &Eb[(size_t)er * NS + ec]);
    }
    cpa_commit();

    const int wv = w - 8;
    const int wm = wv >> 1, wn = wv & 1;
    const int band = w * 16;

    wmma::fragment<wmma::accumulator, 16, 16, 16, float> acc[2][2];
    if (w >= 8) {
#pragma unroll
        for (int i = 0; i < 2; i++)
#pragma unroll
            for (int j = 0; j < 2; j++) wmma::fill_fragment(acc[i][j], 0.0f);
    }

    for (int kc = 0; kc <= 32; kc++) {
        __syncthreads();   // A
        if (kc < 32) {
            if (kc + 1 < 32) {
                float* dE = sEraw + ((kc + 1) & 1) * (128 * 68);
#pragma unroll
                for (int i = 0; i < 4; i++) {
                    int idx = tid + i * 512;
                    int er = idx >> 4, ec = (idx & 15) << 2;
                    cpa16(&dE[er * 68 + ec],
                          &Eb[(size_t)er * NS + (size_t)(kc + 1) * 64 + ec]);
                }
            }
            {
                __nv_bfloat16* dV = sVh + (kc & 1) * (64 * 72);
                int vr = tid >> 3, vc = (tid & 7) << 3;
                cpa16(&dV[vr * 72 + vc], &Vb[(size_t)(kc * 64 + vr) * ND + vc]);
            }
            cpa_commit();
            cpa_wait<1>();
        } else {
            cpa_wait<0>();
        }
        __syncthreads();   // B

        if (w < 8) {
            if (kc < 32) {
                const float* cE = sEraw + (kc & 1) * (128 * 68);
                __nv_bfloat16* dP = sPb + (kc & 1) * (128 * 72);
                const size_t gk = (size_t)kc * 64;
#pragma unroll
                for (int i = 0; i < 8; i++) {
                    int idx = i * 32 + l;
                    int r = band + (idx >> 4);
                    int cc = (idx & 15) << 2;
                    float4 v = *(const float4*)&cE[r * 68 + cc];
                    float iv = sInv[r];
                    v.x *= iv; v.y *= iv; v.z *= iv; v.w *= iv;
                    *(float4*)&Eb[(size_t)r * NS + gk + cc] = v;
                    *(uint32_t*)&dP[r * 72 + cc]     = pack_bf2(v.x, v.y);
                    *(uint32_t*)&dP[r * 72 + cc + 2] = pack_bf2(v.z, v.w);
                }
            }
        } else if (kc >= 1) {
            const int kp = kc - 1;
            const __nv_bfloat16* cP = sPb + (kp & 1) * (128 * 72);
            const __nv_bfloat16* cV = sVh + (kp & 1) * (64 * 72);
#pragma unroll
            for (int kk = 0; kk < 4; kk++) {
                wmma::fragment<wmma::matrix_a, 16, 16, 16, __nv_bfloat16, wmma::row_major> af[2];
                wmma::fragment<wmma::matrix_b, 16, 16, 16, __nv_bfloat16, wmma::row_major> bf[2];
#pragma unroll
                for (int i = 0; i < 2; i++)
                    wmma::load_matrix_sync(af[i], &cP[(wm * 32 + i * 16) * 72 + kk * 16], 72);
#pragma unroll
                for (int j = 0; j < 2; j++)
                    wmma::load_matrix_sync(bf[j], &cV[(kk * 16) * 72 + wn * 32 + j * 16], 72);
#pragma unroll
                for (int i = 0; i < 2; i++)
#pragma unroll
                    for (int j = 0; j < 2; j++)
                        wmma::mma_sync(acc[i][j], af[i], bf[j], acc[i][j]);
            }
        }
    }

    __syncthreads();
    if (w >= 8) {
        float* stg = sEraw + wv * (32 * 36);
#pragma unroll
        for (int i = 0; i < 2; i++)
#pragma unroll
            for (int j = 0; j < 2; j++)
                wmma::store_matrix_sync(&stg[(i * 16) * 36 + j * 16], acc[i][j], 36,
                                        wmma::mem_row_major);
        __syncwarp();
        const float* row = stg + l * 36;
        uint32_t pk[16];
#pragma unroll
        for (int j = 0; j < 16; j++) pk[j] = pack_bf2(row[2 * j], row[2 * j + 1]);
        __nv_bfloat16* gp = g_ctxh + (size_t)(b * NS + m0 + wm * 32 + l) * ND + h * NDH + wn * 32;
#pragma unroll
        for (int j = 0; j < 4; j++)
            *(uint4*)(gp + j * 8) = make_uint4(pk[4 * j], pk[4 * j + 1], pk[4 * j + 2], pk[4 * j + 3]);
    }
}

// ---------------------------------------------------------------------------
// Residual + LayerNorm
// ---------------------------------------------------------------------------
__global__ __launch_bounds__(256) void ln_kernel(const float* __restrict__ resid,
                                                 float* __restrict__ out) {
    const int row = blockIdx.x;
    const int tid = threadIdx.x;

    float4 f  = *(const float4*)&g_fc[(size_t)row * ND + tid * 4];
    float4 rr = *(const float4*)&resid[(size_t)row * ND + tid * 4];
    float4 y;
    y.x = f.x + rr.x; y.y = f.y + rr.y; y.z = f.z + rr.z; y.w = f.w + rr.w;

    float s = y.x + y.y + y.z + y.w;
    float q = y.x * y.x + y.y * y.y + y.z * y.z + y.w * y.w;
#pragma unroll
    for (int off = 16; off > 0; off >>= 1) {
        s += __shfl_down_sync(0xffffffffu, s, off);
        q += __shfl_down_sync(0xffffffffu, q, off);
    }
    __shared__ float ss[8], sq[8];
    __shared__ float mu_s, rs_s;
    if ((tid & 31) == 0) { ss[tid >> 5] = s; sq[tid >> 5] = q; }
    __syncthreads();
    if (tid == 0) {
        float S = 0.0f, Q = 0.0f;
#pragma unroll
        for (int i = 0; i < 8; i++) { S += ss[i]; Q += sq[i]; }
        float mu  = S * (1.0f / ND);
        float var = Q * (1.0f / ND) - mu * mu;
        mu_s = mu;
        rs_s = rsqrtf(var + LN_EPS);
    }
    __syncthreads();
    const float mu = mu_s, rs = rs_s;
    float4 o;
    o.x = (y.x - mu) * rs; o.y = (y.y - mu) * rs;
    o.z = (y.z - mu) * rs; o.w = (y.w - mu) * rs;
    *(float4*)&out[(size_t)row * ND + tid * 4] = o;
}

// ---------------------------------------------------------------------------
extern "C" void kernel_launch(void* const* d_in, const int* in_sizes, int n_in,
                              void* d_out, int out_size) {
    const float* inQ = (const float*)d_in[0];
    const float* inK = (const float*)d_in[1];
    const float* inV = (const float*)d_in[2];
    const unsigned char* mask = (const unsigned char*)d_in[3];
    const float* WQ  = (const float*)d_in[4];
    const float* WK  = (const float*)d_in[5];
    const float* WV  = (const float*)d_in[6];
    const float* Wfc = (const float*)d_in[7];

    float* out  = (float*)d_out;
    float* attn = out + OUT_ELEMS;

    void *pQ, *pK, *pV, *pFc, *pWQr, *pWKr, *pVh, *pWfch, *pCtxh, *pInVh, *pWVh;
    cudaGetSymbolAddress(&pQ, g_Q);
    cudaGetSymbolAddress(&pK, g_K);
    cudaGetSymbolAddress(&pV, g_V);
    cudaGetSymbolAddress(&pFc, g_fc);
    cudaGetSymbolAddress(&pWQr, g_WQr);
    cudaGetSymbolAddress(&pWKr, g_WKr);
    cudaGetSymbolAddress(&pVh, g_Vh);
    cudaGetSymbolAddress(&pWfch, g_Wfch);
    cudaGetSymbolAddress(&pCtxh, g_ctxh);
    cudaGetSymbolAddress(&pInVh, g_inVh);
    cudaGetSymbolAddress(&pWVh, g_WVh);

    cudaFuncSetAttribute(escore_kernel, cudaFuncAttributeMaxDynamicSharedMemorySize, ESC_SMEM);
    cudaFuncSetAttribute(ctxnorm_kernel, cudaFuncAttributeMaxDynamicSharedMemorySize, CTX_SMEM);

    const int NGE = (TOK * ND / 4 + 255) / 256;   // element-grid for TOK*ND
    const int NGW = (ND * ND / 4 + 255) / 256;    // element-grid for ND*ND

    // pre-round QK-path inputs to tf32 (g_V, g_fc free as staging here)
    cvt_tf32_kernel<<<NGE, 256>>>(inQ, (float*)pV, TOK * ND);
    cvt_tf32_kernel<<<NGW, 256>>>(WQ, (float*)pWQr, ND * ND);
    cvt_tf32_kernel<<<NGE, 256>>>(inK, (float*)pFc, TOK * ND);
    cvt_tf32_kernel<<<NGW, 256>>>(WK, (float*)pWKr, ND * ND);

    // bf16 staging for the error-insensitive path
    cvt_kernel<<<NGE, 256>>>(inV, (__nv_bfloat16*)pInVh, TOK * ND);
    cvt_kernel<<<NGW, 256>>>(WV, (__nv_bfloat16*)pWVh, ND * ND);
    cvt_kernel<<<NGW, 256>>>(Wfc, (__nv_bfloat16*)pWfch, ND * ND);

    // Q, K projections in tf32 (no in-loop cvts; outputs tf32-rounded)
    qk_gemm<<<dim3(8, 32, 2), 256>>>((const float*)pV, (const float*)pWQr,
                                     (const float*)pFc, (const float*)pWKr,
                                     (float*)pQ, (float*)pK);

    // V projection in bf16, direct bf16 output
    gemm_bf16_obf<<<dim3(8, 32), 256>>>((const __nv_bfloat16*)pInVh, (const __nv_bfloat16*)pWVh,
                                        (__nv_bfloat16*)pVh);

    escore_kernel<<<dim3(32, 32), 256, ESC_SMEM>>>(mask, attn);

    ctxnorm_kernel<<<dim3(16, 32), 512, CTX_SMEM>>>(attn);

    gemm_bf16<<<dim3(8, 32), 256>>>((const __nv_bfloat16*)pCtxh, (const __nv_bfloat16*)pWfch,
                                    (float*)pFc);

    ln_kernel<<<TOK, 256>>>(inQ, out);
}

// round 14
// speedup vs baseline: 3.4032x; 1.5064x over previous
#include <cuda_runtime.h>
#include <cuda_bf16.h>
#include <cuda_fp16.h>
#include <mma.h>
#include <cstdint>
#include <cstddef>

using namespace nvcuda;

// Problem shape (fixed): B=2, S=2048, D=1024, H=16, Dh=64
#define NB 2
#define NS 2048
#define ND 1024
#define NH 16
#define NDH 64
#define TOK (NB*NS)
#define OUT_ELEMS (4194304)
#define SCALE 0.125f
#define LN_EPS 1e-5f

// ---- scratch (__device__ globals; no allocation allowed) ----
__device__ float g_fc[TOK*ND];                 // fc projection output (f32)
__device__ float g_inv[32 * NS];               // 1/rowsum per [bh][row]
__device__ __half g_Qh[TOK*ND];                // fp16 Q projection
__device__ __half g_Kh[TOK*ND];                // fp16 K projection
__device__ __half g_inQh[TOK*ND];              // fp16 input_Q
__device__ __half g_WQh[ND*ND];                // fp16 W_Q
__device__ __half g_inKh[TOK*ND];              // fp16 input_K
__device__ __half g_WKh[ND*ND];                // fp16 W_K
__device__ __nv_bfloat16 g_inVh[TOK*ND];       // bf16 input_V
__device__ __nv_bfloat16 g_WVh[ND*ND];         // bf16 W_V
__device__ __nv_bfloat16 g_Wfch[ND*ND];        // bf16 W_fc
__device__ __nv_bfloat16 g_Vh[TOK*ND];         // bf16 V projection
__device__ __nv_bfloat16 g_ctxh[TOK*ND];       // bf16 context

// ---------------------------------------------------------------------------
__device__ __forceinline__ void cpa16(void* s, const void* g) {
    uint32_t sa = (uint32_t)__cvta_generic_to_shared(s);
    asm volatile("cp.async.ca.shared.global [%0], [%1], 16;" :: "r"(sa), "l"(g));
}
__device__ __forceinline__ void cpa_commit() {
    asm volatile("cp.async.commit_group;" ::: "memory");
}
template <int N>
__device__ __forceinline__ void cpa_wait() {
    asm volatile("cp.async.wait_group %0;" :: "n"(N) : "memory");
}

__device__ __forceinline__ uint32_t pack_bf2(float a, float b) {
    __nv_bfloat162 t = __float22bfloat162_rn(make_float2(a, b));
    return *(uint32_t*)&t;
}
__device__ __forceinline__ uint32_t pack_hf2(float a, float b) {
    __half2 t = __float22half2_rn(make_float2(a, b));
    return *(uint32_t*)&t;
}

// ---------------------------------------------------------------------------
// One launch converting all 7 inputs: z=0..3 -> fp16 (QK path),
// z=4..6 -> bf16 (V/fc path). 16MB tensors use full 4096-block rows;
// 4MB weights early-exit.
// ---------------------------------------------------------------------------
__global__ __launch_bounds__(256) void cvt_all(const float* __restrict__ inQ,
                                               const float* __restrict__ WQ,
                                               const float* __restrict__ inK,
                                               const float* __restrict__ WK,
                                               const float* __restrict__ inV,
                                               const float* __restrict__ WV,
                                               const float* __restrict__ Wfc) {
    const int z = blockIdx.y;
    const int n = (z == 0 || z == 2 || z == 4) ? TOK * ND : ND * ND;
    int i = (blockIdx.x * 256 + threadIdx.x) * 4;
    if (i >= n) return;
    const float* s;
    switch (z) {
        case 0: s = inQ; break;
        case 1: s = WQ; break;
        case 2: s = inK; break;
        case 3: s = WK; break;
        case 4: s = inV; break;
        case 5: s = WV; break;
        default: s = Wfc; break;
    }
    float4 v = *(const float4*)&s[i];
    if (z < 4) {
        __half* d = (z == 0) ? g_inQh : (z == 1) ? g_WQh : (z == 2) ? g_inKh : g_WKh;
        *(uint32_t*)&d[i]     = pack_hf2(v.x, v.y);
        *(uint32_t*)&d[i + 2] = pack_hf2(v.z, v.w);
    } else {
        __nv_bfloat16* d = (z == 4) ? g_inVh : (z == 5) ? g_WVh : g_Wfch;
        *(uint32_t*)&d[i]     = pack_bf2(v.x, v.y);
        *(uint32_t*)&d[i + 2] = pack_bf2(v.z, v.w);
    }
}

// ---------------------------------------------------------------------------
// fp16 GEMM with direct fp16 output: C half = A half @ B half (f32 accum).
// BK=32, 2-stage cp.async, BM=BN=128, 8 warps, warp tile 64x32.
// Used for Q and K projections (z selects).
// ---------------------------------------------------------------------------
#define LOADHH(sA, sB, A, Bw, st, k0)                                                  \
    {                                                                                  \
        _Pragma("unroll")                                                              \
        for (int i = 0; i < 2; i++) {                                                  \
            int idx = tid + i * 256;                                                   \
            int ra = idx >> 2, ca = (idx & 3) << 3;                                    \
            cpa16(&sA[st][ra][ca], &A[(size_t)(m0 + ra) * ND + (k0) + ca]);            \
            int rb = idx >> 4, cb = (idx & 15) << 3;                                   \
            cpa16(&sB[st][rb][cb], &Bw[(size_t)((k0) + rb) * ND + n0 + cb]);           \
        }                                                                              \
        cpa_commit();                                                                  \
    }

__global__ __launch_bounds__(256, 2) void qk_gemm_h(float dummy) {
    __shared__ __half sA[2][128][40];    // 20480 B (reused as f32 staging in epilogue)
    __shared__ __half sB[2][32][136];

    const int tid = threadIdx.x;
    const int w   = tid >> 5;
    const int l   = tid & 31;
    const int wm  = w >> 2;
    const int wn  = w & 3;
    const int m0  = blockIdx.y * 128;
    const int n0  = blockIdx.x * 128;
    const int z   = blockIdx.z;

    const __half* A  = (z == 0) ? g_inQh : g_inKh;
    const __half* Bw = (z == 0) ? g_WQh  : g_WKh;
    __half*       C  = (z == 0) ? g_Qh   : g_Kh;

    wmma::fragment<wmma::accumulator, 16, 16, 16, float> acc[4][2];
#pragma unroll
    for (int i = 0; i < 4; i++)
#pragma unroll
        for (int j = 0; j < 2; j++) wmma::fill_fragment(acc[i][j], 0.0f);

    LOADHH(sA, sB, A, Bw, 0, 0);

    for (int kt = 0; kt < 32; kt++) {
        if (kt < 31) {
            LOADHH(sA, sB, A, Bw, (kt + 1) & 1, (kt + 1) * 32);
            cpa_wait<1>();
        } else {
            cpa_wait<0>();
        }
        __syncthreads();
        const int st = kt & 1;
#pragma unroll
        for (int ks = 0; ks < 32; ks += 16) {
            wmma::fragment<wmma::matrix_a, 16, 16, 16, __half, wmma::row_major> af[4];
            wmma::fragment<wmma::matrix_b, 16, 16, 16, __half, wmma::row_major> bf[2];
#pragma unroll
            for (int i = 0; i < 4; i++)
                wmma::load_matrix_sync(af[i], &sA[st][wm * 64 + i * 16][ks], 40);
#pragma unroll
            for (int j = 0; j < 2; j++)
                wmma::load_matrix_sync(bf[j], &sB[st][ks][wn * 32 + j * 16], 136);
#pragma unroll
            for (int i = 0; i < 4; i++)
#pragma unroll
                for (int j = 0; j < 2; j++)
                    wmma::mma_sync(acc[i][j], af[i], bf[j], acc[i][j]);
        }
        __syncthreads();   // final iter: all smem reads done -> safe to reuse sA
    }

    // epilogue: per-warp 16x36 f32 staging inside sA, pack to fp16
    float* stg = (float*)sA + (size_t)w * (16 * 36);
#pragma unroll
    for (int i = 0; i < 4; i++) {
        wmma::store_matrix_sync(&stg[0],  acc[i][0], 36, wmma::mem_row_major);
        wmma::store_matrix_sync(&stg[16], acc[i][1], 36, wmma::mem_row_major);
        __syncwarp();
        const int r  = l & 15;
        const int hf = l >> 4;
        const float* row = stg + r * 36 + hf * 16;
        uint32_t pk[8];
#pragma unroll
        for (int q = 0; q < 8; q++) pk[q] = pack_hf2(row[2 * q], row[2 * q + 1]);
        __half* gp = C + (size_t)(m0 + wm * 64 + i * 16 + r) * ND + n0 + wn * 32 + hf * 16;
        *(uint4*)gp       = make_uint4(pk[0], pk[1], pk[2], pk[3]);
        *(uint4*)(gp + 8) = make_uint4(pk[4], pk[5], pk[6], pk[7]);
        __syncwarp();
    }
}

// ---------------------------------------------------------------------------
// bf16 GEMM: C f32 = A bf16 @ B bf16 (fc projection).
// ---------------------------------------------------------------------------
__global__ __launch_bounds__(256, 2) void gemm_bf16(const __nv_bfloat16* __restrict__ A,
                                                    const __nv_bfloat16* __restrict__ Bw,
                                                    float* __restrict__ C) {
    __shared__ __nv_bfloat16 sA[2][128][40];
    __shared__ __nv_bfloat16 sB[2][32][136];

    const int tid = threadIdx.x;
    const int w   = tid >> 5;
    const int wm  = w >> 2;
    const int wn  = w & 3;
    const int m0  = blockIdx.y * 128;
    const int n0  = blockIdx.x * 128;

    wmma::fragment<wmma::accumulator, 16, 16, 16, float> acc[4][2];
#pragma unroll
    for (int i = 0; i < 4; i++)
#pragma unroll
        for (int j = 0; j < 2; j++) wmma::fill_fragment(acc[i][j], 0.0f);

    LOADHH(sA, sB, A, Bw, 0, 0);

    for (int kt = 0; kt < 32; kt++) {
        if (kt < 31) {
            LOADHH(sA, sB, A, Bw, (kt + 1) & 1, (kt + 1) * 32);
            cpa_wait<1>();
        } else {
            cpa_wait<0>();
        }
        __syncthreads();
        const int st = kt & 1;
#pragma unroll
        for (int ks = 0; ks < 32; ks += 16) {
            wmma::fragment<wmma::matrix_a, 16, 16, 16, __nv_bfloat16, wmma::row_major> af[4];
            wmma::fragment<wmma::matrix_b, 16, 16, 16, __nv_bfloat16, wmma::row_major> bf[2];
#pragma unroll
            for (int i = 0; i < 4; i++)
                wmma::load_matrix_sync(af[i], &sA[st][wm * 64 + i * 16][ks], 40);
#pragma unroll
            for (int j = 0; j < 2; j++)
                wmma::load_matrix_sync(bf[j], &sB[st][ks][wn * 32 + j * 16], 136);
#pragma unroll
            for (int i = 0; i < 4; i++)
#pragma unroll
                for (int j = 0; j < 2; j++)
                    wmma::mma_sync(acc[i][j], af[i], bf[j], acc[i][j]);
        }
        __syncthreads();
    }

#pragma unroll
    for (int i = 0; i < 4; i++)
#pragma unroll
        for (int j = 0; j < 2; j++)
            wmma::store_matrix_sync(&C[(size_t)(m0 + wm * 64 + i * 16) * ND + n0 + wn * 32 + j * 16],
                                    acc[i][j], ND, wmma::mem_row_major);
}

// ---------------------------------------------------------------------------
// bf16 GEMM with DIRECT bf16 output (V projection).
// ---------------------------------------------------------------------------
__global__ __launch_bounds__(256, 2) void gemm_bf16_obf(const __nv_bfloat16* __restrict__ A,
                                                        const __nv_bfloat16* __restrict__ Bw,
                                                        __nv_bfloat16* __restrict__ C) {
    __shared__ __nv_bfloat16 sA[2][128][40];
    __shared__ __nv_bfloat16 sB[2][32][136];

    const int tid = threadIdx.x;
    const int w   = tid >> 5;
    const int l   = tid & 31;
    const int wm  = w >> 2;
    const int wn  = w & 3;
    const int m0  = blockIdx.y * 128;
    const int n0  = blockIdx.x * 128;

    wmma::fragment<wmma::accumulator, 16, 16, 16, float> acc[4][2];
#pragma unroll
    for (int i = 0; i < 4; i++)
#pragma unroll
        for (int j = 0; j < 2; j++) wmma::fill_fragment(acc[i][j], 0.0f);

    LOADHH(sA, sB, A, Bw, 0, 0);

    for (int kt = 0; kt < 32; kt++) {
        if (kt < 31) {
            LOADHH(sA, sB, A, Bw, (kt + 1) & 1, (kt + 1) * 32);
            cpa_wait<1>();
        } else {
            cpa_wait<0>();
        }
        __syncthreads();
        const int st = kt & 1;
#pragma unroll
        for (int ks = 0; ks < 32; ks += 16) {
            wmma::fragment<wmma::matrix_a, 16, 16, 16, __nv_bfloat16, wmma::row_major> af[4];
            wmma::fragment<wmma::matrix_b, 16, 16, 16, __nv_bfloat16, wmma::row_major> bf[2];
#pragma unroll
            for (int i = 0; i < 4; i++)
                wmma::load_matrix_sync(af[i], &sA[st][wm * 64 + i * 16][ks], 40);
#pragma unroll
            for (int j = 0; j < 2; j++)
                wmma::load_matrix_sync(bf[j], &sB[st][ks][wn * 32 + j * 16], 136);
#pragma unroll
            for (int i = 0; i < 4; i++)
#pragma unroll
                for (int j = 0; j < 2; j++)
                    wmma::mma_sync(acc[i][j], af[i], bf[j], acc[i][j]);
        }
        __syncthreads();
    }

    float* stg = (float*)sA + (size_t)w * (16 * 36);
#pragma unroll
    for (int i = 0; i < 4; i++) {
        wmma::store_matrix_sync(&stg[0],  acc[i][0], 36, wmma::mem_row_major);
        wmma::store_matrix_sync(&stg[16], acc[i][1], 36, wmma::mem_row_major);
        __syncwarp();
        const int r  = l & 15;
        const int hf = l >> 4;
        const float* row = stg + r * 36 + hf * 16;
        uint32_t pk[8];
#pragma unroll
        for (int q = 0; q < 8; q++) pk[q] = pack_bf2(row[2 * q], row[2 * q + 1]);
        __nv_bfloat16* gp = C + (size_t)(m0 + wm * 64 + i * 16 + r) * ND + n0 + wn * 32 + hf * 16;
        *(uint4*)gp       = make_uint4(pk[0], pk[1], pk[2], pk[3]);
        *(uint4*)(gp + 8) = make_uint4(pk[4], pk[5], pk[6], pk[7]);
        __syncwarp();
    }
}
#undef LOADHH

// ---------------------------------------------------------------------------
// escore v7 — FP16 Q/K (same 10-bit mantissa as tf32; precision-neutral).
// One block = 64-row q-stripe of one (b,h). K streamed in 32 fp16 tiles of
// 64 keys (double-buffered). Q persistent as fp16 frags (af[2][4]). Mask
// triple-buffered. 8 MMAs (16x16x16)/iter. Scores f32 in smem.
// grid = (32, 32), 256 threads, 2 blocks/SM.
// smem layout (bytes): sS f32 64x68 (17408) | sSum 64 f32 (256) |
//   sQ half 64x72 (9216) | sK half 2x64x72 (18432) | mask 3x4096 (12288)
// ---------------------------------------------------------------------------
#define ESC_SMEM (17408 + 256 + 9216 + 18432 + 12288)   // 57600 B

__global__ __launch_bounds__(256, 2) void escore_kernel(const unsigned char* __restrict__ mask,
                                                        float* __restrict__ attnOut) {
    extern __shared__ float sm[];
    float* sS   = sm;                                   // 64 x 68 f32
    float* sSum = sS + 64 * 68;                         // 64
    __half* sQ  = (__half*)(sSum + 64);                 // 64 x 72 half
    __half* sK  = sQ + 64 * 72;                         // 2 x (64 x 72) half
    unsigned char* sMask = (unsigned char*)(sK + 2 * 64 * 72);  // 3 x 4096

    const int tid = threadIdx.x;
    const int w   = tid >> 5;
    const int l   = tid & 31;
    const int bh  = blockIdx.y;
    const int b   = bh >> 4;
    const int h   = bh & 15;
    const int q0  = blockIdx.x * 64;

    const __half* Qb = g_Qh + ((size_t)(b * NS + q0)) * ND + h * NDH;
    const __half* Kb = g_Kh + ((size_t)b * NS) * ND + h * NDH;
    const unsigned char* Mb = mask + ((size_t)(b * NS + q0)) * NS;

    const int mrw = tid >> 2;
    const int mcc = (tid & 3) << 4;

    // initial group: Q stripe (64x64 half = 512 x 16B) + K tile 0 + mask 0
#pragma unroll
    for (int i = 0; i < 2; i++) {
        int idx = tid + i * 256;
        int r = idx >> 3, c = (idx & 7) << 3;
        cpa16(&sQ[r * 72 + c], &Qb[(size_t)r * ND + c]);
        cpa16(&sK[r * 72 + c], &Kb[(size_t)r * ND + c]);
    }
    cpa16(&sMask[mrw * 64 + mcc], &Mb[(size_t)mrw * NS + mcc]);
    cpa_commit();
    if (tid < 64) sSum[tid] = 0.0f;

    const int wm = w >> 2;          // 0..1 : 32-row band
    const int wn = w & 3;           // 0..3 : 16-col band

    // persistent fp16 Q fragments: af[i][kk] rows wm*32+i*16, k-slice kk*16
    wmma::fragment<wmma::matrix_a, 16, 16, 16, __half, wmma::row_major> af[2][4];

    int mbuf = 0;

    for (int ct = 0; ct < 32; ct++) {
        const int mnext = (mbuf + 1 == 3) ? 0 : mbuf + 1;
        if (ct < 31) {
            __half* dst = sK + ((ct + 1) & 1) * (64 * 72);
            const __half* src = Kb + (size_t)(ct + 1) * 64 * ND;
#pragma unroll
            for (int i = 0; i < 2; i++) {
                int idx = tid + i * 256;
                int r = idx >> 3, c = (idx & 7) << 3;
                cpa16(&dst[r * 72 + c], &src[(size_t)r * ND + c]);
            }
            cpa16(&sMask[mnext * 4096 + mrw * 64 + mcc],
                  &Mb[(size_t)mrw * NS + (size_t)(ct + 1) * 64 + mcc]);
            cpa_commit();
            cpa_wait<1>();
        } else {
            cpa_wait<0>();
        }
        __syncthreads();   // A: K[ct], M[ct] (and Q at ct=0) visible

        if (ct == 0) {
#pragma unroll
            for (int i = 0; i < 2; i++)
#pragma unroll
                for (int kk = 0; kk < 4; kk++)
                    wmma::load_matrix_sync(af[i][kk], &sQ[(wm * 32 + i * 16) * 72 + kk * 16], 72);
        }

        const __half* sKt = sK + (ct & 1) * (64 * 72);
        wmma::fragment<wmma::accumulator, 16, 16, 16, float> acc[2];
        wmma::fill_fragment(acc[0], 0.0f);
        wmma::fill_fragment(acc[1], 0.0f);

#pragma unroll
        for (int kk = 0; kk < 4; kk++) {
            wmma::fragment<wmma::matrix_b, 16, 16, 16, __half, wmma::col_major> bf;
            wmma::load_matrix_sync(bf, &sKt[(wn * 16) * 72 + kk * 16], 72);
            wmma::mma_sync(acc[0], af[0][kk], bf, acc[0]);
            wmma::mma_sync(acc[1], af[1][kk], bf, acc[1]);
        }
#pragma unroll
        for (int i = 0; i < 2; i++)
            wmma::store_matrix_sync(&sS[(wm * 32 + i * 16) * 68 + wn * 16], acc[i], 68,
                                    wmma::mem_row_major);
        __syncthreads();   // B: sS complete; K buffer reuse guarded

        const int c0 = ct * 64;
        const unsigned char* mTile = sMask + mbuf * 4096;
#pragma unroll
        for (int pass = 0; pass < 4; pass++) {
            const int r  = w * 8 + pass * 2 + (l >> 4);
            const int cc = (l & 15) << 2;
            float4 v = *(const float4*)&sS[r * 68 + cc];
            uchar4 mk = *(const uchar4*)&mTile[r * 64 + cc];
            v.x = mk.x ? 0.0f : __expf(v.x * SCALE);
            v.y = mk.y ? 0.0f : __expf(v.y * SCALE);
            v.z = mk.z ? 0.0f : __expf(v.z * SCALE);
            v.w = mk.w ? 0.0f : __expf(v.w * SCALE);
            float* erow = attnOut + ((size_t)(bh * NS + q0 + r)) * NS + c0;
            *(float4*)&erow[cc] = v;
            float s = v.x + v.y + v.z + v.w;
#pragma unroll
            for (int off = 8; off > 0; off >>= 1)
                s += __shfl_xor_sync(0xffffffffu, s, off);
            if ((l & 15) == 0) sSum[r] += s;
        }
        mbuf = mnext;
    }

    __syncthreads();
    if (tid < 64) g_inv[(size_t)bh * NS + q0 + tid] = 1.0f / sSum[tid];
}

// ---------------------------------------------------------------------------
// ctxnorm v3.1 — WARP SPECIALIZED, V-prefetch lagged (race-free).
// ---------------------------------------------------------------------------
#define CTX_ER   (2 * 128 * 68 * 4)     // 69632
#define CTX_VH   (2 * 64 * 72 * 2)      // 18432
#define CTX_PB   (2 * 128 * 72 * 2)     // 73728
#define CTX_SMEM (CTX_ER + CTX_VH + CTX_PB + 512)   // 162304

__global__ __launch_bounds__(512) void ctxnorm_kernel(float* __restrict__ attn) {
    extern __shared__ char smc[];
    float*         sEraw = (float*)smc;
    __nv_bfloat16* sVh   = (__nv_bfloat16*)(smc + CTX_ER);
    __nv_bfloat16* sPb   = (__nv_bfloat16*)(smc + CTX_ER + CTX_VH);
    float*         sInv  = (float*)(smc + CTX_ER + CTX_VH + CTX_PB);

    const int tid = threadIdx.x;
    const int w   = tid >> 5;
    const int l   = tid & 31;
    const int bh  = blockIdx.y;
    const int b   = bh >> 4;
    const int h   = bh & 15;
    const int m0  = blockIdx.x * 128;

    float* Eb = attn + ((size_t)bh * NS + m0) * NS;
    const __nv_bfloat16* Vb = g_Vh + ((size_t)b * NS) * ND + h * NDH;

    if (tid < 128) sInv[tid] = g_inv[(size_t)bh * NS + m0 + tid];

#pragma unroll
    for (int i = 0; i < 4; i++) {
        int idx = tid + i * 512;
        int er = idx >> 4, ec = (idx & 15) << 2;
        cpa16(&sEraw[er * 68 + ec], &Eb[(size_t)er * NS + ec]);
    }
    cpa_commit();

    const int wv = w - 8;
    const int wm = wv >> 1, wn = wv & 1;
    const int band = w * 16;

    wmma::fragment<wmma::accumulator, 16, 16, 16, float> acc[2][2];
    if (w >= 8) {
#pragma unroll
        for (int i = 0; i < 2; i++)
#pragma unroll
            for (int j = 0; j < 2; j++) wmma::fill_fragment(acc[i][j], 0.0f);
    }

    for (int kc = 0; kc <= 32; kc++) {
        __syncthreads();   // A
        if (kc < 32) {
            if (kc + 1 < 32) {
                float* dE = sEraw + ((kc + 1) & 1) * (128 * 68);
#pragma unroll
                for (int i = 0; i < 4; i++) {
                    int idx = tid + i * 512;
                    int er = idx >> 4, ec = (idx & 15) << 2;
                    cpa16(&dE[er * 68 + ec],
                          &Eb[(size_t)er * NS + (size_t)(kc + 1) * 64 + ec]);
                }
            }
            {
                __nv_bfloat16* dV = sVh + (kc & 1) * (64 * 72);
                int vr = tid >> 3, vc = (tid & 7) << 3;
                cpa16(&dV[vr * 72 + vc], &Vb[(size_t)(kc * 64 + vr) * ND + vc]);
            }
            cpa_commit();
            cpa_wait<1>();
        } else {
            cpa_wait<0>();
        }
        __syncthreads();   // B

        if (w < 8) {
            if (kc < 32) {
                const float* cE = sEraw + (kc & 1) * (128 * 68);
                __nv_bfloat16* dP = sPb + (kc & 1) * (128 * 72);
                const size_t gk = (size_t)kc * 64;
#pragma unroll
                for (int i = 0; i < 8; i++) {
                    int idx = i * 32 + l;
                    int r = band + (idx >> 4);
                    int cc = (idx & 15) << 2;
                    float4 v = *(const float4*)&cE[r * 68 + cc];
                    float iv = sInv[r];
                    v.x *= iv; v.y *= iv; v.z *= iv; v.w *= iv;
                    *(float4*)&Eb[(size_t)r * NS + gk + cc] = v;
                    *(uint32_t*)&dP[r * 72 + cc]     = pack_bf2(v.x, v.y);
                    *(uint32_t*)&dP[r * 72 + cc + 2] = pack_bf2(v.z, v.w);
                }
            }
        } else if (kc >= 1) {
            const int kp = kc - 1;
            const __nv_bfloat16* cP = sPb + (kp & 1) * (128 * 72);
            const __nv_bfloat16* cV = sVh + (kp & 1) * (64 * 72);
#pragma unroll
            for (int kk = 0; kk < 4; kk++) {
                wmma::fragment<wmma::matrix_a, 16, 16, 16, __nv_bfloat16, wmma::row_major> af[2];
                wmma::fragment<wmma::matrix_b, 16, 16, 16, __nv_bfloat16, wmma::row_major> bf[2];
#pragma unroll
                for (int i = 0; i < 2; i++)
                    wmma::load_matrix_sync(af[i], &cP[(wm * 32 + i * 16) * 72 + kk * 16], 72);
#pragma unroll
                for (int j = 0; j < 2; j++)
                    wmma::load_matrix_sync(bf[j], &cV[(kk * 16) * 72 + wn * 32 + j * 16], 72);
#pragma unroll
                for (int i = 0; i < 2; i++)
#pragma unroll
                    for (int j = 0; j < 2; j++)
                        wmma::mma_sync(acc[i][j], af[i], bf[j], acc[i][j]);
            }
        }
    }

    __syncthreads();
    if (w >= 8) {
        float* stg = sEraw + wv * (32 * 36);
#pragma unroll
        for (int i = 0; i < 2; i++)
#pragma unroll
            for (int j = 0; j < 2; j++)
                wmma::store_matrix_sync(&stg[(i * 16) * 36 + j * 16], acc[i][j], 36,
                                        wmma::mem_row_major);
        __syncwarp();
        const float* row = stg + l * 36;
        uint32_t pk[16];
#pragma unroll
        for (int j = 0; j < 16; j++) pk[j] = pack_bf2(row[2 * j], row[2 * j + 1]);
        __nv_bfloat16* gp = g_ctxh + (size_t)(b * NS + m0 + wm * 32 + l) * ND + h * NDH + wn * 32;
#pragma unroll
        for (int j = 0; j < 4; j++)
            *(uint4*)(gp + j * 8) = make_uint4(pk[4 * j], pk[4 * j + 1], pk[4 * j + 2], pk[4 * j + 3]);
    }
}

// ---------------------------------------------------------------------------
// Residual + LayerNorm
// ---------------------------------------------------------------------------
__global__ __launch_bounds__(256) void ln_kernel(const float* __restrict__ resid,
                                                 float* __restrict__ out) {
    const int row = blockIdx.x;
    const int tid = threadIdx.x;

    float4 f  = *(const float4*)&g_fc[(size_t)row * ND + tid * 4];
    float4 rr = *(const float4*)&resid[(size_t)row * ND + tid * 4];
    float4 y;
    y.x = f.x + rr.x; y.y = f.y + rr.y; y.z = f.z + rr.z; y.w = f.w + rr.w;

    float s = y.x + y.y + y.z + y.w;
    float q = y.x * y.x + y.y * y.y + y.z * y.z + y.w * y.w;
#pragma unroll
    for (int off = 16; off > 0; off >>= 1) {
        s += __shfl_down_sync(0xffffffffu, s, off);
        q += __shfl_down_sync(0xffffffffu, q, off);
    }
    __shared__ float ss[8], sq[8];
    __shared__ float mu_s, rs_s;
    if ((tid & 31) == 0) { ss[tid >> 5] = s; sq[tid >> 5] = q; }
    __syncthreads();
    if (tid == 0) {
        float S = 0.0f, Q = 0.0f;
#pragma unroll
        for (int i = 0; i < 8; i++) { S += ss[i]; Q += sq[i]; }
        float mu  = S * (1.0f / ND);
        float var = Q * (1.0f / ND) - mu * mu;
        mu_s = mu;
        rs_s = rsqrtf(var + LN_EPS);
    }
    __syncthreads();
    const float mu = mu_s, rs = rs_s;
    float4 o;
    o.x = (y.x - mu) * rs; o.y = (y.y - mu) * rs;
    o.z = (y.z - mu) * rs; o.w = (y.w - mu) * rs;
    *(float4*)&out[(size_t)row * ND + tid * 4] = o;
}

// ---------------------------------------------------------------------------
extern "C" void kernel_launch(void* const* d_in, const int* in_sizes, int n_in,
                              void* d_out, int out_size) {
    const float* inQ = (const float*)d_in[0];
    const float* inK = (const float*)d_in[1];
    const float* inV = (const float*)d_in[2];
    const unsigned char* mask = (const unsigned char*)d_in[3];
    const float* WQ  = (const float*)d_in[4];
    const float* WK  = (const float*)d_in[5];
    const float* WV  = (const float*)d_in[6];
    const float* Wfc = (const float*)d_in[7];

    float* out  = (float*)d_out;
    float* attn = out + OUT_ELEMS;

    void *pFc, *pInVh, *pWVh, *pWfch, *pVh, *pCtxh;
    cudaGetSymbolAddress(&pFc, g_fc);
    cudaGetSymbolAddress(&pInVh, g_inVh);
    cudaGetSymbolAddress(&pWVh, g_WVh);
    cudaGetSymbolAddress(&pWfch, g_Wfch);
    cudaGetSymbolAddress(&pVh, g_Vh);
    cudaGetSymbolAddress(&pCtxh, g_ctxh);

    cudaFuncSetAttribute(escore_kernel, cudaFuncAttributeMaxDynamicSharedMemorySize, ESC_SMEM);
    cudaFuncSetAttribute(ctxnorm_kernel, cudaFuncAttributeMaxDynamicSharedMemorySize, CTX_SMEM);

    // all 7 input conversions in one launch
    cvt_all<<<dim3((TOK * ND / 4 + 255) / 256, 7), 256>>>(inQ, WQ, inK, WK, inV, WV, Wfc);

    // Q, K projections in fp16 (same mantissa as tf32; direct fp16 output)
    qk_gemm_h<<<dim3(8, 32, 2), 256>>>(0.0f);

    // V projection in bf16, direct bf16 output
    gemm_bf16_obf<<<dim3(8, 32), 256>>>((const __nv_bfloat16*)pInVh, (const __nv_bfloat16*)pWVh,
                                        (__nv_bfloat16*)pVh);

    escore_kernel<<<dim3(32, 32), 256, ESC_SMEM>>>(mask, attn);

    ctxnorm_kernel<<<dim3(16, 32), 512, CTX_SMEM>>>(attn);

    gemm_bf16<<<dim3(8, 32), 256>>>((const __nv_bfloat16*)pCtxh, (const __nv_bfloat16*)pWfch,
                                    (float*)pFc);

    ln_kernel<<<TOK, 256>>>(inQ, out);
}